// round 1
// baseline (speedup 1.0000x reference)
#include <cuda_runtime.h>
#include <math.h>

#define NN 20000
#define MM 2048
#define EE 320000
#define FF 512
#define HIDD 256
#define CSTAT_ROWS 128
#define CSTAT_BLKS ((NN + CSTAT_ROWS - 1) / CSTAT_ROWS)   // 157

#define NEG_SLOPE 0.01f
#define ATT_SLOPE 0.2f

// ---------------- scratch (static device allocations; no runtime alloc) ----------------
__device__ float g_xl[NN * FF];
__device__ float g_el[MM * FF];
__device__ float g_ef[MM * FF];
__device__ float g_h[NN * FF];
__device__ float g_fc[NN * HIDD];
__device__ float g_xn[NN];
__device__ float g_en[MM];
__device__ float g_alpha[EE];
__device__ float g_Dinv[NN];
__device__ float g_Binv[MM];
__device__ int   g_degn[NN];
__device__ int   g_dege[MM];
__device__ int   g_rstart[NN + 1];
__device__ int   g_cstart[MM + 1];
__device__ int   g_rcur[NN];
__device__ int   g_ccur[MM];
__device__ int   g_rcsr[EE];
__device__ int   g_ccsr[EE];
__device__ float g_p1[CSTAT_BLKS * FF];
__device__ float g_p2[CSTAT_BLKS * FF];
__device__ float g_shift[FF];
__device__ float g_scale[FF];

// ---------------- small utility kernels ----------------
__global__ void k_zero_i(int* p, int n) {
    int i = blockIdx.x * blockDim.x + threadIdx.x;
    if (i < n) p[i] = 0;
}

__global__ void k_copy_i(const int* __restrict__ a, int* __restrict__ b, int n) {
    int i = blockIdx.x * blockDim.x + threadIdx.x;
    if (i < n) b[i] = a[i];
}

__global__ void k_hist(const int* __restrict__ row, const int* __restrict__ col,
                       int* degn, int* dege, int E) {
    int i = blockIdx.x * blockDim.x + threadIdx.x;
    if (i < E) {
        atomicAdd(&degn[row[i]], 1);
        atomicAdd(&dege[col[i]], 1);
    }
}

// one-block exclusive scan (n <= 20480), 1024 threads
__global__ void k_exscan(const int* __restrict__ cnt, int* __restrict__ start, int n) {
    __shared__ int sh[1024];
    int tid = threadIdx.x;
    int per = (n + 1023) >> 10;
    int lo = tid * per;
    int hi = min(lo + per, n);
    int s = 0;
    for (int i = lo; i < hi; i++) s += cnt[i];
    sh[tid] = s;
    __syncthreads();
    for (int off = 1; off < 1024; off <<= 1) {
        int add = (tid >= off) ? sh[tid - off] : 0;
        __syncthreads();
        sh[tid] += add;
        __syncthreads();
    }
    int run = (tid == 0) ? 0 : sh[tid - 1];
    for (int i = lo; i < hi; i++) { start[i] = run; run += cnt[i]; }
    if (tid == 0) start[n] = sh[1023];
}

__global__ void k_scatter(const int* __restrict__ row, const int* __restrict__ col,
                          int* rcur, int* ccur, int* __restrict__ rcsr,
                          int* __restrict__ ccsr, int E) {
    int i = blockIdx.x * blockDim.x + threadIdx.x;
    if (i < E) {
        int pr = atomicAdd(&rcur[row[i]], 1);
        rcsr[pr] = i;
        int pc = atomicAdd(&ccur[col[i]], 1);
        ccsr[pc] = i;
    }
}

__global__ void k_inv(const int* __restrict__ deg, float* __restrict__ inv, int n) {
    int i = blockIdx.x * blockDim.x + threadIdx.x;
    if (i < n) {
        int d = deg[i];
        inv[i] = (d > 0) ? (1.0f / (float)d) : 0.0f;
    }
}

// out[r] = dot(X[r,:512], v)   — one warp per row
__global__ void k_rowdot(const float* __restrict__ X, const float* __restrict__ v,
                         float* __restrict__ out, int rows) {
    int gw = (blockIdx.x * blockDim.x + threadIdx.x) >> 5;
    int lane = threadIdx.x & 31;
    if (gw >= rows) return;
    const float4* xr = (const float4*)(X + (size_t)gw * FF);
    const float4* vv = (const float4*)v;
    float s = 0.f;
#pragma unroll
    for (int j = 0; j < 4; j++) {
        float4 a = xr[lane + 32 * j];
        float4 b = vv[lane + 32 * j];
        s += a.x * b.x + a.y * b.y + a.z * b.z + a.w * b.w;
    }
    for (int o = 16; o; o >>= 1) s += __shfl_down_sync(0xffffffffu, s, o);
    if (!lane) out[gw] = s;
}

// per-hyperedge softmax of leaky_relu(xn[row]+en[m]); writes normalized alpha[e]
__global__ void k_attn(const int* __restrict__ cstart, const int* __restrict__ ccsr,
                       const int* __restrict__ row, const float* __restrict__ xn,
                       const float* __restrict__ en, float* __restrict__ alpha) {
    int m = blockIdx.x;
    int s = cstart[m], e = cstart[m + 1];
    __shared__ float red[128];
    int tid = threadIdx.x;
    float enm = en[m];
    float mx = -3.0e38f;
    for (int i = s + tid; i < e; i += 128) {
        int ed = ccsr[i];
        float p = xn[row[ed]] + enm;
        p = (p > 0.f) ? p : ATT_SLOPE * p;
        alpha[ed] = p;
        mx = fmaxf(mx, p);
    }
    red[tid] = mx;
    __syncthreads();
    for (int o = 64; o; o >>= 1) {
        if (tid < o) red[tid] = fmaxf(red[tid], red[tid + o]);
        __syncthreads();
    }
    float amax = red[0];
    if (!(amax > -1e37f)) amax = 0.f;
    __syncthreads();
    float sm = 0.f;
    for (int i = s + tid; i < e; i += 128) {
        int ed = ccsr[i];
        float ex = expf(alpha[ed] - amax);
        alpha[ed] = ex;
        sm += ex;
    }
    red[tid] = sm;
    __syncthreads();
    for (int o = 64; o; o >>= 1) {
        if (tid < o) red[tid] += red[tid + o];
        __syncthreads();
    }
    float inv = 1.f / fmaxf(red[0], 1e-16f);
    for (int i = s + tid; i < e; i += 128) alpha[ccsr[i]] *= inv;
}

// edge_feat[m,:] = Binv[m] * sum_e alpha[e] * xl[row[e],:]   (block per hyperedge)
__global__ void k_prop1(const int* __restrict__ cstart, const int* __restrict__ ccsr,
                        const int* __restrict__ row, const float* __restrict__ alpha,
                        const float* __restrict__ Binv, const float* __restrict__ xl,
                        float* __restrict__ ef) {
    int m = blockIdx.x;
    int s = cstart[m], e = cstart[m + 1];
    __shared__ int   shr[256];
    __shared__ float shc[256];
    int tid = threadIdx.x;
    float ax = 0.f, ay = 0.f;
    const float* base = xl + 2 * tid;
    for (int b0 = s; b0 < e; b0 += 256) {
        int cnt = min(256, e - b0);
        __syncthreads();
        if (tid < cnt) {
            int ed = ccsr[b0 + tid];
            shr[tid] = row[ed];
            shc[tid] = alpha[ed];
        }
        __syncthreads();
        for (int j = 0; j < cnt; j++) {
            float2 v = *(const float2*)(base + (size_t)shr[j] * FF);
            float cf = shc[j];
            ax += cf * v.x;
            ay += cf * v.y;
        }
    }
    float bi = Binv[m];
    float2 o;
    o.x = ax * bi; o.y = ay * bi;
    *(float2*)(ef + (size_t)m * FF + 2 * tid) = o;
}

// out[n,:] = Dinv[n] * sum_e alpha[e] * ef[col[e],:] + bias   (block per node)
__global__ void k_prop2(const int* __restrict__ rstart, const int* __restrict__ rcsr,
                        const int* __restrict__ col, const float* __restrict__ alpha,
                        const float* __restrict__ Dinv, const float* __restrict__ ef,
                        const float* __restrict__ bias, float* __restrict__ out) {
    int n = blockIdx.x;
    int s = rstart[n], e = rstart[n + 1];
    int tid = threadIdx.x;
    float a0 = 0.f, a1 = 0.f, a2 = 0.f, a3 = 0.f;
    for (int i = s; i < e; i++) {
        int ed = rcsr[i];
        float cf = alpha[ed];
        float4 v = *(const float4*)(ef + (size_t)col[ed] * FF + 4 * tid);
        a0 += cf * v.x; a1 += cf * v.y; a2 += cf * v.z; a3 += cf * v.w;
    }
    float d = Dinv[n];
    float4 b = *(const float4*)(bias + 4 * tid);
    float4 o;
    o.x = a0 * d + b.x; o.y = a1 * d + b.y; o.z = a2 * d + b.z; o.w = a3 * d + b.w;
    *(float4*)(out + (size_t)n * FF + 4 * tid) = o;
}

// per-block column partial sums of x and x^2
__global__ void k_colstat(const float* __restrict__ X, float* __restrict__ p1,
                          float* __restrict__ p2, int rows) {
    int b = blockIdx.x;
    int c = threadIdx.x;
    int r0 = b * CSTAT_ROWS, r1 = min(r0 + CSTAT_ROWS, rows);
    float s1 = 0.f, s2 = 0.f;
    for (int r = r0; r < r1; r++) {
        float v = X[(size_t)r * FF + c];
        s1 += v;
        s2 += v * v;
    }
    p1[b * FF + c] = s1;
    p2[b * FF + c] = s2;
}

// deterministic fixed-order reduce; builds shift = ms*mean, scale = w/sqrt(var+eps)
__global__ void k_statfin(const float* __restrict__ p1, const float* __restrict__ p2,
                          int nblk, const float* __restrict__ w,
                          const float* __restrict__ ms, float* __restrict__ shift,
                          float* __restrict__ scale, float rows_inv) {
    int c = threadIdx.x;
    float s1 = 0.f, s2 = 0.f;
    for (int i = 0; i < nblk; i++) {
        s1 += p1[i * FF + c];
        s2 += p2[i * FF + c];
    }
    float mu = s1 * rows_inv;
    float ex2 = s2 * rows_inv;
    float m = ms[c];
    float sh = m * mu;
    float var = ex2 - sh * (2.f * mu - sh);
    shift[c] = sh;
    scale[c] = w[c] / sqrtf(var + 1e-5f);
}

__global__ void k_normapply(const float* __restrict__ X, const float* __restrict__ shift,
                            const float* __restrict__ scale, const float* __restrict__ beta,
                            float* __restrict__ Y, int total4) {
    int i = blockIdx.x * blockDim.x + threadIdx.x;
    if (i >= total4) return;
    int c = (i & 127) * 4;   // FF/4 = 128 float4 per row
    float4 v = ((const float4*)X)[i];
    float4 sh = *(const float4*)(shift + c);
    float4 sc = *(const float4*)(scale + c);
    float4 be = *(const float4*)(beta + c);
    float y0 = (v.x - sh.x) * sc.x + be.x;
    float y1 = (v.y - sh.y) * sc.y + be.y;
    float y2 = (v.z - sh.z) * sc.z + be.z;
    float y3 = (v.w - sh.w) * sc.w + be.w;
    y0 = (y0 > 0.f) ? y0 : NEG_SLOPE * y0;
    y1 = (y1 > 0.f) ? y1 : NEG_SLOPE * y1;
    y2 = (y2 > 0.f) ? y2 : NEG_SLOPE * y2;
    y3 = (y3 > 0.f) ? y3 : NEG_SLOPE * y3;
    ((float4*)Y)[i] = make_float4(y0, y1, y2, y3);
}

// logits = A[rows,256] @ W[256,2] + b   — one warp per row
__global__ void k_cls(const float* __restrict__ A, const float* __restrict__ W,
                      const float* __restrict__ b, float* __restrict__ out, int rows) {
    int gw = (blockIdx.x * blockDim.x + threadIdx.x) >> 5;
    int lane = threadIdx.x & 31;
    if (gw >= rows) return;
    const float* ar = A + (size_t)gw * HIDD;
    float s0 = 0.f, s1 = 0.f;
    for (int h = lane; h < HIDD; h += 32) {
        float v = ar[h];
        s0 += v * W[h * 2];
        s1 += v * W[h * 2 + 1];
    }
    for (int o = 16; o; o >>= 1) {
        s0 += __shfl_down_sync(0xffffffffu, s0, o);
        s1 += __shfl_down_sync(0xffffffffu, s1, o);
    }
    if (!lane) {
        out[gw * 2] = s0 + b[0];
        out[gw * 2 + 1] = s1 + b[1];
    }
}

// ---------------- SGEMM: C[M,N] = A[M,K] @ B[K,N] (row-major), BM=BN=128 BK=16 ----------------
// MODE 0: store; MODE 1: store lrelu(AB+bias); MODE 2: C += lrelu(AB+bias)
template <int MODE>
__global__ void __launch_bounds__(256) k_sgemm(const float* __restrict__ A,
                                               const float* __restrict__ B,
                                               float* __restrict__ C, int Mr, int Nc, int Kd,
                                               const float* __restrict__ bias) {
    __shared__ float As[16][132];
    __shared__ float Bs[16][128];
    int tid = threadIdx.x;
    int bm = blockIdx.y * 128, bn = blockIdx.x * 128;
    int tx = tid & 15, ty = tid >> 4;
    float acc[8][8];
#pragma unroll
    for (int i = 0; i < 8; i++)
#pragma unroll
        for (int j = 0; j < 8; j++) acc[i][j] = 0.f;
    int aRow = tid >> 2, aCol = (tid & 3) << 2;
    int bRow = tid >> 5, bCol = (tid & 31) << 2;
    for (int k0 = 0; k0 < Kd; k0 += 16) {
#pragma unroll
        for (int u = 0; u < 2; u++) {
            int r = aRow + u * 64;
            int gr = bm + r;
            float4 v = make_float4(0.f, 0.f, 0.f, 0.f);
            if (gr < Mr) v = *(const float4*)(A + (size_t)gr * Kd + k0 + aCol);
            As[aCol][r] = v.x;
            As[aCol + 1][r] = v.y;
            As[aCol + 2][r] = v.z;
            As[aCol + 3][r] = v.w;
        }
#pragma unroll
        for (int u = 0; u < 2; u++) {
            int r = bRow + u * 8;
            *(float4*)&Bs[r][bCol] = *(const float4*)(B + (size_t)(k0 + r) * Nc + bn + bCol);
        }
        __syncthreads();
#pragma unroll
        for (int k = 0; k < 16; k++) {
            float a[8], bv[8];
#pragma unroll
            for (int i = 0; i < 8; i++) a[i] = As[k][ty * 8 + i];
#pragma unroll
            for (int j = 0; j < 8; j++) bv[j] = Bs[k][tx * 8 + j];
#pragma unroll
            for (int i = 0; i < 8; i++)
#pragma unroll
                for (int j = 0; j < 8; j++) acc[i][j] += a[i] * bv[j];
        }
        __syncthreads();
    }
#pragma unroll
    for (int i = 0; i < 8; i++) {
        int rowg = bm + ty * 8 + i;
        if (rowg >= Mr) continue;
        float* crow = C + (size_t)rowg * Nc + bn + tx * 8;
#pragma unroll
        for (int j4 = 0; j4 < 8; j4 += 4) {
            float4 v = make_float4(acc[i][j4], acc[i][j4 + 1], acc[i][j4 + 2], acc[i][j4 + 3]);
            if (MODE >= 1) {
                float4 bb = *(const float4*)(bias + bn + tx * 8 + j4);
                v.x += bb.x; v.y += bb.y; v.z += bb.z; v.w += bb.w;
                v.x = (v.x > 0.f) ? v.x : NEG_SLOPE * v.x;
                v.y = (v.y > 0.f) ? v.y : NEG_SLOPE * v.y;
                v.z = (v.z > 0.f) ? v.z : NEG_SLOPE * v.z;
                v.w = (v.w > 0.f) ? v.w : NEG_SLOPE * v.w;
            }
            if (MODE == 2) {
                float4 o = *(float4*)(crow + j4);
                v.x += o.x; v.y += o.y; v.z += o.z; v.w += o.w;
            }
            *(float4*)(crow + j4) = v;
        }
    }
}

// ---------------- host launch ----------------
extern "C" void kernel_launch(void* const* d_in, const int* in_sizes, int n_in,
                              void* d_out, int out_size) {
    const float* x    = (const float*)d_in[0];
    const int*   ei   = (const int*)d_in[1];
    const float* ea   = (const float*)d_in[2];
    const float* W1   = (const float*)d_in[3];
    const float* att1 = (const float*)d_in[4];
    const float* b1   = (const float*)d_in[5];
    const float* W2   = (const float*)d_in[6];
    const float* att2 = (const float*)d_in[7];
    const float* b2   = (const float*)d_in[8];
    const float* gn1w = (const float*)d_in[9];
    const float* gn1b = (const float*)d_in[10];
    const float* gn1ms= (const float*)d_in[11];
    const float* gn2w = (const float*)d_in[12];
    const float* gn2b = (const float*)d_in[13];
    const float* gn2ms= (const float*)d_in[14];
    const float* fc1W = (const float*)d_in[15];
    const float* fc1b = (const float*)d_in[16];
    const float* fc2W = (const float*)d_in[17];
    const float* fc2b = (const float*)d_in[18];
    const float* clsW = (const float*)d_in[19];
    const float* clsb = (const float*)d_in[20];
    float* outp = (float*)d_out;

    const int* row = ei;
    const int* col = ei + EE;

    float *xl, *el, *ef, *h, *fc, *xn, *en, *alpha, *Dinv, *Binv, *p1, *p2, *shift, *scale;
    int *degn, *dege, *rstart, *cstart, *rcur, *ccur, *rcsr, *ccsr;
    cudaGetSymbolAddress((void**)&xl, g_xl);
    cudaGetSymbolAddress((void**)&el, g_el);
    cudaGetSymbolAddress((void**)&ef, g_ef);
    cudaGetSymbolAddress((void**)&h, g_h);
    cudaGetSymbolAddress((void**)&fc, g_fc);
    cudaGetSymbolAddress((void**)&xn, g_xn);
    cudaGetSymbolAddress((void**)&en, g_en);
    cudaGetSymbolAddress((void**)&alpha, g_alpha);
    cudaGetSymbolAddress((void**)&Dinv, g_Dinv);
    cudaGetSymbolAddress((void**)&Binv, g_Binv);
    cudaGetSymbolAddress((void**)&p1, g_p1);
    cudaGetSymbolAddress((void**)&p2, g_p2);
    cudaGetSymbolAddress((void**)&shift, g_shift);
    cudaGetSymbolAddress((void**)&scale, g_scale);
    cudaGetSymbolAddress((void**)&degn, g_degn);
    cudaGetSymbolAddress((void**)&dege, g_dege);
    cudaGetSymbolAddress((void**)&rstart, g_rstart);
    cudaGetSymbolAddress((void**)&cstart, g_cstart);
    cudaGetSymbolAddress((void**)&rcur, g_rcur);
    cudaGetSymbolAddress((void**)&ccur, g_ccur);
    cudaGetSymbolAddress((void**)&rcsr, g_rcsr);
    cudaGetSymbolAddress((void**)&ccsr, g_ccsr);

    // ---- graph structure (edge_index only) ----
    k_zero_i<<<(NN + 255) / 256, 256>>>(degn, NN);
    k_zero_i<<<(MM + 255) / 256, 256>>>(dege, MM);
    k_hist<<<(EE + 255) / 256, 256>>>(row, col, degn, dege, EE);
    k_exscan<<<1, 1024>>>(dege, cstart, MM);
    k_exscan<<<1, 1024>>>(degn, rstart, NN);
    k_copy_i<<<(MM + 255) / 256, 256>>>(cstart, ccur, MM);
    k_copy_i<<<(NN + 255) / 256, 256>>>(rstart, rcur, NN);
    k_scatter<<<(EE + 255) / 256, 256>>>(row, col, rcur, ccur, rcsr, ccsr, EE);
    k_inv<<<(NN + 255) / 256, 256>>>(degn, Dinv, NN);
    k_inv<<<(MM + 255) / 256, 256>>>(dege, Binv, MM);

    const float rows_inv = 1.0f / (float)NN;
    dim3 gN(FF / 128, (NN + 127) / 128);   // (4, 157)
    dim3 gM(FF / 128, MM / 128);           // (4, 16)
    dim3 gFC(HIDD / 128, (NN + 127) / 128);// (2, 157)

    // ---- conv1 ----
    k_sgemm<0><<<gN, 256>>>(x, W1, xl, NN, FF, FF, nullptr);
    k_sgemm<0><<<gM, 256>>>(ea, W1, el, MM, FF, FF, nullptr);
    k_rowdot<<<(NN * 32 + 255) / 256, 256>>>(xl, att1, xn, NN);
    k_rowdot<<<(MM * 32 + 255) / 256, 256>>>(el, att1 + FF, en, MM);
    k_attn<<<MM, 128>>>(cstart, ccsr, row, xn, en, alpha);
    k_prop1<<<MM, 256>>>(cstart, ccsr, row, alpha, Binv, xl, ef);
    k_prop2<<<NN, 128>>>(rstart, rcsr, col, alpha, Dinv, ef, b1, h);
    // graph_norm 1 + leaky_relu (in place)
    k_colstat<<<CSTAT_BLKS, FF>>>(h, p1, p2, NN);
    k_statfin<<<1, FF>>>(p1, p2, CSTAT_BLKS, gn1w, gn1ms, shift, scale, rows_inv);
    k_normapply<<<(NN * (FF / 4) + 255) / 256, 256>>>(h, shift, scale, gn1b, h, NN * (FF / 4));
    // fc1: out = lrelu(h @ fc1_W + b)
    k_sgemm<1><<<gFC, 256>>>(h, fc1W, fc, NN, HIDD, FF, fc1b);

    // ---- conv2 (input = h) ----
    k_sgemm<0><<<gN, 256>>>(h, W2, xl, NN, FF, FF, nullptr);
    k_sgemm<0><<<gM, 256>>>(ea, W2, el, MM, FF, FF, nullptr);
    k_rowdot<<<(NN * 32 + 255) / 256, 256>>>(xl, att2, xn, NN);
    k_rowdot<<<(MM * 32 + 255) / 256, 256>>>(el, att2 + FF, en, MM);
    k_attn<<<MM, 128>>>(cstart, ccsr, row, xn, en, alpha);
    k_prop1<<<MM, 256>>>(cstart, ccsr, row, alpha, Binv, xl, ef);
    k_prop2<<<NN, 128>>>(rstart, rcsr, col, alpha, Dinv, ef, b2, h);
    // graph_norm 2 + leaky_relu (in place)
    k_colstat<<<CSTAT_BLKS, FF>>>(h, p1, p2, NN);
    k_statfin<<<1, FF>>>(p1, p2, CSTAT_BLKS, gn2w, gn2ms, shift, scale, rows_inv);
    k_normapply<<<(NN * (FF / 4) + 255) / 256, 256>>>(h, shift, scale, gn2b, h, NN * (FF / 4));
    // fc2: out += lrelu(h @ fc2_W + b)
    k_sgemm<2><<<gFC, 256>>>(h, fc2W, fc, NN, HIDD, FF, fc2b);

    // ---- classifier ----
    k_cls<<<(NN * 32 + 255) / 256, 256>>>(fc, clsW, clsb, outp, NN);
}

// round 4
// speedup vs baseline: 1.2576x; 1.2576x over previous
#include <cuda_runtime.h>
#include <cuda_bf16.h>
#include <mma.h>
#include <cstdint>
#include <math.h>

using namespace nvcuda;

#define NN 20000
#define MM 2048
#define EE 320000
#define FF 512
#define HIDD 256
#define CSTAT_ROWS 128
#define CSTAT_BLKS ((NN + CSTAT_ROWS - 1) / CSTAT_ROWS)   // 157

#define NEG_SLOPE 0.01f
#define ATT_SLOPE 0.2f

// ---------------- scratch (static device allocations; no runtime alloc) ----------------
__device__ float g_xl[NN * FF];
__device__ float g_el[MM * FF];
__device__ float g_ef[MM * FF];
__device__ float g_h[NN * FF];
__device__ float g_fc[NN * HIDD];
__device__ float g_xn[NN];
__device__ float g_en[MM];
__device__ float g_alpha[EE];
__device__ float g_Dinv[NN];
__device__ float g_Binv[MM];
__device__ int   g_degn[NN];
__device__ int   g_dege[MM];
__device__ int   g_rstart[NN + 1];
__device__ int   g_cstart[MM + 1];
__device__ int   g_rcur[NN];
__device__ int   g_ccur[MM];
__device__ int   g_rcsr[EE];
__device__ int   g_ccsr[EE];
__device__ float g_p1[CSTAT_BLKS * FF];
__device__ float g_p2[CSTAT_BLKS * FF];
__device__ float g_shift[FF];
__device__ float g_scale[FF];
// bf16 split operands
__device__ __nv_bfloat16 g_Ahi[NN * FF];
__device__ __nv_bfloat16 g_Alo[NN * FF];
__device__ __nv_bfloat16 g_eahi[MM * FF];
__device__ __nv_bfloat16 g_ealo[MM * FF];
__device__ __nv_bfloat16 g_W1thi[FF * FF];
__device__ __nv_bfloat16 g_W1tlo[FF * FF];
__device__ __nv_bfloat16 g_W2thi[FF * FF];
__device__ __nv_bfloat16 g_W2tlo[FF * FF];
__device__ __nv_bfloat16 g_f1thi[HIDD * FF];
__device__ __nv_bfloat16 g_f1tlo[HIDD * FF];
__device__ __nv_bfloat16 g_f2thi[HIDD * FF];
__device__ __nv_bfloat16 g_f2tlo[HIDD * FF];

// ---------------- wmma split-bf16 GEMM ----------------
// C[Mr,Nc] = (Ahi+Alo)[Mr,K] @ B[K,Nc], B stored transposed [Nc,K] (K-contiguous).
// Accumulates hi*hi + lo*hi + hi*lo into the same fp32 fragments (3-term split).
// MODE 0: store; MODE 1: store lrelu(AB+bias); MODE 2: C += lrelu(AB+bias)
#define APAD 72   // 64 + 8 pad (bf16 elems): keeps 16-row tile origins 32B-aligned
template <int MODE>
__global__ void __launch_bounds__(256) k_wgemm(
    const __nv_bfloat16* __restrict__ Ahi, const __nv_bfloat16* __restrict__ Alo,
    const __nv_bfloat16* __restrict__ Bthi, const __nv_bfloat16* __restrict__ Btlo,
    float* __restrict__ C, int Mr, int Nc, int Kd, const float* __restrict__ bias) {
    __shared__ __nv_bfloat16 As[128][APAD];
    __shared__ __nv_bfloat16 Bs[128][APAD];
    __shared__ float stage[8][256];

    const int tid = threadIdx.x;
    const int wid = tid >> 5;
    const int lane = tid & 31;
    const int wm = wid >> 2;      // 0..1 : 64-row group
    const int wn = wid & 3;       // 0..3 : 32-col group
    const int bm = blockIdx.y * 128;
    const int bn = blockIdx.x * 128;

    wmma::fragment<wmma::accumulator, 16, 16, 16, float> acc[4][2];
#pragma unroll
    for (int i = 0; i < 4; i++)
#pragma unroll
        for (int j = 0; j < 2; j++) wmma::fill_fragment(acc[i][j], 0.0f);

    // global load indices: 128 rows x 8 uint4 (64 bf16) per tile; 4 uint4 per thread
    const int lr = tid >> 1;             // 0..127 row (2 threads per row, 4 uint4 each)
    const int lc = (tid & 1) * 4;        // starting uint4 within row

    for (int seg = 0; seg < 3; seg++) {
        const __nv_bfloat16* A = (seg == 1) ? Alo : Ahi;
        const __nv_bfloat16* B = (seg == 2) ? Btlo : Bthi;
        for (int k0 = 0; k0 < Kd; k0 += 64) {
            // load A tile (rows clamped) and B tile
            {
                int ga = bm + lr;
                ga = min(ga, Mr - 1);
                const uint4* arow = (const uint4*)(A + (size_t)ga * Kd + k0);
                const uint4* brow = (const uint4*)(B + (size_t)(bn + lr) * Kd + k0);
                uint4* asm_ = (uint4*)&As[lr][0];
                uint4* bsm_ = (uint4*)&Bs[lr][0];
#pragma unroll
                for (int u = 0; u < 4; u++) {
                    asm_[lc + u] = arow[lc + u];
                    bsm_[lc + u] = brow[lc + u];
                }
            }
            __syncthreads();
#pragma unroll
            for (int kt = 0; kt < 4; kt++) {
                wmma::fragment<wmma::matrix_a, 16, 16, 16, __nv_bfloat16, wmma::row_major> af[4];
                wmma::fragment<wmma::matrix_b, 16, 16, 16, __nv_bfloat16, wmma::col_major> bf[2];
#pragma unroll
                for (int n = 0; n < 2; n++)
                    wmma::load_matrix_sync(bf[n], &Bs[wn * 32 + n * 16][kt * 16], APAD);
#pragma unroll
                for (int m = 0; m < 4; m++)
                    wmma::load_matrix_sync(af[m], &As[wm * 64 + m * 16][kt * 16], APAD);
#pragma unroll
                for (int m = 0; m < 4; m++)
#pragma unroll
                    for (int n = 0; n < 2; n++)
                        wmma::mma_sync(acc[m][n], af[m], bf[n], acc[m][n]);
            }
            __syncthreads();
        }
    }

    // epilogue: per-warp staging through private smem patch (no cross-warp sync needed)
    const int srow = lane >> 1;          // 0..15
    const int scol = (lane & 1) * 8;     // 0 or 8
#pragma unroll
    for (int m = 0; m < 4; m++) {
#pragma unroll
        for (int n = 0; n < 2; n++) {
            wmma::store_matrix_sync(&stage[wid][0], acc[m][n], 16, wmma::mem_row_major);
            __syncwarp();
            int grow = bm + wm * 64 + m * 16 + srow;
            int gcol = bn + wn * 32 + n * 16 + scol;
            if (grow < Mr) {
                float* crow = C + (size_t)grow * Nc + gcol;
                const float* sp = &stage[wid][srow * 16 + scol];
#pragma unroll
                for (int q = 0; q < 2; q++) {
                    float4 v = *(const float4*)(sp + q * 4);
                    if (MODE >= 1) {
                        float4 bb = *(const float4*)(bias + gcol + q * 4);
                        v.x += bb.x; v.y += bb.y; v.z += bb.z; v.w += bb.w;
                        v.x = (v.x > 0.f) ? v.x : NEG_SLOPE * v.x;
                        v.y = (v.y > 0.f) ? v.y : NEG_SLOPE * v.y;
                        v.z = (v.z > 0.f) ? v.z : NEG_SLOPE * v.z;
                        v.w = (v.w > 0.f) ? v.w : NEG_SLOPE * v.w;
                    }
                    if (MODE == 2) {
                        float4 o = *(const float4*)(crow + q * 4);
                        v.x += o.x; v.y += o.y; v.z += o.z; v.w += o.w;
                    }
                    *(float4*)(crow + q * 4) = v;
                }
            }
            __syncwarp();
        }
    }
}

// ---------------- conversion kernels ----------------
__global__ void k_split(const float* __restrict__ X, __nv_bfloat16* __restrict__ hi,
                        __nv_bfloat16* __restrict__ lo, int total4) {
    int i = blockIdx.x * blockDim.x + threadIdx.x;
    if (i >= total4) return;
    float4 v = ((const float4*)X)[i];
    __nv_bfloat16 h0 = __float2bfloat16(v.x), h1 = __float2bfloat16(v.y);
    __nv_bfloat16 h2 = __float2bfloat16(v.z), h3 = __float2bfloat16(v.w);
    __nv_bfloat16 l0 = __float2bfloat16(v.x - __bfloat162float(h0));
    __nv_bfloat16 l1 = __float2bfloat16(v.y - __bfloat162float(h1));
    __nv_bfloat16 l2 = __float2bfloat16(v.z - __bfloat162float(h2));
    __nv_bfloat16 l3 = __float2bfloat16(v.w - __bfloat162float(h3));
    ((__nv_bfloat162*)hi)[i * 2]     = __nv_bfloat162(h0, h1);
    ((__nv_bfloat162*)hi)[i * 2 + 1] = __nv_bfloat162(h2, h3);
    ((__nv_bfloat162*)lo)[i * 2]     = __nv_bfloat162(l0, l1);
    ((__nv_bfloat162*)lo)[i * 2 + 1] = __nv_bfloat162(l2, l3);
}

__global__ void k_wsplit(const float* __restrict__ W, __nv_bfloat16* __restrict__ thi,
                         __nv_bfloat16* __restrict__ tlo, int K, int N) {
    int i = blockIdx.x * blockDim.x + threadIdx.x;
    if (i >= K * N) return;
    int n = i / K, k = i - n * K;
    float v = W[(size_t)k * N + n];
    __nv_bfloat16 h = __float2bfloat16(v);
    thi[i] = h;
    tlo[i] = __float2bfloat16(v - __bfloat162float(h));
}

// ---------------- small utility kernels ----------------
__global__ void k_zero_i(int* p, int n) {
    int i = blockIdx.x * blockDim.x + threadIdx.x;
    if (i < n) p[i] = 0;
}

__global__ void k_copy_i(const int* __restrict__ a, int* __restrict__ b, int n) {
    int i = blockIdx.x * blockDim.x + threadIdx.x;
    if (i < n) b[i] = a[i];
}

__global__ void k_hist(const int* __restrict__ row, const int* __restrict__ col,
                       int* degn, int* dege, int E) {
    int i = blockIdx.x * blockDim.x + threadIdx.x;
    if (i < E) {
        atomicAdd(&degn[row[i]], 1);
        atomicAdd(&dege[col[i]], 1);
    }
}

__global__ void k_exscan(const int* __restrict__ cnt, int* __restrict__ start, int n) {
    __shared__ int sh[1024];
    int tid = threadIdx.x;
    int per = (n + 1023) >> 10;
    int lo = tid * per;
    int hi = min(lo + per, n);
    int s = 0;
    for (int i = lo; i < hi; i++) s += cnt[i];
    sh[tid] = s;
    __syncthreads();
    for (int off = 1; off < 1024; off <<= 1) {
        int add = (tid >= off) ? sh[tid - off] : 0;
        __syncthreads();
        sh[tid] += add;
        __syncthreads();
    }
    int run = (tid == 0) ? 0 : sh[tid - 1];
    for (int i = lo; i < hi; i++) { start[i] = run; run += cnt[i]; }
    if (tid == 0) start[n] = sh[1023];
}

__global__ void k_scatter(const int* __restrict__ row, const int* __restrict__ col,
                          int* rcur, int* ccur, int* __restrict__ rcsr,
                          int* __restrict__ ccsr, int E) {
    int i = blockIdx.x * blockDim.x + threadIdx.x;
    if (i < E) {
        int pr = atomicAdd(&rcur[row[i]], 1);
        rcsr[pr] = i;
        int pc = atomicAdd(&ccur[col[i]], 1);
        ccsr[pc] = i;
    }
}

__global__ void k_inv(const int* __restrict__ deg, float* __restrict__ inv, int n) {
    int i = blockIdx.x * blockDim.x + threadIdx.x;
    if (i < n) {
        int d = deg[i];
        inv[i] = (d > 0) ? (1.0f / (float)d) : 0.0f;
    }
}

__global__ void k_rowdot(const float* __restrict__ X, const float* __restrict__ v,
                         float* __restrict__ out, int rows) {
    int gw = (blockIdx.x * blockDim.x + threadIdx.x) >> 5;
    int lane = threadIdx.x & 31;
    if (gw >= rows) return;
    const float4* xr = (const float4*)(X + (size_t)gw * FF);
    const float4* vv = (const float4*)v;
    float s = 0.f;
#pragma unroll
    for (int j = 0; j < 4; j++) {
        float4 a = xr[lane + 32 * j];
        float4 b = vv[lane + 32 * j];
        s += a.x * b.x + a.y * b.y + a.z * b.z + a.w * b.w;
    }
    for (int o = 16; o; o >>= 1) s += __shfl_down_sync(0xffffffffu, s, o);
    if (!lane) out[gw] = s;
}

__global__ void k_attn(const int* __restrict__ cstart, const int* __restrict__ ccsr,
                       const int* __restrict__ row, const float* __restrict__ xn,
                       const float* __restrict__ en, float* __restrict__ alpha) {
    int m = blockIdx.x;
    int s = cstart[m], e = cstart[m + 1];
    __shared__ float red[128];
    int tid = threadIdx.x;
    float enm = en[m];
    float mx = -3.0e38f;
    for (int i = s + tid; i < e; i += 128) {
        int ed = ccsr[i];
        float p = xn[row[ed]] + enm;
        p = (p > 0.f) ? p : ATT_SLOPE * p;
        alpha[ed] = p;
        mx = fmaxf(mx, p);
    }
    red[tid] = mx;
    __syncthreads();
    for (int o = 64; o; o >>= 1) {
        if (tid < o) red[tid] = fmaxf(red[tid], red[tid + o]);
        __syncthreads();
    }
    float amax = red[0];
    if (!(amax > -1e37f)) amax = 0.f;
    __syncthreads();
    float sm = 0.f;
    for (int i = s + tid; i < e; i += 128) {
        int ed = ccsr[i];
        float ex = expf(alpha[ed] - amax);
        alpha[ed] = ex;
        sm += ex;
    }
    red[tid] = sm;
    __syncthreads();
    for (int o = 64; o; o >>= 1) {
        if (tid < o) red[tid] += red[tid + o];
        __syncthreads();
    }
    float inv = 1.f / fmaxf(red[0], 1e-16f);
    for (int i = s + tid; i < e; i += 128) alpha[ccsr[i]] *= inv;
}

__global__ void k_prop1(const int* __restrict__ cstart, const int* __restrict__ ccsr,
                        const int* __restrict__ row, const float* __restrict__ alpha,
                        const float* __restrict__ Binv, const float* __restrict__ xl,
                        float* __restrict__ ef) {
    int m = blockIdx.x;
    int s = cstart[m], e = cstart[m + 1];
    __shared__ int   shr[256];
    __shared__ float shc[256];
    int tid = threadIdx.x;
    float ax = 0.f, ay = 0.f;
    const float* base = xl + 2 * tid;
    for (int b0 = s; b0 < e; b0 += 256) {
        int cnt = min(256, e - b0);
        __syncthreads();
        if (tid < cnt) {
            int ed = ccsr[b0 + tid];
            shr[tid] = row[ed];
            shc[tid] = alpha[ed];
        }
        __syncthreads();
        for (int j = 0; j < cnt; j++) {
            float2 v = *(const float2*)(base + (size_t)shr[j] * FF);
            float cf = shc[j];
            ax += cf * v.x;
            ay += cf * v.y;
        }
    }
    float bi = Binv[m];
    float2 o;
    o.x = ax * bi; o.y = ay * bi;
    *(float2*)(ef + (size_t)m * FF + 2 * tid) = o;
}

__global__ void k_prop2(const int* __restrict__ rstart, const int* __restrict__ rcsr,
                        const int* __restrict__ col, const float* __restrict__ alpha,
                        const float* __restrict__ Dinv, const float* __restrict__ ef,
                        const float* __restrict__ bias, float* __restrict__ out) {
    int n = blockIdx.x;
    int s = rstart[n], e = rstart[n + 1];
    int tid = threadIdx.x;
    float a0 = 0.f, a1 = 0.f, a2 = 0.f, a3 = 0.f;
    for (int i = s; i < e; i++) {
        int ed = rcsr[i];
        float cf = alpha[ed];
        float4 v = *(const float4*)(ef + (size_t)col[ed] * FF + 4 * tid);
        a0 += cf * v.x; a1 += cf * v.y; a2 += cf * v.z; a3 += cf * v.w;
    }
    float d = Dinv[n];
    float4 b = *(const float4*)(bias + 4 * tid);
    float4 o;
    o.x = a0 * d + b.x; o.y = a1 * d + b.y; o.z = a2 * d + b.z; o.w = a3 * d + b.w;
    *(float4*)(out + (size_t)n * FF + 4 * tid) = o;
}

__global__ void k_colstat(const float* __restrict__ X, float* __restrict__ p1,
                          float* __restrict__ p2, int rows) {
    int b = blockIdx.x;
    int c = threadIdx.x;
    int r0 = b * CSTAT_ROWS, r1 = min(r0 + CSTAT_ROWS, rows);
    float s1 = 0.f, s2 = 0.f;
    for (int r = r0; r < r1; r++) {
        float v = X[(size_t)r * FF + c];
        s1 += v;
        s2 += v * v;
    }
    p1[b * FF + c] = s1;
    p2[b * FF + c] = s2;
}

__global__ void k_statfin(const float* __restrict__ p1, const float* __restrict__ p2,
                          int nblk, const float* __restrict__ w,
                          const float* __restrict__ ms, float* __restrict__ shift,
                          float* __restrict__ scale, float rows_inv) {
    int c = threadIdx.x;
    float s1 = 0.f, s2 = 0.f;
    for (int i = 0; i < nblk; i++) {
        s1 += p1[i * FF + c];
        s2 += p2[i * FF + c];
    }
    float mu = s1 * rows_inv;
    float ex2 = s2 * rows_inv;
    float m = ms[c];
    float sh = m * mu;
    float var = ex2 - sh * (2.f * mu - sh);
    shift[c] = sh;
    scale[c] = w[c] / sqrtf(var + 1e-5f);
}

__global__ void k_normsplit(const float* __restrict__ X, const float* __restrict__ shift,
                            const float* __restrict__ scale, const float* __restrict__ beta,
                            __nv_bfloat16* __restrict__ hi, __nv_bfloat16* __restrict__ lo,
                            int total4) {
    int i = blockIdx.x * blockDim.x + threadIdx.x;
    if (i >= total4) return;
    int c = (i & 127) * 4;
    float4 v = ((const float4*)X)[i];
    float4 sh = *(const float4*)(shift + c);
    float4 sc = *(const float4*)(scale + c);
    float4 be = *(const float4*)(beta + c);
    float y0 = (v.x - sh.x) * sc.x + be.x;
    float y1 = (v.y - sh.y) * sc.y + be.y;
    float y2 = (v.z - sh.z) * sc.z + be.z;
    float y3 = (v.w - sh.w) * sc.w + be.w;
    y0 = (y0 > 0.f) ? y0 : NEG_SLOPE * y0;
    y1 = (y1 > 0.f) ? y1 : NEG_SLOPE * y1;
    y2 = (y2 > 0.f) ? y2 : NEG_SLOPE * y2;
    y3 = (y3 > 0.f) ? y3 : NEG_SLOPE * y3;
    __nv_bfloat16 h0 = __float2bfloat16(y0), h1 = __float2bfloat16(y1);
    __nv_bfloat16 h2 = __float2bfloat16(y2), h3 = __float2bfloat16(y3);
    __nv_bfloat16 l0 = __float2bfloat16(y0 - __bfloat162float(h0));
    __nv_bfloat16 l1 = __float2bfloat16(y1 - __bfloat162float(h1));
    __nv_bfloat16 l2 = __float2bfloat16(y2 - __bfloat162float(h2));
    __nv_bfloat16 l3 = __float2bfloat16(y3 - __bfloat162float(h3));
    ((__nv_bfloat162*)hi)[i * 2]     = __nv_bfloat162(h0, h1);
    ((__nv_bfloat162*)hi)[i * 2 + 1] = __nv_bfloat162(h2, h3);
    ((__nv_bfloat162*)lo)[i * 2]     = __nv_bfloat162(l0, l1);
    ((__nv_bfloat162*)lo)[i * 2 + 1] = __nv_bfloat162(l2, l3);
}

__global__ void k_cls(const float* __restrict__ A, const float* __restrict__ W,
                      const float* __restrict__ b, float* __restrict__ out, int rows) {
    int gw = (blockIdx.x * blockDim.x + threadIdx.x) >> 5;
    int lane = threadIdx.x & 31;
    if (gw >= rows) return;
    const float* ar = A + (size_t)gw * HIDD;
    float s0 = 0.f, s1 = 0.f;
    for (int h = lane; h < HIDD; h += 32) {
        float v = ar[h];
        s0 += v * W[h * 2];
        s1 += v * W[h * 2 + 1];
    }
    for (int o = 16; o; o >>= 1) {
        s0 += __shfl_down_sync(0xffffffffu, s0, o);
        s1 += __shfl_down_sync(0xffffffffu, s1, o);
    }
    if (!lane) {
        out[gw * 2] = s0 + b[0];
        out[gw * 2 + 1] = s1 + b[1];
    }
}

// ---------------- host launch ----------------
extern "C" void kernel_launch(void* const* d_in, const int* in_sizes, int n_in,
                              void* d_out, int out_size) {
    const float* x    = (const float*)d_in[0];
    const int*   ei   = (const int*)d_in[1];
    const float* ea   = (const float*)d_in[2];
    const float* W1   = (const float*)d_in[3];
    const float* att1 = (const float*)d_in[4];
    const float* b1   = (const float*)d_in[5];
    const float* W2   = (const float*)d_in[6];
    const float* att2 = (const float*)d_in[7];
    const float* b2   = (const float*)d_in[8];
    const float* gn1w = (const float*)d_in[9];
    const float* gn1b = (const float*)d_in[10];
    const float* gn1ms= (const float*)d_in[11];
    const float* gn2w = (const float*)d_in[12];
    const float* gn2b = (const float*)d_in[13];
    const float* gn2ms= (const float*)d_in[14];
    const float* fc1W = (const float*)d_in[15];
    const float* fc1b = (const float*)d_in[16];
    const float* fc2W = (const float*)d_in[17];
    const float* fc2b = (const float*)d_in[18];
    const float* clsW = (const float*)d_in[19];
    const float* clsb = (const float*)d_in[20];
    float* outp = (float*)d_out;

    const int* row = ei;
    const int* col = ei + EE;

    float *xl, *el, *ef, *h, *fc, *xn, *en, *alpha, *Dinv, *Binv, *p1, *p2, *shift, *scale;
    int *degn, *dege, *rstart, *cstart, *rcur, *ccur, *rcsr, *ccsr;
    __nv_bfloat16 *Ahi, *Alo, *eahi, *ealo, *W1thi, *W1tlo, *W2thi, *W2tlo;
    __nv_bfloat16 *f1thi, *f1tlo, *f2thi, *f2tlo;
    cudaGetSymbolAddress((void**)&xl, g_xl);
    cudaGetSymbolAddress((void**)&el, g_el);
    cudaGetSymbolAddress((void**)&ef, g_ef);
    cudaGetSymbolAddress((void**)&h, g_h);
    cudaGetSymbolAddress((void**)&fc, g_fc);
    cudaGetSymbolAddress((void**)&xn, g_xn);
    cudaGetSymbolAddress((void**)&en, g_en);
    cudaGetSymbolAddress((void**)&alpha, g_alpha);
    cudaGetSymbolAddress((void**)&Dinv, g_Dinv);
    cudaGetSymbolAddress((void**)&Binv, g_Binv);
    cudaGetSymbolAddress((void**)&p1, g_p1);
    cudaGetSymbolAddress((void**)&p2, g_p2);
    cudaGetSymbolAddress((void**)&shift, g_shift);
    cudaGetSymbolAddress((void**)&scale, g_scale);
    cudaGetSymbolAddress((void**)&degn, g_degn);
    cudaGetSymbolAddress((void**)&dege, g_dege);
    cudaGetSymbolAddress((void**)&rstart, g_rstart);
    cudaGetSymbolAddress((void**)&cstart, g_cstart);
    cudaGetSymbolAddress((void**)&rcur, g_rcur);
    cudaGetSymbolAddress((void**)&ccur, g_ccur);
    cudaGetSymbolAddress((void**)&rcsr, g_rcsr);
    cudaGetSymbolAddress((void**)&ccsr, g_ccsr);
    cudaGetSymbolAddress((void**)&Ahi, g_Ahi);
    cudaGetSymbolAddress((void**)&Alo, g_Alo);
    cudaGetSymbolAddress((void**)&eahi, g_eahi);
    cudaGetSymbolAddress((void**)&ealo, g_ealo);
    cudaGetSymbolAddress((void**)&W1thi, g_W1thi);
    cudaGetSymbolAddress((void**)&W1tlo, g_W1tlo);
    cudaGetSymbolAddress((void**)&W2thi, g_W2thi);
    cudaGetSymbolAddress((void**)&W2tlo, g_W2tlo);
    cudaGetSymbolAddress((void**)&f1thi, g_f1thi);
    cudaGetSymbolAddress((void**)&f1tlo, g_f1tlo);
    cudaGetSymbolAddress((void**)&f2thi, g_f2thi);
    cudaGetSymbolAddress((void**)&f2tlo, g_f2tlo);

    // ---- graph structure (edge_index only) ----
    k_zero_i<<<(NN + 255) / 256, 256>>>(degn, NN);
    k_zero_i<<<(MM + 255) / 256, 256>>>(dege, MM);
    k_hist<<<(EE + 255) / 256, 256>>>(row, col, degn, dege, EE);
    k_exscan<<<1, 1024>>>(dege, cstart, MM);
    k_exscan<<<1, 1024>>>(degn, rstart, NN);
    k_copy_i<<<(MM + 255) / 256, 256>>>(cstart, ccur, MM);
    k_copy_i<<<(NN + 255) / 256, 256>>>(rstart, rcur, NN);
    k_scatter<<<(EE + 255) / 256, 256>>>(row, col, rcur, ccur, rcsr, ccsr, EE);
    k_inv<<<(NN + 255) / 256, 256>>>(degn, Dinv, NN);
    k_inv<<<(MM + 255) / 256, 256>>>(dege, Binv, MM);

    // ---- operand conversions ----
    k_wsplit<<<(FF * FF + 255) / 256, 256>>>(W1, W1thi, W1tlo, FF, FF);
    k_wsplit<<<(FF * FF + 255) / 256, 256>>>(W2, W2thi, W2tlo, FF, FF);
    k_wsplit<<<(FF * HIDD + 255) / 256, 256>>>(fc1W, f1thi, f1tlo, FF, HIDD);
    k_wsplit<<<(FF * HIDD + 255) / 256, 256>>>(fc2W, f2thi, f2tlo, FF, HIDD);
    k_split<<<(NN * (FF / 4) + 255) / 256, 256>>>(x, Ahi, Alo, NN * (FF / 4));
    k_split<<<(MM * (FF / 4) + 255) / 256, 256>>>(ea, eahi, ealo, MM * (FF / 4));

    const float rows_inv = 1.0f / (float)NN;
    dim3 gN(FF / 128, (NN + 127) / 128);    // (4, 157)
    dim3 gM(FF / 128, MM / 128);            // (4, 16)
    dim3 gFC(HIDD / 128, (NN + 127) / 128); // (2, 157)

    // ---- conv1 ----
    k_wgemm<0><<<gN, 256>>>(Ahi, Alo, W1thi, W1tlo, xl, NN, FF, FF, nullptr);
    k_wgemm<0><<<gM, 256>>>(eahi, ealo, W1thi, W1tlo, el, MM, FF, FF, nullptr);
    k_rowdot<<<(NN * 32 + 255) / 256, 256>>>(xl, att1, xn, NN);
    k_rowdot<<<(MM * 32 + 255) / 256, 256>>>(el, att1 + FF, en, MM);
    k_attn<<<MM, 128>>>(cstart, ccsr, row, xn, en, alpha);
    k_prop1<<<MM, 256>>>(cstart, ccsr, row, alpha, Binv, xl, ef);
    k_prop2<<<NN, 128>>>(rstart, rcsr, col, alpha, Dinv, ef, b1, h);
    // graph_norm 1 + leaky_relu -> bf16 split (overwrites x split, no longer needed)
    k_colstat<<<CSTAT_BLKS, FF>>>(h, p1, p2, NN);
    k_statfin<<<1, FF>>>(p1, p2, CSTAT_BLKS, gn1w, gn1ms, shift, scale, rows_inv);
    k_normsplit<<<(NN * (FF / 4) + 255) / 256, 256>>>(h, shift, scale, gn1b, Ahi, Alo, NN * (FF / 4));
    // fc1: out = lrelu(h @ fc1_W + b)
    k_wgemm<1><<<gFC, 256>>>(Ahi, Alo, f1thi, f1tlo, fc, NN, HIDD, FF, fc1b);

    // ---- conv2 (input = h split in Ahi/Alo) ----
    k_wgemm<0><<<gN, 256>>>(Ahi, Alo, W2thi, W2tlo, xl, NN, FF, FF, nullptr);
    k_wgemm<0><<<gM, 256>>>(eahi, ealo, W2thi, W2tlo, el, MM, FF, FF, nullptr);
    k_rowdot<<<(NN * 32 + 255) / 256, 256>>>(xl, att2, xn, NN);
    k_rowdot<<<(MM * 32 + 255) / 256, 256>>>(el, att2 + FF, en, MM);
    k_attn<<<MM, 128>>>(cstart, ccsr, row, xn, en, alpha);
    k_prop1<<<MM, 256>>>(cstart, ccsr, row, alpha, Binv, xl, ef);
    k_prop2<<<NN, 128>>>(rstart, rcsr, col, alpha, Dinv, ef, b2, h);
    // graph_norm 2 + leaky_relu -> bf16 split
    k_colstat<<<CSTAT_BLKS, FF>>>(h, p1, p2, NN);
    k_statfin<<<1, FF>>>(p1, p2, CSTAT_BLKS, gn2w, gn2ms, shift, scale, rows_inv);
    k_normsplit<<<(NN * (FF / 4) + 255) / 256, 256>>>(h, shift, scale, gn2b, Ahi, Alo, NN * (FF / 4));
    // fc2: out += lrelu(h @ fc2_W + b)
    k_wgemm<2><<<gFC, 256>>>(Ahi, Alo, f2thi, f2tlo, fc, NN, HIDD, FF, fc2b);

    // ---- classifier ----
    k_cls<<<(NN * 32 + 255) / 256, 256>>>(fc, clsW, clsb, outp, NN);
}

// round 5
// speedup vs baseline: 1.8346x; 1.4588x over previous
#include <cuda_runtime.h>
#include <cuda_bf16.h>
#include <mma.h>
#include <cstdint>
#include <math.h>

using namespace nvcuda;

#define NN 20000
#define MM 2048
#define EE 320000
#define FF 512
#define HIDD 256
#define CSTAT_ROWS 128
#define CSTAT_BLKS ((NN + CSTAT_ROWS - 1) / CSTAT_ROWS)   // 157

#define NEG_SLOPE 0.01f
#define ATT_SLOPE 0.2f

// ---------------- scratch ----------------
__device__ float g_xl[NN * FF];       // conv outputs (node space)
__device__ float g_el[MM * FF];       // ef (edge_feat after GEMM)
__device__ float g_ef[MM * FF];       // ef_raw (pre-GEMM propagated input feats)
__device__ float g_h[NN * FF];        // normalized node features (fp32)
__device__ float g_fc[NN * HIDD];
__device__ float g_xn[NN];
__device__ float g_en[MM];
__device__ float g_wa[FF];
__device__ float g_wb[FF];
__device__ float g_alpha[EE];
__device__ float g_Dinv[NN];
__device__ float g_Binv[MM];
__device__ int   g_degn[NN];
__device__ int   g_dege[MM];
__device__ int   g_rstart[NN + 1];
__device__ int   g_cstart[MM + 1];
__device__ int   g_rcur[NN];
__device__ int   g_ccur[MM];
__device__ int   g_rcsr[EE];
__device__ int   g_ccsr[EE];
__device__ float g_p1[CSTAT_BLKS * FF];
__device__ float g_p2[CSTAT_BLKS * FF];
__device__ float g_shift[FF];
__device__ float g_scale[FF];
// bf16 split operands
__device__ __nv_bfloat16 g_Ahi[NN * FF];
__device__ __nv_bfloat16 g_Alo[NN * FF];
__device__ __nv_bfloat16 g_eahi[MM * FF];   // ef_raw split
__device__ __nv_bfloat16 g_ealo[MM * FF];
__device__ __nv_bfloat16 g_W1thi[FF * FF];
__device__ __nv_bfloat16 g_W1tlo[FF * FF];
__device__ __nv_bfloat16 g_W2thi[FF * FF];
__device__ __nv_bfloat16 g_W2tlo[FF * FF];
__device__ __nv_bfloat16 g_f1thi[HIDD * FF];
__device__ __nv_bfloat16 g_f1tlo[HIDD * FF];
__device__ __nv_bfloat16 g_f2thi[HIDD * FF];
__device__ __nv_bfloat16 g_f2tlo[HIDD * FF];

// ---------------- wmma split-bf16 GEMM ----------------
#define APAD 72
template <int MODE>
__global__ void __launch_bounds__(256) k_wgemm(
    const __nv_bfloat16* __restrict__ Ahi, const __nv_bfloat16* __restrict__ Alo,
    const __nv_bfloat16* __restrict__ Bthi, const __nv_bfloat16* __restrict__ Btlo,
    float* __restrict__ C, int Mr, int Nc, int Kd, const float* __restrict__ bias) {
    __shared__ __nv_bfloat16 As[128][APAD];
    __shared__ __nv_bfloat16 Bs[128][APAD];
    __shared__ float stage[8][256];

    const int tid = threadIdx.x;
    const int wid = tid >> 5;
    const int lane = tid & 31;
    const int wm = wid >> 2;
    const int wn = wid & 3;
    const int bm = blockIdx.y * 128;
    const int bn = blockIdx.x * 128;

    wmma::fragment<wmma::accumulator, 16, 16, 16, float> acc[4][2];
#pragma unroll
    for (int i = 0; i < 4; i++)
#pragma unroll
        for (int j = 0; j < 2; j++) wmma::fill_fragment(acc[i][j], 0.0f);

    const int lr = tid >> 1;
    const int lc = (tid & 1) * 4;

    for (int seg = 0; seg < 3; seg++) {
        const __nv_bfloat16* A = (seg == 1) ? Alo : Ahi;
        const __nv_bfloat16* B = (seg == 2) ? Btlo : Bthi;
        for (int k0 = 0; k0 < Kd; k0 += 64) {
            {
                int ga = bm + lr;
                ga = min(ga, Mr - 1);
                const uint4* arow = (const uint4*)(A + (size_t)ga * Kd + k0);
                const uint4* brow = (const uint4*)(B + (size_t)(bn + lr) * Kd + k0);
                uint4* asm_ = (uint4*)&As[lr][0];
                uint4* bsm_ = (uint4*)&Bs[lr][0];
#pragma unroll
                for (int u = 0; u < 4; u++) {
                    asm_[lc + u] = arow[lc + u];
                    bsm_[lc + u] = brow[lc + u];
                }
            }
            __syncthreads();
#pragma unroll
            for (int kt = 0; kt < 4; kt++) {
                wmma::fragment<wmma::matrix_a, 16, 16, 16, __nv_bfloat16, wmma::row_major> af[4];
                wmma::fragment<wmma::matrix_b, 16, 16, 16, __nv_bfloat16, wmma::col_major> bf[2];
#pragma unroll
                for (int n = 0; n < 2; n++)
                    wmma::load_matrix_sync(bf[n], &Bs[wn * 32 + n * 16][kt * 16], APAD);
#pragma unroll
                for (int m = 0; m < 4; m++)
                    wmma::load_matrix_sync(af[m], &As[wm * 64 + m * 16][kt * 16], APAD);
#pragma unroll
                for (int m = 0; m < 4; m++)
#pragma unroll
                    for (int n = 0; n < 2; n++)
                        wmma::mma_sync(acc[m][n], af[m], bf[n], acc[m][n]);
            }
            __syncthreads();
        }
    }

    const int srow = lane >> 1;
    const int scol = (lane & 1) * 8;
#pragma unroll
    for (int m = 0; m < 4; m++) {
#pragma unroll
        for (int n = 0; n < 2; n++) {
            wmma::store_matrix_sync(&stage[wid][0], acc[m][n], 16, wmma::mem_row_major);
            __syncwarp();
            int grow = bm + wm * 64 + m * 16 + srow;
            int gcol = bn + wn * 32 + n * 16 + scol;
            if (grow < Mr) {
                float* crow = C + (size_t)grow * Nc + gcol;
                const float* sp = &stage[wid][srow * 16 + scol];
#pragma unroll
                for (int q = 0; q < 2; q++) {
                    float4 v = *(const float4*)(sp + q * 4);
                    if (MODE >= 1) {
                        float4 bb = *(const float4*)(bias + gcol + q * 4);
                        v.x += bb.x; v.y += bb.y; v.z += bb.z; v.w += bb.w;
                        v.x = (v.x > 0.f) ? v.x : NEG_SLOPE * v.x;
                        v.y = (v.y > 0.f) ? v.y : NEG_SLOPE * v.y;
                        v.z = (v.z > 0.f) ? v.z : NEG_SLOPE * v.z;
                        v.w = (v.w > 0.f) ? v.w : NEG_SLOPE * v.w;
                    }
                    if (MODE == 2) {
                        float4 o = *(const float4*)(crow + q * 4);
                        v.x += o.x; v.y += o.y; v.z += o.z; v.w += o.w;
                    }
                    *(float4*)(crow + q * 4) = v;
                }
            }
            __syncwarp();
        }
    }
}

// ---------------- conversion kernels ----------------
__global__ void k_split(const float* __restrict__ X, __nv_bfloat16* __restrict__ hi,
                        __nv_bfloat16* __restrict__ lo, int total4) {
    int i = blockIdx.x * blockDim.x + threadIdx.x;
    if (i >= total4) return;
    float4 v = ((const float4*)X)[i];
    __nv_bfloat16 h0 = __float2bfloat16(v.x), h1 = __float2bfloat16(v.y);
    __nv_bfloat16 h2 = __float2bfloat16(v.z), h3 = __float2bfloat16(v.w);
    __nv_bfloat16 l0 = __float2bfloat16(v.x - __bfloat162float(h0));
    __nv_bfloat16 l1 = __float2bfloat16(v.y - __bfloat162float(h1));
    __nv_bfloat16 l2 = __float2bfloat16(v.z - __bfloat162float(h2));
    __nv_bfloat16 l3 = __float2bfloat16(v.w - __bfloat162float(h3));
    ((__nv_bfloat162*)hi)[i * 2]     = __nv_bfloat162(h0, h1);
    ((__nv_bfloat162*)hi)[i * 2 + 1] = __nv_bfloat162(h2, h3);
    ((__nv_bfloat162*)lo)[i * 2]     = __nv_bfloat162(l0, l1);
    ((__nv_bfloat162*)lo)[i * 2 + 1] = __nv_bfloat162(l2, l3);
}

__global__ void k_wsplit(const float* __restrict__ W, __nv_bfloat16* __restrict__ thi,
                         __nv_bfloat16* __restrict__ tlo, int K, int N) {
    int i = blockIdx.x * blockDim.x + threadIdx.x;
    if (i >= K * N) return;
    int n = i / K, k = i - n * K;
    float v = W[(size_t)k * N + n];
    __nv_bfloat16 h = __float2bfloat16(v);
    thi[i] = h;
    tlo[i] = __float2bfloat16(v - __bfloat162float(h));
}

// ---------------- small utility kernels ----------------
__global__ void k_zero_i(int* p, int n) {
    int i = blockIdx.x * blockDim.x + threadIdx.x;
    if (i < n) p[i] = 0;
}

__global__ void k_copy_i(const int* __restrict__ a, int* __restrict__ b, int n) {
    int i = blockIdx.x * blockDim.x + threadIdx.x;
    if (i < n) b[i] = a[i];
}

__global__ void k_hist(const int* __restrict__ row, const int* __restrict__ col,
                       int* degn, int* dege, int E) {
    int i = blockIdx.x * blockDim.x + threadIdx.x;
    if (i < E) {
        atomicAdd(&degn[row[i]], 1);
        atomicAdd(&dege[col[i]], 1);
    }
}

__global__ void k_exscan(const int* __restrict__ cnt, int* __restrict__ start, int n) {
    __shared__ int sh[1024];
    int tid = threadIdx.x;
    int per = (n + 1023) >> 10;
    int lo = tid * per;
    int hi = min(lo + per, n);
    int s = 0;
    for (int i = lo; i < hi; i++) s += cnt[i];
    sh[tid] = s;
    __syncthreads();
    for (int off = 1; off < 1024; off <<= 1) {
        int add = (tid >= off) ? sh[tid - off] : 0;
        __syncthreads();
        sh[tid] += add;
        __syncthreads();
    }
    int run = (tid == 0) ? 0 : sh[tid - 1];
    for (int i = lo; i < hi; i++) { start[i] = run; run += cnt[i]; }
    if (tid == 0) start[n] = sh[1023];
}

__global__ void k_scatter(const int* __restrict__ row, const int* __restrict__ col,
                          int* rcur, int* ccur, int* __restrict__ rcsr,
                          int* __restrict__ ccsr, int E) {
    int i = blockIdx.x * blockDim.x + threadIdx.x;
    if (i < E) {
        int pr = atomicAdd(&rcur[row[i]], 1);
        rcsr[pr] = i;
        int pc = atomicAdd(&ccur[col[i]], 1);
        ccsr[pc] = i;
    }
}

__global__ void k_inv(const int* __restrict__ deg, float* __restrict__ inv, int n) {
    int i = blockIdx.x * blockDim.x + threadIdx.x;
    if (i < n) {
        int d = deg[i];
        inv[i] = (d > 0) ? (1.0f / (float)d) : 0.0f;
    }
}

// out[r] = dot(X[r,:512], v)   — one warp per row (row length fixed = FF)
__global__ void k_rowdot(const float* __restrict__ X, const float* __restrict__ v,
                         float* __restrict__ out, int rows) {
    int gw = (blockIdx.x * blockDim.x + threadIdx.x) >> 5;
    int lane = threadIdx.x & 31;
    if (gw >= rows) return;
    const float4* xr = (const float4*)(X + (size_t)gw * FF);
    const float4* vv = (const float4*)v;
    float s = 0.f;
#pragma unroll
    for (int j = 0; j < 4; j++) {
        float4 a = xr[lane + 32 * j];
        float4 b = vv[lane + 32 * j];
        s += a.x * b.x + a.y * b.y + a.z * b.z + a.w * b.w;
    }
    for (int o = 16; o; o >>= 1) s += __shfl_down_sync(0xffffffffu, s, o);
    if (!lane) out[gw] = s;
}

__global__ void k_attn(const int* __restrict__ cstart, const int* __restrict__ ccsr,
                       const int* __restrict__ row, const float* __restrict__ xn,
                       const float* __restrict__ en, float* __restrict__ alpha) {
    int m = blockIdx.x;
    int s = cstart[m], e = cstart[m + 1];
    __shared__ float red[128];
    int tid = threadIdx.x;
    float enm = en[m];
    float mx = -3.0e38f;
    for (int i = s + tid; i < e; i += 128) {
        int ed = ccsr[i];
        float p = xn[row[ed]] + enm;
        p = (p > 0.f) ? p : ATT_SLOPE * p;
        alpha[ed] = p;
        mx = fmaxf(mx, p);
    }
    red[tid] = mx;
    __syncthreads();
    for (int o = 64; o; o >>= 1) {
        if (tid < o) red[tid] = fmaxf(red[tid], red[tid + o]);
        __syncthreads();
    }
    float amax = red[0];
    if (!(amax > -1e37f)) amax = 0.f;
    __syncthreads();
    float sm = 0.f;
    for (int i = s + tid; i < e; i += 128) {
        int ed = ccsr[i];
        float ex = expf(alpha[ed] - amax);
        alpha[ed] = ex;
        sm += ex;
    }
    red[tid] = sm;
    __syncthreads();
    for (int o = 64; o; o >>= 1) {
        if (tid < o) red[tid] += red[tid + o];
        __syncthreads();
    }
    float inv = 1.f / fmaxf(red[0], 1e-16f);
    for (int i = s + tid; i < e; i += 128) alpha[ccsr[i]] *= inv;
}

// ef_raw[m,:] = Binv[m] * sum_e alpha[e] * X[row[e],:]   (block per hyperedge)
__global__ void k_prop1(const int* __restrict__ cstart, const int* __restrict__ ccsr,
                        const int* __restrict__ row, const float* __restrict__ alpha,
                        const float* __restrict__ Binv, const float* __restrict__ X,
                        float* __restrict__ ef) {
    int m = blockIdx.x;
    int s = cstart[m], e = cstart[m + 1];
    __shared__ int   shr[256];
    __shared__ float shc[256];
    int tid = threadIdx.x;
    float ax = 0.f, ay = 0.f;
    const float* base = X + 2 * tid;
    for (int b0 = s; b0 < e; b0 += 256) {
        int cnt = min(256, e - b0);
        __syncthreads();
        if (tid < cnt) {
            int ed = ccsr[b0 + tid];
            shr[tid] = row[ed];
            shc[tid] = alpha[ed];
        }
        __syncthreads();
        for (int j = 0; j < cnt; j++) {
            float2 v = *(const float2*)(base + (size_t)shr[j] * FF);
            float cf = shc[j];
            ax += cf * v.x;
            ay += cf * v.y;
        }
    }
    float bi = Binv[m];
    float2 o;
    o.x = ax * bi; o.y = ay * bi;
    *(float2*)(ef + (size_t)m * FF + 2 * tid) = o;
}

__global__ void k_prop2(const int* __restrict__ rstart, const int* __restrict__ rcsr,
                        const int* __restrict__ col, const float* __restrict__ alpha,
                        const float* __restrict__ Dinv, const float* __restrict__ ef,
                        const float* __restrict__ bias, float* __restrict__ out) {
    int n = blockIdx.x;
    int s = rstart[n], e = rstart[n + 1];
    int tid = threadIdx.x;
    float a0 = 0.f, a1 = 0.f, a2 = 0.f, a3 = 0.f;
    for (int i = s; i < e; i++) {
        int ed = rcsr[i];
        float cf = alpha[ed];
        float4 v = *(const float4*)(ef + (size_t)col[ed] * FF + 4 * tid);
        a0 += cf * v.x; a1 += cf * v.y; a2 += cf * v.z; a3 += cf * v.w;
    }
    float d = Dinv[n];
    float4 b = *(const float4*)(bias + 4 * tid);
    float4 o;
    o.x = a0 * d + b.x; o.y = a1 * d + b.y; o.z = a2 * d + b.z; o.w = a3 * d + b.w;
    *(float4*)(out + (size_t)n * FF + 4 * tid) = o;
}

__global__ void k_colstat(const float* __restrict__ X, float* __restrict__ p1,
                          float* __restrict__ p2, int rows) {
    int b = blockIdx.x;
    int c = threadIdx.x;
    int r0 = b * CSTAT_ROWS, r1 = min(r0 + CSTAT_ROWS, rows);
    float s1 = 0.f, s2 = 0.f;
    for (int r = r0; r < r1; r++) {
        float v = X[(size_t)r * FF + c];
        s1 += v;
        s2 += v * v;
    }
    p1[b * FF + c] = s1;
    p2[b * FF + c] = s2;
}

__global__ void k_statfin(const float* __restrict__ p1, const float* __restrict__ p2,
                          int nblk, const float* __restrict__ w,
                          const float* __restrict__ ms, float* __restrict__ shift,
                          float* __restrict__ scale, float rows_inv) {
    int c = threadIdx.x;
    float s1 = 0.f, s2 = 0.f;
    for (int i = 0; i < nblk; i++) {
        s1 += p1[i * FF + c];
        s2 += p2[i * FF + c];
    }
    float mu = s1 * rows_inv;
    float ex2 = s2 * rows_inv;
    float m = ms[c];
    float sh = m * mu;
    float var = ex2 - sh * (2.f * mu - sh);
    shift[c] = sh;
    scale[c] = w[c] / sqrtf(var + 1e-5f);
}

// graph_norm apply + leaky_relu: writes fp32 result AND bf16 hi/lo split
__global__ void k_normsplit(const float* __restrict__ X, const float* __restrict__ shift,
                            const float* __restrict__ scale, const float* __restrict__ beta,
                            float* __restrict__ Yf, __nv_bfloat16* __restrict__ hi,
                            __nv_bfloat16* __restrict__ lo, int total4) {
    int i = blockIdx.x * blockDim.x + threadIdx.x;
    if (i >= total4) return;
    int c = (i & 127) * 4;
    float4 v = ((const float4*)X)[i];
    float4 sh = *(const float4*)(shift + c);
    float4 sc = *(const float4*)(scale + c);
    float4 be = *(const float4*)(beta + c);
    float y0 = (v.x - sh.x) * sc.x + be.x;
    float y1 = (v.y - sh.y) * sc.y + be.y;
    float y2 = (v.z - sh.z) * sc.z + be.z;
    float y3 = (v.w - sh.w) * sc.w + be.w;
    y0 = (y0 > 0.f) ? y0 : NEG_SLOPE * y0;
    y1 = (y1 > 0.f) ? y1 : NEG_SLOPE * y1;
    y2 = (y2 > 0.f) ? y2 : NEG_SLOPE * y2;
    y3 = (y3 > 0.f) ? y3 : NEG_SLOPE * y3;
    ((float4*)Yf)[i] = make_float4(y0, y1, y2, y3);
    __nv_bfloat16 h0 = __float2bfloat16(y0), h1 = __float2bfloat16(y1);
    __nv_bfloat16 h2 = __float2bfloat16(y2), h3 = __float2bfloat16(y3);
    __nv_bfloat16 l0 = __float2bfloat16(y0 - __bfloat162float(h0));
    __nv_bfloat16 l1 = __float2bfloat16(y1 - __bfloat162float(h1));
    __nv_bfloat16 l2 = __float2bfloat16(y2 - __bfloat162float(h2));
    __nv_bfloat16 l3 = __float2bfloat16(y3 - __bfloat162float(h3));
    ((__nv_bfloat162*)hi)[i * 2]     = __nv_bfloat162(h0, h1);
    ((__nv_bfloat162*)hi)[i * 2 + 1] = __nv_bfloat162(h2, h3);
    ((__nv_bfloat162*)lo)[i * 2]     = __nv_bfloat162(l0, l1);
    ((__nv_bfloat162*)lo)[i * 2 + 1] = __nv_bfloat162(l2, l3);
}

__global__ void k_cls(const float* __restrict__ A, const float* __restrict__ W,
                      const float* __restrict__ b, float* __restrict__ out, int rows) {
    int gw = (blockIdx.x * blockDim.x + threadIdx.x) >> 5;
    int lane = threadIdx.x & 31;
    if (gw >= rows) return;
    const float* ar = A + (size_t)gw * HIDD;
    float s0 = 0.f, s1 = 0.f;
    for (int h = lane; h < HIDD; h += 32) {
        float v = ar[h];
        s0 += v * W[h * 2];
        s1 += v * W[h * 2 + 1];
    }
    for (int o = 16; o; o >>= 1) {
        s0 += __shfl_down_sync(0xffffffffu, s0, o);
        s1 += __shfl_down_sync(0xffffffffu, s1, o);
    }
    if (!lane) {
        out[gw * 2] = s0 + b[0];
        out[gw * 2 + 1] = s1 + b[1];
    }
}

// ---------------- host launch ----------------
extern "C" void kernel_launch(void* const* d_in, const int* in_sizes, int n_in,
                              void* d_out, int out_size) {
    const float* x    = (const float*)d_in[0];
    const int*   ei   = (const int*)d_in[1];
    const float* ea   = (const float*)d_in[2];
    const float* W1   = (const float*)d_in[3];
    const float* att1 = (const float*)d_in[4];
    const float* b1   = (const float*)d_in[5];
    const float* W2   = (const float*)d_in[6];
    const float* att2 = (const float*)d_in[7];
    const float* b2   = (const float*)d_in[8];
    const float* gn1w = (const float*)d_in[9];
    const float* gn1b = (const float*)d_in[10];
    const float* gn1ms= (const float*)d_in[11];
    const float* gn2w = (const float*)d_in[12];
    const float* gn2b = (const float*)d_in[13];
    const float* gn2ms= (const float*)d_in[14];
    const float* fc1W = (const float*)d_in[15];
    const float* fc1b = (const float*)d_in[16];
    const float* fc2W = (const float*)d_in[17];
    const float* fc2b = (const float*)d_in[18];
    const float* clsW = (const float*)d_in[19];
    const float* clsb = (const float*)d_in[20];
    float* outp = (float*)d_out;

    const int* row = ei;
    const int* col = ei + EE;

    float *xl, *el, *ef, *h, *fc, *xn, *en, *wa, *wb, *alpha, *Dinv, *Binv;
    float *p1, *p2, *shift, *scale;
    int *degn, *dege, *rstart, *cstart, *rcur, *ccur, *rcsr, *ccsr;
    __nv_bfloat16 *Ahi, *Alo, *eahi, *ealo, *W1thi, *W1tlo, *W2thi, *W2tlo;
    __nv_bfloat16 *f1thi, *f1tlo, *f2thi, *f2tlo;
    cudaGetSymbolAddress((void**)&xl, g_xl);
    cudaGetSymbolAddress((void**)&el, g_el);
    cudaGetSymbolAddress((void**)&ef, g_ef);
    cudaGetSymbolAddress((void**)&h, g_h);
    cudaGetSymbolAddress((void**)&fc, g_fc);
    cudaGetSymbolAddress((void**)&xn, g_xn);
    cudaGetSymbolAddress((void**)&en, g_en);
    cudaGetSymbolAddress((void**)&wa, g_wa);
    cudaGetSymbolAddress((void**)&wb, g_wb);
    cudaGetSymbolAddress((void**)&alpha, g_alpha);
    cudaGetSymbolAddress((void**)&Dinv, g_Dinv);
    cudaGetSymbolAddress((void**)&Binv, g_Binv);
    cudaGetSymbolAddress((void**)&p1, g_p1);
    cudaGetSymbolAddress((void**)&p2, g_p2);
    cudaGetSymbolAddress((void**)&shift, g_shift);
    cudaGetSymbolAddress((void**)&scale, g_scale);
    cudaGetSymbolAddress((void**)&degn, g_degn);
    cudaGetSymbolAddress((void**)&dege, g_dege);
    cudaGetSymbolAddress((void**)&rstart, g_rstart);
    cudaGetSymbolAddress((void**)&cstart, g_cstart);
    cudaGetSymbolAddress((void**)&rcur, g_rcur);
    cudaGetSymbolAddress((void**)&ccur, g_ccur);
    cudaGetSymbolAddress((void**)&rcsr, g_rcsr);
    cudaGetSymbolAddress((void**)&ccsr, g_ccsr);
    cudaGetSymbolAddress((void**)&Ahi, g_Ahi);
    cudaGetSymbolAddress((void**)&Alo, g_Alo);
    cudaGetSymbolAddress((void**)&eahi, g_eahi);
    cudaGetSymbolAddress((void**)&ealo, g_ealo);
    cudaGetSymbolAddress((void**)&W1thi, g_W1thi);
    cudaGetSymbolAddress((void**)&W1tlo, g_W1tlo);
    cudaGetSymbolAddress((void**)&W2thi, g_W2thi);
    cudaGetSymbolAddress((void**)&W2tlo, g_W2tlo);
    cudaGetSymbolAddress((void**)&f1thi, g_f1thi);
    cudaGetSymbolAddress((void**)&f1tlo, g_f1tlo);
    cudaGetSymbolAddress((void**)&f2thi, g_f2thi);
    cudaGetSymbolAddress((void**)&f2tlo, g_f2tlo);

    // ---- graph structure ----
    k_zero_i<<<(NN + 255) / 256, 256>>>(degn, NN);
    k_zero_i<<<(MM + 255) / 256, 256>>>(dege, MM);
    k_hist<<<(EE + 255) / 256, 256>>>(row, col, degn, dege, EE);
    k_exscan<<<1, 1024>>>(dege, cstart, MM);
    k_exscan<<<1, 1024>>>(degn, rstart, NN);
    k_copy_i<<<(MM + 255) / 256, 256>>>(cstart, ccur, MM);
    k_copy_i<<<(NN + 255) / 256, 256>>>(rstart, rcur, NN);
    k_scatter<<<(EE + 255) / 256, 256>>>(row, col, rcur, ccur, rcsr, ccsr, EE);
    k_inv<<<(NN + 255) / 256, 256>>>(degn, Dinv, NN);
    k_inv<<<(MM + 255) / 256, 256>>>(dege, Binv, MM);

    // ---- weight conversions ----
    k_wsplit<<<(FF * FF + 255) / 256, 256>>>(W1, W1thi, W1tlo, FF, FF);
    k_wsplit<<<(FF * FF + 255) / 256, 256>>>(W2, W2thi, W2tlo, FF, FF);
    k_wsplit<<<(FF * HIDD + 255) / 256, 256>>>(fc1W, f1thi, f1tlo, FF, HIDD);
    k_wsplit<<<(FF * HIDD + 255) / 256, 256>>>(fc2W, f2thi, f2tlo, FF, HIDD);

    const float rows_inv = 1.0f / (float)NN;
    dim3 gM(FF / 128, MM / 128);            // (4, 16)   ef GEMM
    dim3 gFC(HIDD / 128, (NN + 127) / 128); // (2, 157)  fc GEMM

    // ==== conv1 ====
    // attention projections: w1a = W1 @ att1[:F], w1b = W1 @ att1[F:]
    k_rowdot<<<(FF * 32 + 255) / 256, 256>>>(W1, att1, wa, FF);
    k_rowdot<<<(FF * 32 + 255) / 256, 256>>>(W1, att1 + FF, wb, FF);
    k_rowdot<<<(NN * 32 + 255) / 256, 256>>>(x, wa, xn, NN);
    k_rowdot<<<(MM * 32 + 255) / 256, 256>>>(ea, wb, en, MM);
    k_attn<<<MM, 128>>>(cstart, ccsr, row, xn, en, alpha);
    // propagate in input space, then tiny GEMM: ef = (segsum alpha*Binv*x[row]) @ W1
    k_prop1<<<MM, 256>>>(cstart, ccsr, row, alpha, Binv, x, ef);
    k_split<<<(MM * (FF / 4) + 255) / 256, 256>>>(ef, eahi, ealo, MM * (FF / 4));
    k_wgemm<0><<<gM, 256>>>(eahi, ealo, W1thi, W1tlo, el, MM, FF, FF, nullptr);
    k_prop2<<<NN, 128>>>(rstart, rcsr, col, alpha, Dinv, el, b1, xl);
    // graph_norm 1 + leaky_relu -> h1 fp32 + bf16 split
    k_colstat<<<CSTAT_BLKS, FF>>>(xl, p1, p2, NN);
    k_statfin<<<1, FF>>>(p1, p2, CSTAT_BLKS, gn1w, gn1ms, shift, scale, rows_inv);
    k_normsplit<<<(NN * (FF / 4) + 255) / 256, 256>>>(xl, shift, scale, gn1b, h, Ahi, Alo, NN * (FF / 4));
    // fc1: out = lrelu(h1 @ fc1_W + b)
    k_wgemm<1><<<gFC, 256>>>(Ahi, Alo, f1thi, f1tlo, fc, NN, HIDD, FF, fc1b);

    // ==== conv2 (input = h1) ====
    k_rowdot<<<(FF * 32 + 255) / 256, 256>>>(W2, att2, wa, FF);
    k_rowdot<<<(FF * 32 + 255) / 256, 256>>>(W2, att2 + FF, wb, FF);
    k_rowdot<<<(NN * 32 + 255) / 256, 256>>>(h, wa, xn, NN);
    k_rowdot<<<(MM * 32 + 255) / 256, 256>>>(ea, wb, en, MM);
    k_attn<<<MM, 128>>>(cstart, ccsr, row, xn, en, alpha);
    k_prop1<<<MM, 256>>>(cstart, ccsr, row, alpha, Binv, h, ef);
    k_split<<<(MM * (FF / 4) + 255) / 256, 256>>>(ef, eahi, ealo, MM * (FF / 4));
    k_wgemm<0><<<gM, 256>>>(eahi, ealo, W2thi, W2tlo, el, MM, FF, FF, nullptr);
    k_prop2<<<NN, 128>>>(rstart, rcsr, col, alpha, Dinv, el, b2, xl);
    // graph_norm 2 + leaky_relu -> h2 fp32 + bf16 split
    k_colstat<<<CSTAT_BLKS, FF>>>(xl, p1, p2, NN);
    k_statfin<<<1, FF>>>(p1, p2, CSTAT_BLKS, gn2w, gn2ms, shift, scale, rows_inv);
    k_normsplit<<<(NN * (FF / 4) + 255) / 256, 256>>>(xl, shift, scale, gn2b, h, Ahi, Alo, NN * (FF / 4));
    // fc2: out += lrelu(h2 @ fc2_W + b)
    k_wgemm<2><<<gFC, 256>>>(Ahi, Alo, f2thi, f2tlo, fc, NN, HIDD, FF, fc2b);

    // ---- classifier ----
    k_cls<<<(NN * 32 + 255) / 256, 256>>>(fc, clsW, clsb, outp, NN);
}

// round 6
// speedup vs baseline: 2.0005x; 1.0904x over previous
#include <cuda_runtime.h>
#include <cuda_bf16.h>
#include <mma.h>
#include <cstdint>
#include <math.h>

using namespace nvcuda;

#define NN 20000
#define MM 2048
#define EE 320000
#define FF 512
#define HIDD 256
#define CSTAT_ROWS 128
#define CSTAT_BLKS ((NN + CSTAT_ROWS - 1) / CSTAT_ROWS)   // 157

#define NEG_SLOPE 0.01f
#define ATT_SLOPE 0.2f

// ---------------- scratch ----------------
__device__ float g_xl[NN * FF];       // conv output (node space, pre-norm)
__device__ float g_el[MM * FF];       // edge_feat after GEMM
__device__ float g_h[NN * FF];        // normalized node features (fp32)
__device__ float g_fc[NN * HIDD];
__device__ float g_xn[NN];
__device__ float g_en[MM];
__device__ float g_wa[FF];
__device__ float g_wb[FF];
__device__ float g_alpha[EE];
__device__ float g_Dinv[NN];
__device__ float g_Binv[MM];
__device__ int   g_degn[NN];
__device__ int   g_dege[MM];
__device__ int   g_rstart[NN + 1];
__device__ int   g_cstart[MM + 1];
__device__ int   g_rcur[NN];
__device__ int   g_ccur[MM];
__device__ int   g_rcsr[EE];
__device__ int   g_ccsr[EE];
__device__ float g_p1[CSTAT_BLKS * FF];
__device__ float g_p2[CSTAT_BLKS * FF];
__device__ float g_shift[FF];
__device__ float g_scale[FF];
// bf16 split operands
__device__ __nv_bfloat16 g_Ahi[NN * FF];
__device__ __nv_bfloat16 g_Alo[NN * FF];
__device__ __nv_bfloat16 g_eahi[MM * FF];   // ef_raw split (written by attnprop)
__device__ __nv_bfloat16 g_ealo[MM * FF];
__device__ __nv_bfloat16 g_W1thi[FF * FF];
__device__ __nv_bfloat16 g_W1tlo[FF * FF];
__device__ __nv_bfloat16 g_W2thi[FF * FF];
__device__ __nv_bfloat16 g_W2tlo[FF * FF];
__device__ __nv_bfloat16 g_f1thi[HIDD * FF];
__device__ __nv_bfloat16 g_f1tlo[HIDD * FF];
__device__ __nv_bfloat16 g_f2thi[HIDD * FF];
__device__ __nv_bfloat16 g_f2tlo[HIDD * FF];

// ---------------- cp.async helpers ----------------
__device__ __forceinline__ uint32_t smem_u32(const void* p) {
    uint32_t a;
    asm("{ .reg .u64 t; cvta.to.shared.u64 t, %1; cvt.u32.u64 %0, t; }" : "=r"(a) : "l"(p));
    return a;
}
__device__ __forceinline__ void cp16(uint32_t dst, const void* src) {
    asm volatile("cp.async.ca.shared.global [%0], [%1], 16;" :: "r"(dst), "l"(src));
}
#define CP_COMMIT() asm volatile("cp.async.commit_group;" ::: "memory")
#define CP_WAIT1()  asm volatile("cp.async.wait_group 1;" ::: "memory")
#define CP_WAIT0()  asm volatile("cp.async.wait_group 0;" ::: "memory")

// dynamic smem layout for k_wgemm (bytes)
#define APAD 72                 // bf16 elems per padded row (144 B)
#define TILE_B (128 * APAD * 2) // 18432
#define SM_A0 0
#define SM_B0 18432
#define SM_A1 36864
#define SM_B1 55296
#define SM_STG 73728            // 8 warps * 256 floats = 8192
#define GEMM_SMEM 81920

// ---------------- cp.async double-buffered wmma split-bf16 GEMM ----------------
// C[Mr,Nc] = (Ahi+Alo)[Mr,K] @ B[K,Nc], B stored transposed [Nc,K].
// 3 K-segments: hi*hi + lo*hi + hi*lo into the same fp32 accumulators.
// MODE 0: store; MODE 1: store lrelu(AB+bias); MODE 2: C += lrelu(AB+bias)
template <int MODE>
__global__ void __launch_bounds__(256) k_wgemm(
    const __nv_bfloat16* __restrict__ Ahi, const __nv_bfloat16* __restrict__ Alo,
    const __nv_bfloat16* __restrict__ Bthi, const __nv_bfloat16* __restrict__ Btlo,
    float* __restrict__ C, int Mr, int Nc, int Kd, const float* __restrict__ bias) {
    extern __shared__ __align__(16) char dsm[];
    const uint32_t sb = smem_u32(dsm);

    const int tid = threadIdx.x;
    const int wid = tid >> 5;
    const int lane = tid & 31;
    const int wm = wid >> 2;
    const int wn = wid & 3;
    const int bm = blockIdx.y * 128;
    const int bn = blockIdx.x * 128;

    const int CPS = Kd >> 6;      // 64-col chunks per segment
    const int NCH = 3 * CPS;

    // loader indices: 128 rows x 128 B per tile, 2 threads/row, 4 x 16 B each
    const int lr = tid >> 1;
    const int lc = (tid & 1) * 4;
    const int gaRow = min(bm + lr, Mr - 1);
    const int gbRow = bn + lr;

    wmma::fragment<wmma::accumulator, 16, 16, 16, float> acc[4][2];
#pragma unroll
    for (int i = 0; i < 4; i++)
#pragma unroll
        for (int j = 0; j < 2; j++) wmma::fill_fragment(acc[i][j], 0.0f);

    // issue cp.async loads for chunk c into buffer c&1
    auto issue = [&](int c) {
        int seg = c / CPS;
        int j = c - seg * CPS;
        const __nv_bfloat16* A = (seg == 1) ? Alo : Ahi;
        const __nv_bfloat16* B = (seg == 2) ? Btlo : Bthi;
        int koff = j << 6;
        int buf = c & 1;
        uint32_t abase = sb + (buf ? SM_A1 : SM_A0) + lr * 144;
        uint32_t bbase = sb + (buf ? SM_B1 : SM_B0) + lr * 144;
        const char* ap = (const char*)(A + (size_t)gaRow * Kd + koff);
        const char* bp = (const char*)(B + (size_t)gbRow * Kd + koff);
#pragma unroll
        for (int u = 0; u < 4; u++) {
            cp16(abase + (lc + u) * 16, ap + (lc + u) * 16);
            cp16(bbase + (lc + u) * 16, bp + (lc + u) * 16);
        }
        CP_COMMIT();
    };

    issue(0);
    for (int c = 0; c < NCH; c++) {
        if (c + 1 < NCH) { issue(c + 1); CP_WAIT1(); }
        else             { CP_WAIT0(); }
        __syncthreads();
        const int buf = c & 1;
        const __nv_bfloat16* As = (const __nv_bfloat16*)(dsm + (buf ? SM_A1 : SM_A0));
        const __nv_bfloat16* Bs = (const __nv_bfloat16*)(dsm + (buf ? SM_B1 : SM_B0));
#pragma unroll
        for (int kt = 0; kt < 4; kt++) {
            wmma::fragment<wmma::matrix_a, 16, 16, 16, __nv_bfloat16, wmma::row_major> af[4];
            wmma::fragment<wmma::matrix_b, 16, 16, 16, __nv_bfloat16, wmma::col_major> bf[2];
#pragma unroll
            for (int n = 0; n < 2; n++)
                wmma::load_matrix_sync(bf[n], Bs + (wn * 32 + n * 16) * APAD + kt * 16, APAD);
#pragma unroll
            for (int m = 0; m < 4; m++)
                wmma::load_matrix_sync(af[m], As + (wm * 64 + m * 16) * APAD + kt * 16, APAD);
#pragma unroll
            for (int m = 0; m < 4; m++)
#pragma unroll
                for (int n = 0; n < 2; n++)
                    wmma::mma_sync(acc[m][n], af[m], bf[n], acc[m][n]);
        }
        __syncthreads();   // protect buffer before reuse
    }

    float* stg = (float*)(dsm + SM_STG) + wid * 256;
    const int srow = lane >> 1;
    const int scol = (lane & 1) * 8;
#pragma unroll
    for (int m = 0; m < 4; m++) {
#pragma unroll
        for (int n = 0; n < 2; n++) {
            wmma::store_matrix_sync(stg, acc[m][n], 16, wmma::mem_row_major);
            __syncwarp();
            int grow = bm + wm * 64 + m * 16 + srow;
            int gcol = bn + wn * 32 + n * 16 + scol;
            if (grow < Mr) {
                float* crow = C + (size_t)grow * Nc + gcol;
                const float* sp = stg + srow * 16 + scol;
#pragma unroll
                for (int q = 0; q < 2; q++) {
                    float4 v = *(const float4*)(sp + q * 4);
                    if (MODE >= 1) {
                        float4 bb = *(const float4*)(bias + gcol + q * 4);
                        v.x += bb.x; v.y += bb.y; v.z += bb.z; v.w += bb.w;
                        v.x = (v.x > 0.f) ? v.x : NEG_SLOPE * v.x;
                        v.y = (v.y > 0.f) ? v.y : NEG_SLOPE * v.y;
                        v.z = (v.z > 0.f) ? v.z : NEG_SLOPE * v.z;
                        v.w = (v.w > 0.f) ? v.w : NEG_SLOPE * v.w;
                    }
                    if (MODE == 2) {
                        float4 o = *(const float4*)(crow + q * 4);
                        v.x += o.x; v.y += o.y; v.z += o.z; v.w += o.w;
                    }
                    *(float4*)(crow + q * 4) = v;
                }
            }
            __syncwarp();
        }
    }
}

// ---------------- weight transpose+split ----------------
__global__ void k_wsplit(const float* __restrict__ W, __nv_bfloat16* __restrict__ thi,
                         __nv_bfloat16* __restrict__ tlo, int K, int N) {
    int i = blockIdx.x * blockDim.x + threadIdx.x;
    if (i >= K * N) return;
    int n = i / K, k = i - n * K;
    float v = W[(size_t)k * N + n];
    __nv_bfloat16 h = __float2bfloat16(v);
    thi[i] = h;
    tlo[i] = __float2bfloat16(v - __bfloat162float(h));
}

// ---------------- structure kernels ----------------
__global__ void k_zero2(int* a, int na, int* b, int nb) {
    int i = blockIdx.x * blockDim.x + threadIdx.x;
    if (i < na) a[i] = 0;
    else if (i < na + nb) b[i - na] = 0;
}

__global__ void k_hist(const int* __restrict__ row, const int* __restrict__ col,
                       int* degn, int* dege, int E) {
    int i = blockIdx.x * blockDim.x + threadIdx.x;
    if (i < E) {
        atomicAdd(&degn[row[i]], 1);
        atomicAdd(&dege[col[i]], 1);
    }
}

// one-block exclusive scan; also writes cur[i] = start[i]
__global__ void k_exscan(const int* __restrict__ cnt, int* __restrict__ start,
                         int* __restrict__ cur, int n) {
    __shared__ int sh[1024];
    int tid = threadIdx.x;
    int per = (n + 1023) >> 10;
    int lo = tid * per;
    int hi = min(lo + per, n);
    int s = 0;
    for (int i = lo; i < hi; i++) s += cnt[i];
    sh[tid] = s;
    __syncthreads();
    for (int off = 1; off < 1024; off <<= 1) {
        int add = (tid >= off) ? sh[tid - off] : 0;
        __syncthreads();
        sh[tid] += add;
        __syncthreads();
    }
    int run = (tid == 0) ? 0 : sh[tid - 1];
    for (int i = lo; i < hi; i++) { start[i] = run; cur[i] = run; run += cnt[i]; }
    if (tid == 0) start[n] = sh[1023];
}

__global__ void k_scatter(const int* __restrict__ row, const int* __restrict__ col,
                          int* rcur, int* ccur, int* __restrict__ rcsr,
                          int* __restrict__ ccsr, int E) {
    int i = blockIdx.x * blockDim.x + threadIdx.x;
    if (i < E) {
        int pr = atomicAdd(&rcur[row[i]], 1);
        rcsr[pr] = i;
        int pc = atomicAdd(&ccur[col[i]], 1);
        ccsr[pc] = i;
    }
}

__global__ void k_inv2(const int* __restrict__ da, float* __restrict__ ia, int na,
                       const int* __restrict__ db, float* __restrict__ ib, int nb) {
    int i = blockIdx.x * blockDim.x + threadIdx.x;
    if (i < na) {
        int d = da[i];
        ia[i] = (d > 0) ? (1.0f / (float)d) : 0.0f;
    } else if (i < na + nb) {
        int d = db[i - na];
        ib[i - na] = (d > 0) ? (1.0f / (float)d) : 0.0f;
    }
}

// ---------------- row dots ----------------
__global__ void k_rowdot(const float* __restrict__ X, const float* __restrict__ v,
                         float* __restrict__ out, int rows) {
    int gw = (blockIdx.x * blockDim.x + threadIdx.x) >> 5;
    int lane = threadIdx.x & 31;
    if (gw >= rows) return;
    const float4* xr = (const float4*)(X + (size_t)gw * FF);
    const float4* vv = (const float4*)v;
    float s = 0.f;
#pragma unroll
    for (int j = 0; j < 4; j++) {
        float4 a = xr[lane + 32 * j];
        float4 b = vv[lane + 32 * j];
        s += a.x * b.x + a.y * b.y + a.z * b.z + a.w * b.w;
    }
    for (int o = 16; o; o >>= 1) s += __shfl_down_sync(0xffffffffu, s, o);
    if (!lane) out[gw] = s;
}

// two dots per row in one read pass
__global__ void k_rowdot2(const float* __restrict__ X, const float* __restrict__ v1,
                          const float* __restrict__ v2, float* __restrict__ o1,
                          float* __restrict__ o2, int rows) {
    int gw = (blockIdx.x * blockDim.x + threadIdx.x) >> 5;
    int lane = threadIdx.x & 31;
    if (gw >= rows) return;
    const float4* xr = (const float4*)(X + (size_t)gw * FF);
    const float4* va = (const float4*)v1;
    const float4* vb = (const float4*)v2;
    float s1 = 0.f, s2 = 0.f;
#pragma unroll
    for (int j = 0; j < 4; j++) {
        float4 a = xr[lane + 32 * j];
        float4 b = va[lane + 32 * j];
        float4 c = vb[lane + 32 * j];
        s1 += a.x * b.x + a.y * b.y + a.z * b.z + a.w * b.w;
        s2 += a.x * c.x + a.y * c.y + a.z * c.z + a.w * c.w;
    }
    for (int o = 16; o; o >>= 1) {
        s1 += __shfl_down_sync(0xffffffffu, s1, o);
        s2 += __shfl_down_sync(0xffffffffu, s2, o);
    }
    if (!lane) { o1[gw] = s1; o2[gw] = s2; }
}

// ---------------- fused attention softmax + propagate-1 (+bf16 split out) ----------------
// block per hyperedge m: softmax over its edges, write normalized alpha,
// gather ef_raw[m,:] = Binv[m]*sum alpha*X[row], emit bf16 hi/lo.
__global__ void __launch_bounds__(256) k_attnprop(
    const int* __restrict__ cstart, const int* __restrict__ ccsr,
    const int* __restrict__ row, const float* __restrict__ xn,
    const float* __restrict__ en, const float* __restrict__ Binv,
    const float* __restrict__ X, float* __restrict__ alpha,
    __nv_bfloat16* __restrict__ efhi, __nv_bfloat16* __restrict__ eflo) {
    int m = blockIdx.x;
    int s = cstart[m], e = cstart[m + 1];
    int tid = threadIdx.x;
    __shared__ float red[256];
    __shared__ int   shr[256];
    __shared__ float shc[256];

    float enm = en[m];
    // pass 1: logits -> alpha (raw), block max
    float mx = -3.0e38f;
    for (int i = s + tid; i < e; i += 256) {
        int ed = ccsr[i];
        float p = xn[row[ed]] + enm;
        p = (p > 0.f) ? p : ATT_SLOPE * p;
        alpha[ed] = p;
        mx = fmaxf(mx, p);
    }
    red[tid] = mx;
    __syncthreads();
    for (int o = 128; o; o >>= 1) {
        if (tid < o) red[tid] = fmaxf(red[tid], red[tid + o]);
        __syncthreads();
    }
    float amax = red[0];
    if (!(amax > -1e37f)) amax = 0.f;
    __syncthreads();
    // pass 2: exp, block sum
    float sm = 0.f;
    for (int i = s + tid; i < e; i += 256) {
        int ed = ccsr[i];
        float ex = expf(alpha[ed] - amax);
        alpha[ed] = ex;
        sm += ex;
    }
    red[tid] = sm;
    __syncthreads();
    for (int o = 128; o; o >>= 1) {
        if (tid < o) red[tid] += red[tid + o];
        __syncthreads();
    }
    float inv = 1.f / fmaxf(red[0], 1e-16f);
    float bi = Binv[m];
    // pass 3 fused with gather: finalize alpha, stage, accumulate
    float ax = 0.f, ay = 0.f;
    const float* base = X + 2 * tid;
    for (int b0 = s; b0 < e; b0 += 256) {
        int cnt = min(256, e - b0);
        __syncthreads();
        if (tid < cnt) {
            int ed = ccsr[b0 + tid];
            float a = alpha[ed] * inv;
            alpha[ed] = a;           // final normalized alpha for prop2
            shr[tid] = row[ed];
            shc[tid] = a * bi;
        }
        __syncthreads();
        for (int j = 0; j < cnt; j++) {
            float2 v = *(const float2*)(base + (size_t)shr[j] * FF);
            float cf = shc[j];
            ax += cf * v.x;
            ay += cf * v.y;
        }
    }
    __nv_bfloat16 hx = __float2bfloat16(ax), hy = __float2bfloat16(ay);
    __nv_bfloat16 lx = __float2bfloat16(ax - __bfloat162float(hx));
    __nv_bfloat16 ly = __float2bfloat16(ay - __bfloat162float(hy));
    ((__nv_bfloat162*)(efhi + (size_t)m * FF))[tid] = __nv_bfloat162(hx, hy);
    ((__nv_bfloat162*)(eflo + (size_t)m * FF))[tid] = __nv_bfloat162(lx, ly);
}

// ---------------- propagate-2 ----------------
__global__ void k_prop2(const int* __restrict__ rstart, const int* __restrict__ rcsr,
                        const int* __restrict__ col, const float* __restrict__ alpha,
                        const float* __restrict__ Dinv, const float* __restrict__ ef,
                        const float* __restrict__ bias, float* __restrict__ out) {
    int n = blockIdx.x;
    int s = rstart[n], e = rstart[n + 1];
    int tid = threadIdx.x;
    float a0 = 0.f, a1 = 0.f, a2 = 0.f, a3 = 0.f;
    for (int i = s; i < e; i++) {
        int ed = rcsr[i];
        float cf = alpha[ed];
        float4 v = *(const float4*)(ef + (size_t)col[ed] * FF + 4 * tid);
        a0 += cf * v.x; a1 += cf * v.y; a2 += cf * v.z; a3 += cf * v.w;
    }
    float d = Dinv[n];
    float4 b = *(const float4*)(bias + 4 * tid);
    float4 o;
    o.x = a0 * d + b.x; o.y = a1 * d + b.y; o.z = a2 * d + b.z; o.w = a3 * d + b.w;
    *(float4*)(out + (size_t)n * FF + 4 * tid) = o;
}

// ---------------- graph norm ----------------
__global__ void k_colstat(const float* __restrict__ X, float* __restrict__ p1,
                          float* __restrict__ p2, int rows) {
    int b = blockIdx.x;
    int c = threadIdx.x;
    int r0 = b * CSTAT_ROWS, r1 = min(r0 + CSTAT_ROWS, rows);
    float s1 = 0.f, s2 = 0.f;
    for (int r = r0; r < r1; r++) {
        float v = X[(size_t)r * FF + c];
        s1 += v;
        s2 += v * v;
    }
    p1[b * FF + c] = s1;
    p2[b * FF + c] = s2;
}

__global__ void k_statfin(const float* __restrict__ p1, const float* __restrict__ p2,
                          int nblk, const float* __restrict__ w,
                          const float* __restrict__ ms, float* __restrict__ shift,
                          float* __restrict__ scale, float rows_inv) {
    int c = threadIdx.x;
    float s1 = 0.f, s2 = 0.f;
    for (int i = 0; i < nblk; i++) {
        s1 += p1[i * FF + c];
        s2 += p2[i * FF + c];
    }
    float mu = s1 * rows_inv;
    float ex2 = s2 * rows_inv;
    float m = ms[c];
    float sh = m * mu;
    float var = ex2 - sh * (2.f * mu - sh);
    shift[c] = sh;
    scale[c] = w[c] / sqrtf(var + 1e-5f);
}

// graph_norm apply + leaky_relu: writes fp32 result AND bf16 hi/lo split
__global__ void k_normsplit(const float* __restrict__ X, const float* __restrict__ shift,
                            const float* __restrict__ scale, const float* __restrict__ beta,
                            float* __restrict__ Yf, __nv_bfloat16* __restrict__ hi,
                            __nv_bfloat16* __restrict__ lo, int total4) {
    int i = blockIdx.x * blockDim.x + threadIdx.x;
    if (i >= total4) return;
    int c = (i & 127) * 4;
    float4 v = ((const float4*)X)[i];
    float4 sh = *(const float4*)(shift + c);
    float4 sc = *(const float4*)(scale + c);
    float4 be = *(const float4*)(beta + c);
    float y0 = (v.x - sh.x) * sc.x + be.x;
    float y1 = (v.y - sh.y) * sc.y + be.y;
    float y2 = (v.z - sh.z) * sc.z + be.z;
    float y3 = (v.w - sh.w) * sc.w + be.w;
    y0 = (y0 > 0.f) ? y0 : NEG_SLOPE * y0;
    y1 = (y1 > 0.f) ? y1 : NEG_SLOPE * y1;
    y2 = (y2 > 0.f) ? y2 : NEG_SLOPE * y2;
    y3 = (y3 > 0.f) ? y3 : NEG_SLOPE * y3;
    ((float4*)Yf)[i] = make_float4(y0, y1, y2, y3);
    __nv_bfloat16 h0 = __float2bfloat16(y0), h1 = __float2bfloat16(y1);
    __nv_bfloat16 h2 = __float2bfloat16(y2), h3 = __float2bfloat16(y3);
    __nv_bfloat16 l0 = __float2bfloat16(y0 - __bfloat162float(h0));
    __nv_bfloat16 l1 = __float2bfloat16(y1 - __bfloat162float(h1));
    __nv_bfloat16 l2 = __float2bfloat16(y2 - __bfloat162float(h2));
    __nv_bfloat16 l3 = __float2bfloat16(y3 - __bfloat162float(h3));
    ((__nv_bfloat162*)hi)[i * 2]     = __nv_bfloat162(h0, h1);
    ((__nv_bfloat162*)hi)[i * 2 + 1] = __nv_bfloat162(h2, h3);
    ((__nv_bfloat162*)lo)[i * 2]     = __nv_bfloat162(l0, l1);
    ((__nv_bfloat162*)lo)[i * 2 + 1] = __nv_bfloat162(l2, l3);
}

__global__ void k_cls(const float* __restrict__ A, const float* __restrict__ W,
                      const float* __restrict__ b, float* __restrict__ out, int rows) {
    int gw = (blockIdx.x * blockDim.x + threadIdx.x) >> 5;
    int lane = threadIdx.x & 31;
    if (gw >= rows) return;
    const float* ar = A + (size_t)gw * HIDD;
    float s0 = 0.f, s1 = 0.f;
    for (int h = lane; h < HIDD; h += 32) {
        float v = ar[h];
        s0 += v * W[h * 2];
        s1 += v * W[h * 2 + 1];
    }
    for (int o = 16; o; o >>= 1) {
        s0 += __shfl_down_sync(0xffffffffu, s0, o);
        s1 += __shfl_down_sync(0xffffffffu, s1, o);
    }
    if (!lane) {
        out[gw * 2] = s0 + b[0];
        out[gw * 2 + 1] = s1 + b[1];
    }
}

// ---------------- host launch ----------------
extern "C" void kernel_launch(void* const* d_in, const int* in_sizes, int n_in,
                              void* d_out, int out_size) {
    const float* x    = (const float*)d_in[0];
    const int*   ei   = (const int*)d_in[1];
    const float* ea   = (const float*)d_in[2];
    const float* W1   = (const float*)d_in[3];
    const float* att1 = (const float*)d_in[4];
    const float* b1   = (const float*)d_in[5];
    const float* W2   = (const float*)d_in[6];
    const float* att2 = (const float*)d_in[7];
    const float* b2   = (const float*)d_in[8];
    const float* gn1w = (const float*)d_in[9];
    const float* gn1b = (const float*)d_in[10];
    const float* gn1ms= (const float*)d_in[11];
    const float* gn2w = (const float*)d_in[12];
    const float* gn2b = (const float*)d_in[13];
    const float* gn2ms= (const float*)d_in[14];
    const float* fc1W = (const float*)d_in[15];
    const float* fc1b = (const float*)d_in[16];
    const float* fc2W = (const float*)d_in[17];
    const float* fc2b = (const float*)d_in[18];
    const float* clsW = (const float*)d_in[19];
    const float* clsb = (const float*)d_in[20];
    float* outp = (float*)d_out;

    const int* row = ei;
    const int* col = ei + EE;

    float *xl, *el, *h, *fc, *xn, *en, *wa, *wb, *alpha, *Dinv, *Binv;
    float *p1, *p2, *shift, *scale;
    int *degn, *dege, *rstart, *cstart, *rcur, *ccur, *rcsr, *ccsr;
    __nv_bfloat16 *Ahi, *Alo, *eahi, *ealo, *W1thi, *W1tlo, *W2thi, *W2tlo;
    __nv_bfloat16 *f1thi, *f1tlo, *f2thi, *f2tlo;
    cudaGetSymbolAddress((void**)&xl, g_xl);
    cudaGetSymbolAddress((void**)&el, g_el);
    cudaGetSymbolAddress((void**)&h, g_h);
    cudaGetSymbolAddress((void**)&fc, g_fc);
    cudaGetSymbolAddress((void**)&xn, g_xn);
    cudaGetSymbolAddress((void**)&en, g_en);
    cudaGetSymbolAddress((void**)&wa, g_wa);
    cudaGetSymbolAddress((void**)&wb, g_wb);
    cudaGetSymbolAddress((void**)&alpha, g_alpha);
    cudaGetSymbolAddress((void**)&Dinv, g_Dinv);
    cudaGetSymbolAddress((void**)&Binv, g_Binv);
    cudaGetSymbolAddress((void**)&p1, g_p1);
    cudaGetSymbolAddress((void**)&p2, g_p2);
    cudaGetSymbolAddress((void**)&shift, g_shift);
    cudaGetSymbolAddress((void**)&scale, g_scale);
    cudaGetSymbolAddress((void**)&degn, g_degn);
    cudaGetSymbolAddress((void**)&dege, g_dege);
    cudaGetSymbolAddress((void**)&rstart, g_rstart);
    cudaGetSymbolAddress((void**)&cstart, g_cstart);
    cudaGetSymbolAddress((void**)&rcur, g_rcur);
    cudaGetSymbolAddress((void**)&ccur, g_ccur);
    cudaGetSymbolAddress((void**)&rcsr, g_rcsr);
    cudaGetSymbolAddress((void**)&ccsr, g_ccsr);
    cudaGetSymbolAddress((void**)&Ahi, g_Ahi);
    cudaGetSymbolAddress((void**)&Alo, g_Alo);
    cudaGetSymbolAddress((void**)&eahi, g_eahi);
    cudaGetSymbolAddress((void**)&ealo, g_ealo);
    cudaGetSymbolAddress((void**)&W1thi, g_W1thi);
    cudaGetSymbolAddress((void**)&W1tlo, g_W1tlo);
    cudaGetSymbolAddress((void**)&W2thi, g_W2thi);
    cudaGetSymbolAddress((void**)&W2tlo, g_W2tlo);
    cudaGetSymbolAddress((void**)&f1thi, g_f1thi);
    cudaGetSymbolAddress((void**)&f1tlo, g_f1tlo);
    cudaGetSymbolAddress((void**)&f2thi, g_f2thi);
    cudaGetSymbolAddress((void**)&f2tlo, g_f2tlo);

    static bool attr_set = false;
    if (!attr_set) {
        cudaFuncSetAttribute(k_wgemm<0>, cudaFuncAttributeMaxDynamicSharedMemorySize, GEMM_SMEM);
        cudaFuncSetAttribute(k_wgemm<1>, cudaFuncAttributeMaxDynamicSharedMemorySize, GEMM_SMEM);
        cudaFuncSetAttribute(k_wgemm<2>, cudaFuncAttributeMaxDynamicSharedMemorySize, GEMM_SMEM);
        attr_set = true;
    }

    // ---- graph structure ----
    k_zero2<<<(NN + MM + 255) / 256, 256>>>(degn, NN, dege, MM);
    k_hist<<<(EE + 255) / 256, 256>>>(row, col, degn, dege, EE);
    k_exscan<<<1, 1024>>>(dege, cstart, ccur, MM);
    k_exscan<<<1, 1024>>>(degn, rstart, rcur, NN);
    k_scatter<<<(EE + 255) / 256, 256>>>(row, col, rcur, ccur, rcsr, ccsr, EE);
    k_inv2<<<(NN + MM + 255) / 256, 256>>>(degn, Dinv, NN, dege, Binv, MM);

    // ---- weight conversions ----
    k_wsplit<<<(FF * FF + 255) / 256, 256>>>(W1, W1thi, W1tlo, FF, FF);
    k_wsplit<<<(FF * FF + 255) / 256, 256>>>(W2, W2thi, W2tlo, FF, FF);
    k_wsplit<<<(FF * HIDD + 255) / 256, 256>>>(fc1W, f1thi, f1tlo, FF, HIDD);
    k_wsplit<<<(FF * HIDD + 255) / 256, 256>>>(fc2W, f2thi, f2tlo, FF, HIDD);

    const float rows_inv = 1.0f / (float)NN;
    dim3 gM(FF / 128, MM / 128);            // (4, 16)   ef GEMM
    dim3 gFC(HIDD / 128, (NN + 127) / 128); // (2, 157)  fc GEMM

    // ==== conv1 ====
    k_rowdot2<<<(FF * 32 + 255) / 256, 256>>>(W1, att1, att1 + FF, wa, wb, FF);
    k_rowdot<<<(NN * 32 + 255) / 256, 256>>>(x, wa, xn, NN);
    k_rowdot<<<(MM * 32 + 255) / 256, 256>>>(ea, wb, en, MM);
    k_attnprop<<<MM, 256>>>(cstart, ccsr, row, xn, en, Binv, x, alpha, eahi, ealo);
    k_wgemm<0><<<gM, 256, GEMM_SMEM>>>(eahi, ealo, W1thi, W1tlo, el, MM, FF, FF, nullptr);
    k_prop2<<<NN, 128>>>(rstart, rcsr, col, alpha, Dinv, el, b1, xl);
    k_colstat<<<CSTAT_BLKS, FF>>>(xl, p1, p2, NN);
    k_statfin<<<1, FF>>>(p1, p2, CSTAT_BLKS, gn1w, gn1ms, shift, scale, rows_inv);
    k_normsplit<<<(NN * (FF / 4) + 255) / 256, 256>>>(xl, shift, scale, gn1b, h, Ahi, Alo, NN * (FF / 4));
    k_wgemm<1><<<gFC, 256, GEMM_SMEM>>>(Ahi, Alo, f1thi, f1tlo, fc, NN, HIDD, FF, fc1b);

    // ==== conv2 (input = h) ====
    k_rowdot2<<<(FF * 32 + 255) / 256, 256>>>(W2, att2, att2 + FF, wa, wb, FF);
    k_rowdot<<<(NN * 32 + 255) / 256, 256>>>(h, wa, xn, NN);
    k_rowdot<<<(MM * 32 + 255) / 256, 256>>>(ea, wb, en, MM);
    k_attnprop<<<MM, 256>>>(cstart, ccsr, row, xn, en, Binv, h, alpha, eahi, ealo);
    k_wgemm<0><<<gM, 256, GEMM_SMEM>>>(eahi, ealo, W2thi, W2tlo, el, MM, FF, FF, nullptr);
    k_prop2<<<NN, 128>>>(rstart, rcsr, col, alpha, Dinv, el, b2, xl);
    k_colstat<<<CSTAT_BLKS, FF>>>(xl, p1, p2, NN);
    k_statfin<<<1, FF>>>(p1, p2, CSTAT_BLKS, gn2w, gn2ms, shift, scale, rows_inv);
    k_normsplit<<<(NN * (FF / 4) + 255) / 256, 256>>>(xl, shift, scale, gn2b, h, Ahi, Alo, NN * (FF / 4));
    k_wgemm<2><<<gFC, 256, GEMM_SMEM>>>(Ahi, Alo, f2thi, f2tlo, fc, NN, HIDD, FF, fc2b);

    // ---- classifier ----
    k_cls<<<(NN * 32 + 255) / 256, 256>>>(fc, clsW, clsb, outp, NN);
}

// round 7
// speedup vs baseline: 2.0475x; 1.0235x over previous
#include <cuda_runtime.h>
#include <cuda_bf16.h>
#include <mma.h>
#include <cstdint>
#include <math.h>

using namespace nvcuda;

#define NN 20000
#define MM 2048
#define EE 320000
#define FF 512
#define HIDD 256
#define CSTAT_ROWS 128
#define CSTAT_BLKS ((NN + CSTAT_ROWS - 1) / CSTAT_ROWS)   // 157

#define NEG_SLOPE 0.01f
#define ATT_SLOPE 0.2f

// ---------------- scratch ----------------
__device__ float g_xl[NN * FF];
__device__ float g_el[MM * FF];
__device__ float g_h[NN * FF];
__device__ float g_fc[NN * HIDD];
__device__ float g_xn[NN];
__device__ float g_en[MM];
__device__ float g_wa[FF];
__device__ float g_wb[FF];
__device__ float g_alpha[EE];
__device__ float g_Dinv[NN];
__device__ float g_Binv[MM];
__device__ int   g_degn[NN];
__device__ int   g_dege[MM];
__device__ int   g_rstart[NN + 1];
__device__ int   g_cstart[MM + 1];
__device__ int   g_rcur[NN];
__device__ int   g_ccur[MM];
__device__ int   g_rcsr[EE];
__device__ int   g_ccsr[EE];
__device__ int   g_bsumN[32];
__device__ int   g_bsumM[8];
__device__ float g_p1[CSTAT_BLKS * FF];
__device__ float g_p2[CSTAT_BLKS * FF];
__device__ float g_shift[FF];
__device__ float g_scale[FF];
__device__ __nv_bfloat16 g_Ahi[NN * FF];
__device__ __nv_bfloat16 g_Alo[NN * FF];
__device__ __nv_bfloat16 g_eahi[MM * FF];
__device__ __nv_bfloat16 g_ealo[MM * FF];
__device__ __nv_bfloat16 g_W1thi[FF * FF];
__device__ __nv_bfloat16 g_W1tlo[FF * FF];
__device__ __nv_bfloat16 g_W2thi[FF * FF];
__device__ __nv_bfloat16 g_W2tlo[FF * FF];
__device__ __nv_bfloat16 g_f1thi[HIDD * FF];
__device__ __nv_bfloat16 g_f1tlo[HIDD * FF];
__device__ __nv_bfloat16 g_f2thi[HIDD * FF];
__device__ __nv_bfloat16 g_f2tlo[HIDD * FF];

// ---------------- cp.async helpers ----------------
__device__ __forceinline__ uint32_t smem_u32(const void* p) {
    uint32_t a;
    asm("{ .reg .u64 t; cvta.to.shared.u64 t, %1; cvt.u32.u64 %0, t; }" : "=r"(a) : "l"(p));
    return a;
}
__device__ __forceinline__ void cp16(uint32_t dst, const void* src) {
    asm volatile("cp.async.ca.shared.global [%0], [%1], 16;" :: "r"(dst), "l"(src));
}
#define CP_COMMIT() asm volatile("cp.async.commit_group;" ::: "memory")
#define CP_WAIT1()  asm volatile("cp.async.wait_group 1;" ::: "memory")
#define CP_WAIT0()  asm volatile("cp.async.wait_group 0;" ::: "memory")

#define APAD 72
#define SM_A0 0
#define SM_B0 18432
#define SM_A1 36864
#define SM_B1 55296
#define SM_STG 73728
#define GEMM_SMEM 81920

// ---------------- cp.async double-buffered wmma split-bf16 GEMM ----------------
template <int MODE>
__global__ void __launch_bounds__(256) k_wgemm(
    const __nv_bfloat16* __restrict__ Ahi, const __nv_bfloat16* __restrict__ Alo,
    const __nv_bfloat16* __restrict__ Bthi, const __nv_bfloat16* __restrict__ Btlo,
    float* __restrict__ C, int Mr, int Nc, int Kd, const float* __restrict__ bias) {
    extern __shared__ __align__(16) char dsm[];
    const uint32_t sb = smem_u32(dsm);

    const int tid = threadIdx.x;
    const int wid = tid >> 5;
    const int lane = tid & 31;
    const int wm = wid >> 2;
    const int wn = wid & 3;
    const int bm = blockIdx.y * 128;
    const int bn = blockIdx.x * 128;

    const int CPS = Kd >> 6;
    const int NCH = 3 * CPS;

    const int lr = tid >> 1;
    const int lc = (tid & 1) * 4;
    const int gaRow = min(bm + lr, Mr - 1);
    const int gbRow = bn + lr;

    wmma::fragment<wmma::accumulator, 16, 16, 16, float> acc[4][2];
#pragma unroll
    for (int i = 0; i < 4; i++)
#pragma unroll
        for (int j = 0; j < 2; j++) wmma::fill_fragment(acc[i][j], 0.0f);

    auto issue = [&](int c) {
        int seg = c / CPS;
        int j = c - seg * CPS;
        const __nv_bfloat16* A = (seg == 1) ? Alo : Ahi;
        const __nv_bfloat16* B = (seg == 2) ? Btlo : Bthi;
        int koff = j << 6;
        int buf = c & 1;
        uint32_t abase = sb + (buf ? SM_A1 : SM_A0) + lr * 144;
        uint32_t bbase = sb + (buf ? SM_B1 : SM_B0) + lr * 144;
        const char* ap = (const char*)(A + (size_t)gaRow * Kd + koff);
        const char* bp = (const char*)(B + (size_t)gbRow * Kd + koff);
#pragma unroll
        for (int u = 0; u < 4; u++) {
            cp16(abase + (lc + u) * 16, ap + (lc + u) * 16);
            cp16(bbase + (lc + u) * 16, bp + (lc + u) * 16);
        }
        CP_COMMIT();
    };

    issue(0);
    for (int c = 0; c < NCH; c++) {
        if (c + 1 < NCH) { issue(c + 1); CP_WAIT1(); }
        else             { CP_WAIT0(); }
        __syncthreads();
        const int buf = c & 1;
        const __nv_bfloat16* As = (const __nv_bfloat16*)(dsm + (buf ? SM_A1 : SM_A0));
        const __nv_bfloat16* Bs = (const __nv_bfloat16*)(dsm + (buf ? SM_B1 : SM_B0));
#pragma unroll
        for (int kt = 0; kt < 4; kt++) {
            wmma::fragment<wmma::matrix_a, 16, 16, 16, __nv_bfloat16, wmma::row_major> af[4];
            wmma::fragment<wmma::matrix_b, 16, 16, 16, __nv_bfloat16, wmma::col_major> bf[2];
#pragma unroll
            for (int n = 0; n < 2; n++)
                wmma::load_matrix_sync(bf[n], Bs + (wn * 32 + n * 16) * APAD + kt * 16, APAD);
#pragma unroll
            for (int m = 0; m < 4; m++)
                wmma::load_matrix_sync(af[m], As + (wm * 64 + m * 16) * APAD + kt * 16, APAD);
#pragma unroll
            for (int m = 0; m < 4; m++)
#pragma unroll
                for (int n = 0; n < 2; n++)
                    wmma::mma_sync(acc[m][n], af[m], bf[n], acc[m][n]);
        }
        __syncthreads();
    }

    float* stg = (float*)(dsm + SM_STG) + wid * 256;
    const int srow = lane >> 1;
    const int scol = (lane & 1) * 8;
#pragma unroll
    for (int m = 0; m < 4; m++) {
#pragma unroll
        for (int n = 0; n < 2; n++) {
            wmma::store_matrix_sync(stg, acc[m][n], 16, wmma::mem_row_major);
            __syncwarp();
            int grow = bm + wm * 64 + m * 16 + srow;
            int gcol = bn + wn * 32 + n * 16 + scol;
            if (grow < Mr) {
                float* crow = C + (size_t)grow * Nc + gcol;
                const float* sp = stg + srow * 16 + scol;
#pragma unroll
                for (int q = 0; q < 2; q++) {
                    float4 v = *(const float4*)(sp + q * 4);
                    if (MODE >= 1) {
                        float4 bb = *(const float4*)(bias + gcol + q * 4);
                        v.x += bb.x; v.y += bb.y; v.z += bb.z; v.w += bb.w;
                        v.x = (v.x > 0.f) ? v.x : NEG_SLOPE * v.x;
                        v.y = (v.y > 0.f) ? v.y : NEG_SLOPE * v.y;
                        v.z = (v.z > 0.f) ? v.z : NEG_SLOPE * v.z;
                        v.w = (v.w > 0.f) ? v.w : NEG_SLOPE * v.w;
                    }
                    if (MODE == 2) {
                        float4 o = *(const float4*)(crow + q * 4);
                        v.x += o.x; v.y += o.y; v.z += o.z; v.w += o.w;
                    }
                    *(float4*)(crow + q * 4) = v;
                }
            }
            __syncwarp();
        }
    }
}

// ---------------- weight transpose+split ----------------
__global__ void k_wsplit(const float* __restrict__ W, __nv_bfloat16* __restrict__ thi,
                         __nv_bfloat16* __restrict__ tlo, int K, int N) {
    int i = blockIdx.x * blockDim.x + threadIdx.x;
    if (i >= K * N) return;
    int n = i / K, k = i - n * K;
    float v = W[(size_t)k * N + n];
    __nv_bfloat16 h = __float2bfloat16(v);
    thi[i] = h;
    tlo[i] = __float2bfloat16(v - __bfloat162float(h));
}

// ---------------- structure kernels ----------------
__global__ void k_zero2(int* a, int na, int* b, int nb) {
    int i = blockIdx.x * blockDim.x + threadIdx.x;
    if (i < na) a[i] = 0;
    else if (i < na + nb) b[i - na] = 0;
}

__global__ void k_hist(const int* __restrict__ row, const int* __restrict__ col,
                       int* degn, int* dege, int E) {
    int i = blockIdx.x * blockDim.x + threadIdx.x;
    if (i < E) {
        atomicAdd(&degn[row[i]], 1);
        atomicAdd(&dege[col[i]], 1);
    }
}

// ---- 3-stage parallel exclusive scan (1024 elems per block) ----
__global__ void k_bsum(const int* __restrict__ cnt, int* __restrict__ bsum, int n) {
    int b = blockIdx.x, t = threadIdx.x;   // 256 threads
    int base = b * 1024;
    int s = 0;
#pragma unroll
    for (int u = 0; u < 4; u++) {
        int i = base + t + u * 256;
        if (i < n) s += cnt[i];
    }
    __shared__ int red[8];
    for (int o = 16; o; o >>= 1) s += __shfl_down_sync(0xffffffffu, s, o);
    if ((t & 31) == 0) red[t >> 5] = s;
    __syncthreads();
    if (t == 0) {
        int v = 0;
#pragma unroll
        for (int w = 0; w < 8; w++) v += red[w];
        bsum[b] = v;
    }
}

__global__ void k_bscan(int* bsum, int nb) {
    if (threadIdx.x == 0) {
        int run = 0;
        for (int i = 0; i < nb; i++) { int v = bsum[i]; bsum[i] = run; run += v; }
        bsum[nb] = run;
    }
}

__global__ void k_lscan(const int* __restrict__ cnt, const int* __restrict__ bsum,
                        int* __restrict__ start, int* __restrict__ cur, int n, int nb) {
    int b = blockIdx.x, t = threadIdx.x;   // 256 threads, 1024 elems/block
    __shared__ int sh[256];
    int base = b * 1024;
    int v[4];
    int s = 0;
#pragma unroll
    for (int u = 0; u < 4; u++) {
        int i = base + t * 4 + u;
        v[u] = (i < n) ? cnt[i] : 0;
        s += v[u];
    }
    sh[t] = s;
    __syncthreads();
    for (int o = 1; o < 256; o <<= 1) {
        int a = (t >= o) ? sh[t - o] : 0;
        __syncthreads();
        sh[t] += a;
        __syncthreads();
    }
    int run = bsum[b] + ((t == 0) ? 0 : sh[t - 1]);
#pragma unroll
    for (int u = 0; u < 4; u++) {
        int i = base + t * 4 + u;
        if (i < n) { start[i] = run; cur[i] = run; run += v[u]; }
    }
    if (b == 0 && t == 0) start[n] = bsum[nb];
}

__global__ void k_scatter(const int* __restrict__ row, const int* __restrict__ col,
                          int* rcur, int* ccur, int* __restrict__ rcsr,
                          int* __restrict__ ccsr, int E) {
    int i = blockIdx.x * blockDim.x + threadIdx.x;
    if (i < E) {
        int pr = atomicAdd(&rcur[row[i]], 1);
        rcsr[pr] = i;
        int pc = atomicAdd(&ccur[col[i]], 1);
        ccsr[pc] = i;
    }
}

__global__ void k_inv2(const int* __restrict__ da, float* __restrict__ ia, int na,
                       const int* __restrict__ db, float* __restrict__ ib, int nb) {
    int i = blockIdx.x * blockDim.x + threadIdx.x;
    if (i < na) {
        int d = da[i];
        ia[i] = (d > 0) ? (1.0f / (float)d) : 0.0f;
    } else if (i < na + nb) {
        int d = db[i - na];
        ib[i - na] = (d > 0) ? (1.0f / (float)d) : 0.0f;
    }
}

// ---------------- row dots ----------------
__global__ void k_rowdot(const float* __restrict__ X, const float* __restrict__ v,
                         float* __restrict__ out, int rows) {
    int gw = (blockIdx.x * blockDim.x + threadIdx.x) >> 5;
    int lane = threadIdx.x & 31;
    if (gw >= rows) return;
    const float4* xr = (const float4*)(X + (size_t)gw * FF);
    const float4* vv = (const float4*)v;
    float s = 0.f;
#pragma unroll
    for (int j = 0; j < 4; j++) {
        float4 a = xr[lane + 32 * j];
        float4 b = vv[lane + 32 * j];
        s += a.x * b.x + a.y * b.y + a.z * b.z + a.w * b.w;
    }
    for (int o = 16; o; o >>= 1) s += __shfl_down_sync(0xffffffffu, s, o);
    if (!lane) out[gw] = s;
}

__global__ void k_rowdot2(const float* __restrict__ X, const float* __restrict__ v1,
                          const float* __restrict__ v2, float* __restrict__ o1,
                          float* __restrict__ o2, int rows) {
    int gw = (blockIdx.x * blockDim.x + threadIdx.x) >> 5;
    int lane = threadIdx.x & 31;
    if (gw >= rows) return;
    const float4* xr = (const float4*)(X + (size_t)gw * FF);
    const float4* va = (const float4*)v1;
    const float4* vb = (const float4*)v2;
    float s1 = 0.f, s2 = 0.f;
#pragma unroll
    for (int j = 0; j < 4; j++) {
        float4 a = xr[lane + 32 * j];
        float4 b = va[lane + 32 * j];
        float4 c = vb[lane + 32 * j];
        s1 += a.x * b.x + a.y * b.y + a.z * b.z + a.w * b.w;
        s2 += a.x * c.x + a.y * c.y + a.z * c.z + a.w * c.w;
    }
    for (int o = 16; o; o >>= 1) {
        s1 += __shfl_down_sync(0xffffffffu, s1, o);
        s2 += __shfl_down_sync(0xffffffffu, s2, o);
    }
    if (!lane) { o1[gw] = s1; o2[gw] = s2; }
}

// ---------------- fused attention softmax + propagate-1 ----------------
__global__ void __launch_bounds__(256) k_attnprop(
    const int* __restrict__ cstart, const int* __restrict__ ccsr,
    const int* __restrict__ row, const float* __restrict__ xn,
    const float* __restrict__ en, const float* __restrict__ Binv,
    const float* __restrict__ X, float* __restrict__ alpha,
    __nv_bfloat16* __restrict__ efhi, __nv_bfloat16* __restrict__ eflo) {
    int m = blockIdx.x;
    int s = cstart[m], e = cstart[m + 1];
    int tid = threadIdx.x;
    __shared__ float red[256];
    __shared__ int   shr[256];
    __shared__ float shc[256];

    float enm = en[m];
    float mx = -3.0e38f;
    for (int i = s + tid; i < e; i += 256) {
        int ed = ccsr[i];
        float p = xn[row[ed]] + enm;
        p = (p > 0.f) ? p : ATT_SLOPE * p;
        alpha[ed] = p;
        mx = fmaxf(mx, p);
    }
    red[tid] = mx;
    __syncthreads();
    for (int o = 128; o; o >>= 1) {
        if (tid < o) red[tid] = fmaxf(red[tid], red[tid + o]);
        __syncthreads();
    }
    float amax = red[0];
    if (!(amax > -1e37f)) amax = 0.f;
    __syncthreads();
    float sm = 0.f;
    for (int i = s + tid; i < e; i += 256) {
        int ed = ccsr[i];
        float ex = expf(alpha[ed] - amax);
        alpha[ed] = ex;
        sm += ex;
    }
    red[tid] = sm;
    __syncthreads();
    for (int o = 128; o; o >>= 1) {
        if (tid < o) red[tid] += red[tid + o];
        __syncthreads();
    }
    float inv = 1.f / fmaxf(red[0], 1e-16f);
    float bi = Binv[m];
    float ax = 0.f, ay = 0.f;
    const float* base = X + 2 * tid;
    for (int b0 = s; b0 < e; b0 += 256) {
        int cnt = min(256, e - b0);
        __syncthreads();
        if (tid < cnt) {
            int ed = ccsr[b0 + tid];
            float a = alpha[ed] * inv;
            alpha[ed] = a;
            shr[tid] = row[ed];
            shc[tid] = a * bi;
        }
        __syncthreads();
        int j = 0;
        // unrolled x4: 4 outstanding L2 loads per thread
        for (; j + 4 <= cnt; j += 4) {
            int r0 = shr[j], r1 = shr[j + 1], r2 = shr[j + 2], r3 = shr[j + 3];
            float c0 = shc[j], c1 = shc[j + 1], c2 = shc[j + 2], c3 = shc[j + 3];
            float2 v0 = *(const float2*)(base + (size_t)r0 * FF);
            float2 v1 = *(const float2*)(base + (size_t)r1 * FF);
            float2 v2 = *(const float2*)(base + (size_t)r2 * FF);
            float2 v3 = *(const float2*)(base + (size_t)r3 * FF);
            ax += c0 * v0.x + c1 * v1.x + c2 * v2.x + c3 * v3.x;
            ay += c0 * v0.y + c1 * v1.y + c2 * v2.y + c3 * v3.y;
        }
        for (; j < cnt; j++) {
            float2 v = *(const float2*)(base + (size_t)shr[j] * FF);
            float cf = shc[j];
            ax += cf * v.x;
            ay += cf * v.y;
        }
    }
    __nv_bfloat16 hx = __float2bfloat16(ax), hy = __float2bfloat16(ay);
    __nv_bfloat16 lx = __float2bfloat16(ax - __bfloat162float(hx));
    __nv_bfloat16 ly = __float2bfloat16(ay - __bfloat162float(hy));
    ((__nv_bfloat162*)(efhi + (size_t)m * FF))[tid] = __nv_bfloat162(hx, hy);
    ((__nv_bfloat162*)(eflo + (size_t)m * FF))[tid] = __nv_bfloat162(lx, ly);
}

// ---------------- propagate-2 (unrolled x4) ----------------
__global__ void k_prop2(const int* __restrict__ rstart, const int* __restrict__ rcsr,
                        const int* __restrict__ col, const float* __restrict__ alpha,
                        const float* __restrict__ Dinv, const float* __restrict__ ef,
                        const float* __restrict__ bias, float* __restrict__ out) {
    int n = blockIdx.x;
    int s = rstart[n], e = rstart[n + 1];
    int tid = threadIdx.x;
    float a0 = 0.f, a1 = 0.f, a2 = 0.f, a3 = 0.f;
    int i = s;
    for (; i + 4 <= e; i += 4) {
        int e0 = rcsr[i], e1 = rcsr[i + 1], e2 = rcsr[i + 2], e3 = rcsr[i + 3];
        float c0 = alpha[e0], c1 = alpha[e1], c2 = alpha[e2], c3 = alpha[e3];
        float4 v0 = *(const float4*)(ef + (size_t)col[e0] * FF + 4 * tid);
        float4 v1 = *(const float4*)(ef + (size_t)col[e1] * FF + 4 * tid);
        float4 v2 = *(const float4*)(ef + (size_t)col[e2] * FF + 4 * tid);
        float4 v3 = *(const float4*)(ef + (size_t)col[e3] * FF + 4 * tid);
        a0 += c0 * v0.x + c1 * v1.x + c2 * v2.x + c3 * v3.x;
        a1 += c0 * v0.y + c1 * v1.y + c2 * v2.y + c3 * v3.y;
        a2 += c0 * v0.z + c1 * v1.z + c2 * v2.z + c3 * v3.z;
        a3 += c0 * v0.w + c1 * v1.w + c2 * v2.w + c3 * v3.w;
    }
    for (; i < e; i++) {
        int ed = rcsr[i];
        float cf = alpha[ed];
        float4 v = *(const float4*)(ef + (size_t)col[ed] * FF + 4 * tid);
        a0 += cf * v.x; a1 += cf * v.y; a2 += cf * v.z; a3 += cf * v.w;
    }
    float d = Dinv[n];
    float4 b = *(const float4*)(bias + 4 * tid);
    float4 o;
    o.x = a0 * d + b.x; o.y = a1 * d + b.y; o.z = a2 * d + b.z; o.w = a3 * d + b.w;
    *(float4*)(out + (size_t)n * FF + 4 * tid) = o;
}

// ---------------- graph norm ----------------
__global__ void k_colstat(const float* __restrict__ X, float* __restrict__ p1,
                          float* __restrict__ p2, int rows) {
    int b = blockIdx.x;
    int c = threadIdx.x;
    int r0 = b * CSTAT_ROWS, r1 = min(r0 + CSTAT_ROWS, rows);
    float s1 = 0.f, s2 = 0.f;
    for (int r = r0; r < r1; r++) {
        float v = X[(size_t)r * FF + c];
        s1 += v;
        s2 += v * v;
    }
    p1[b * FF + c] = s1;
    p2[b * FF + c] = s2;
}

__global__ void k_statfin(const float* __restrict__ p1, const float* __restrict__ p2,
                          int nblk, const float* __restrict__ w,
                          const float* __restrict__ ms, float* __restrict__ shift,
                          float* __restrict__ scale, float rows_inv) {
    int c = threadIdx.x;
    float s1 = 0.f, s2 = 0.f;
    for (int i = 0; i < nblk; i++) {
        s1 += p1[i * FF + c];
        s2 += p2[i * FF + c];
    }
    float mu = s1 * rows_inv;
    float ex2 = s2 * rows_inv;
    float m = ms[c];
    float sh = m * mu;
    float var = ex2 - sh * (2.f * mu - sh);
    shift[c] = sh;
    scale[c] = w[c] / sqrtf(var + 1e-5f);
}

__global__ void k_normsplit(const float* __restrict__ X, const float* __restrict__ shift,
                            const float* __restrict__ scale, const float* __restrict__ beta,
                            float* __restrict__ Yf, __nv_bfloat16* __restrict__ hi,
                            __nv_bfloat16* __restrict__ lo, int total4) {
    int i = blockIdx.x * blockDim.x + threadIdx.x;
    if (i >= total4) return;
    int c = (i & 127) * 4;
    float4 v = ((const float4*)X)[i];
    float4 sh = *(const float4*)(shift + c);
    float4 sc = *(const float4*)(scale + c);
    float4 be = *(const float4*)(beta + c);
    float y0 = (v.x - sh.x) * sc.x + be.x;
    float y1 = (v.y - sh.y) * sc.y + be.y;
    float y2 = (v.z - sh.z) * sc.z + be.z;
    float y3 = (v.w - sh.w) * sc.w + be.w;
    y0 = (y0 > 0.f) ? y0 : NEG_SLOPE * y0;
    y1 = (y1 > 0.f) ? y1 : NEG_SLOPE * y1;
    y2 = (y2 > 0.f) ? y2 : NEG_SLOPE * y2;
    y3 = (y3 > 0.f) ? y3 : NEG_SLOPE * y3;
    ((float4*)Yf)[i] = make_float4(y0, y1, y2, y3);
    __nv_bfloat16 h0 = __float2bfloat16(y0), h1 = __float2bfloat16(y1);
    __nv_bfloat16 h2 = __float2bfloat16(y2), h3 = __float2bfloat16(y3);
    __nv_bfloat16 l0 = __float2bfloat16(y0 - __bfloat162float(h0));
    __nv_bfloat16 l1 = __float2bfloat16(y1 - __bfloat162float(h1));
    __nv_bfloat16 l2 = __float2bfloat16(y2 - __bfloat162float(h2));
    __nv_bfloat16 l3 = __float2bfloat16(y3 - __bfloat162float(h3));
    ((__nv_bfloat162*)hi)[i * 2]     = __nv_bfloat162(h0, h1);
    ((__nv_bfloat162*)hi)[i * 2 + 1] = __nv_bfloat162(h2, h3);
    ((__nv_bfloat162*)lo)[i * 2]     = __nv_bfloat162(l0, l1);
    ((__nv_bfloat162*)lo)[i * 2 + 1] = __nv_bfloat162(l2, l3);
}

__global__ void k_cls(const float* __restrict__ A, const float* __restrict__ W,
                      const float* __restrict__ b, float* __restrict__ out, int rows) {
    int gw = (blockIdx.x * blockDim.x + threadIdx.x) >> 5;
    int lane = threadIdx.x & 31;
    if (gw >= rows) return;
    const float* ar = A + (size_t)gw * HIDD;
    float s0 = 0.f, s1 = 0.f;
    for (int h = lane; h < HIDD; h += 32) {
        float v = ar[h];
        s0 += v * W[h * 2];
        s1 += v * W[h * 2 + 1];
    }
    for (int o = 16; o; o >>= 1) {
        s0 += __shfl_down_sync(0xffffffffu, s0, o);
        s1 += __shfl_down_sync(0xffffffffu, s1, o);
    }
    if (!lane) {
        out[gw * 2] = s0 + b[0];
        out[gw * 2 + 1] = s1 + b[1];
    }
}

// ---------------- host launch ----------------
extern "C" void kernel_launch(void* const* d_in, const int* in_sizes, int n_in,
                              void* d_out, int out_size) {
    const float* x    = (const float*)d_in[0];
    const int*   ei   = (const int*)d_in[1];
    const float* ea   = (const float*)d_in[2];
    const float* W1   = (const float*)d_in[3];
    const float* att1 = (const float*)d_in[4];
    const float* b1   = (const float*)d_in[5];
    const float* W2   = (const float*)d_in[6];
    const float* att2 = (const float*)d_in[7];
    const float* b2   = (const float*)d_in[8];
    const float* gn1w = (const float*)d_in[9];
    const float* gn1b = (const float*)d_in[10];
    const float* gn1ms= (const float*)d_in[11];
    const float* gn2w = (const float*)d_in[12];
    const float* gn2b = (const float*)d_in[13];
    const float* gn2ms= (const float*)d_in[14];
    const float* fc1W = (const float*)d_in[15];
    const float* fc1b = (const float*)d_in[16];
    const float* fc2W = (const float*)d_in[17];
    const float* fc2b = (const float*)d_in[18];
    const float* clsW = (const float*)d_in[19];
    const float* clsb = (const float*)d_in[20];
    float* outp = (float*)d_out;

    const int* row = ei;
    const int* col = ei + EE;

    float *xl, *el, *h, *fc, *xn, *en, *wa, *wb, *alpha, *Dinv, *Binv;
    float *p1, *p2, *shift, *scale;
    int *degn, *dege, *rstart, *cstart, *rcur, *ccur, *rcsr, *ccsr, *bsumN, *bsumM;
    __nv_bfloat16 *Ahi, *Alo, *eahi, *ealo, *W1thi, *W1tlo, *W2thi, *W2tlo;
    __nv_bfloat16 *f1thi, *f1tlo, *f2thi, *f2tlo;
    cudaGetSymbolAddress((void**)&xl, g_xl);
    cudaGetSymbolAddress((void**)&el, g_el);
    cudaGetSymbolAddress((void**)&h, g_h);
    cudaGetSymbolAddress((void**)&fc, g_fc);
    cudaGetSymbolAddress((void**)&xn, g_xn);
    cudaGetSymbolAddress((void**)&en, g_en);
    cudaGetSymbolAddress((void**)&wa, g_wa);
    cudaGetSymbolAddress((void**)&wb, g_wb);
    cudaGetSymbolAddress((void**)&alpha, g_alpha);
    cudaGetSymbolAddress((void**)&Dinv, g_Dinv);
    cudaGetSymbolAddress((void**)&Binv, g_Binv);
    cudaGetSymbolAddress((void**)&p1, g_p1);
    cudaGetSymbolAddress((void**)&p2, g_p2);
    cudaGetSymbolAddress((void**)&shift, g_shift);
    cudaGetSymbolAddress((void**)&scale, g_scale);
    cudaGetSymbolAddress((void**)&degn, g_degn);
    cudaGetSymbolAddress((void**)&dege, g_dege);
    cudaGetSymbolAddress((void**)&rstart, g_rstart);
    cudaGetSymbolAddress((void**)&cstart, g_cstart);
    cudaGetSymbolAddress((void**)&rcur, g_rcur);
    cudaGetSymbolAddress((void**)&ccur, g_ccur);
    cudaGetSymbolAddress((void**)&rcsr, g_rcsr);
    cudaGetSymbolAddress((void**)&ccsr, g_ccsr);
    cudaGetSymbolAddress((void**)&bsumN, g_bsumN);
    cudaGetSymbolAddress((void**)&bsumM, g_bsumM);
    cudaGetSymbolAddress((void**)&Ahi, g_Ahi);
    cudaGetSymbolAddress((void**)&Alo, g_Alo);
    cudaGetSymbolAddress((void**)&eahi, g_eahi);
    cudaGetSymbolAddress((void**)&ealo, g_ealo);
    cudaGetSymbolAddress((void**)&W1thi, g_W1thi);
    cudaGetSymbolAddress((void**)&W1tlo, g_W1tlo);
    cudaGetSymbolAddress((void**)&W2thi, g_W2thi);
    cudaGetSymbolAddress((void**)&W2tlo, g_W2tlo);
    cudaGetSymbolAddress((void**)&f1thi, g_f1thi);
    cudaGetSymbolAddress((void**)&f1tlo, g_f1tlo);
    cudaGetSymbolAddress((void**)&f2thi, g_f2thi);
    cudaGetSymbolAddress((void**)&f2tlo, g_f2tlo);

    static bool attr_set = false;
    if (!attr_set) {
        cudaFuncSetAttribute(k_wgemm<0>, cudaFuncAttributeMaxDynamicSharedMemorySize, GEMM_SMEM);
        cudaFuncSetAttribute(k_wgemm<1>, cudaFuncAttributeMaxDynamicSharedMemorySize, GEMM_SMEM);
        cudaFuncSetAttribute(k_wgemm<2>, cudaFuncAttributeMaxDynamicSharedMemorySize, GEMM_SMEM);
        attr_set = true;
    }

    const int NBN = (NN + 1023) / 1024;   // 20
    const int NBM = (MM + 1023) / 1024;   // 2

    // ---- graph structure ----
    k_zero2<<<(NN + MM + 255) / 256, 256>>>(degn, NN, dege, MM);
    k_hist<<<(EE + 255) / 256, 256>>>(row, col, degn, dege, EE);
    k_bsum<<<NBM, 256>>>(dege, bsumM, MM);
    k_bsum<<<NBN, 256>>>(degn, bsumN, NN);
    k_bscan<<<1, 32>>>(bsumM, NBM);
    k_bscan<<<1, 32>>>(bsumN, NBN);
    k_lscan<<<NBM, 256>>>(dege, bsumM, cstart, ccur, MM, NBM);
    k_lscan<<<NBN, 256>>>(degn, bsumN, rstart, rcur, NN, NBN);
    k_scatter<<<(EE + 255) / 256, 256>>>(row, col, rcur, ccur, rcsr, ccsr, EE);
    k_inv2<<<(NN + MM + 255) / 256, 256>>>(degn, Dinv, NN, dege, Binv, MM);

    // ---- weight conversions ----
    k_wsplit<<<(FF * FF + 255) / 256, 256>>>(W1, W1thi, W1tlo, FF, FF);
    k_wsplit<<<(FF * FF + 255) / 256, 256>>>(W2, W2thi, W2tlo, FF, FF);
    k_wsplit<<<(FF * HIDD + 255) / 256, 256>>>(fc1W, f1thi, f1tlo, FF, HIDD);
    k_wsplit<<<(FF * HIDD + 255) / 256, 256>>>(fc2W, f2thi, f2tlo, FF, HIDD);

    const float rows_inv = 1.0f / (float)NN;
    dim3 gM(FF / 128, MM / 128);
    dim3 gFC(HIDD / 128, (NN + 127) / 128);

    // ==== conv1 ====
    k_rowdot2<<<(FF * 32 + 255) / 256, 256>>>(W1, att1, att1 + FF, wa, wb, FF);
    k_rowdot<<<(NN * 32 + 255) / 256, 256>>>(x, wa, xn, NN);
    k_rowdot<<<(MM * 32 + 255) / 256, 256>>>(ea, wb, en, MM);
    k_attnprop<<<MM, 256>>>(cstart, ccsr, row, xn, en, Binv, x, alpha, eahi, ealo);
    k_wgemm<0><<<gM, 256, GEMM_SMEM>>>(eahi, ealo, W1thi, W1tlo, el, MM, FF, FF, nullptr);
    k_prop2<<<NN, 128>>>(rstart, rcsr, col, alpha, Dinv, el, b1, xl);
    k_colstat<<<CSTAT_BLKS, FF>>>(xl, p1, p2, NN);
    k_statfin<<<1, FF>>>(p1, p2, CSTAT_BLKS, gn1w, gn1ms, shift, scale, rows_inv);
    k_normsplit<<<(NN * (FF / 4) + 255) / 256, 256>>>(xl, shift, scale, gn1b, h, Ahi, Alo, NN * (FF / 4));
    k_wgemm<1><<<gFC, 256, GEMM_SMEM>>>(Ahi, Alo, f1thi, f1tlo, fc, NN, HIDD, FF, fc1b);

    // ==== conv2 ====
    k_rowdot2<<<(FF * 32 + 255) / 256, 256>>>(W2, att2, att2 + FF, wa, wb, FF);
    k_rowdot<<<(NN * 32 + 255) / 256, 256>>>(h, wa, xn, NN);
    k_rowdot<<<(MM * 32 + 255) / 256, 256>>>(ea, wb, en, MM);
    k_attnprop<<<MM, 256>>>(cstart, ccsr, row, xn, en, Binv, h, alpha, eahi, ealo);
    k_wgemm<0><<<gM, 256, GEMM_SMEM>>>(eahi, ealo, W2thi, W2tlo, el, MM, FF, FF, nullptr);
    k_prop2<<<NN, 128>>>(rstart, rcsr, col, alpha, Dinv, el, b2, xl);
    k_colstat<<<CSTAT_BLKS, FF>>>(xl, p1, p2, NN);
    k_statfin<<<1, FF>>>(p1, p2, CSTAT_BLKS, gn2w, gn2ms, shift, scale, rows_inv);
    k_normsplit<<<(NN * (FF / 4) + 255) / 256, 256>>>(xl, shift, scale, gn2b, h, Ahi, Alo, NN * (FF / 4));
    k_wgemm<2><<<gFC, 256, GEMM_SMEM>>>(Ahi, Alo, f2thi, f2tlo, fc, NN, HIDD, FF, fc2b);

    // ---- classifier ----
    k_cls<<<(NN * 32 + 255) / 256, 256>>>(fc, clsW, clsb, outp, NN);
}

// round 9
// speedup vs baseline: 2.1569x; 1.0534x over previous
#include <cuda_runtime.h>
#include <cuda_bf16.h>
#include <cuda_fp16.h>
#include <mma.h>
#include <cstdint>
#include <math.h>

using namespace nvcuda;

#define NN 20000
#define MM 2048
#define EE 320000
#define FF 512
#define HIDD 256
#define CSTAT_ROWS 128
#define CSTAT_BLKS ((NN + CSTAT_ROWS - 1) / CSTAT_ROWS)   // 157

#define NEG_SLOPE 0.01f
#define ATT_SLOPE 0.2f

// ---------------- scratch ----------------
__device__ float g_xl[NN * FF];
__device__ __half g_elb[MM * FF];          // edge_feat after GEMM (fp16 gather table)
__device__ float g_h[NN * FF];
__device__ __half g_h16[NN * FF];          // fp16 gather table: x (conv1) then h (conv2)
__device__ float g_fc[NN * HIDD];
__device__ float g_xn[NN];
__device__ float g_en[MM];
__device__ float g_wa[FF];
__device__ float g_wb[FF];
__device__ float g_alpha[EE];
__device__ float g_Dinv[NN];
__device__ float g_Binv[MM];
__device__ int   g_degn[NN];
__device__ int   g_dege[MM];
__device__ int   g_rstart[NN + 1];
__device__ int   g_cstart[MM + 1];
__device__ int   g_rcur[NN];
__device__ int   g_ccur[MM];
__device__ int   g_rcsr[EE];
__device__ int   g_ccsr[EE];
__device__ int   g_bsumN[32];
__device__ int   g_bsumM[8];
__device__ float g_p1[CSTAT_BLKS * FF];
__device__ float g_p2[CSTAT_BLKS * FF];
__device__ float g_shift[FF];
__device__ float g_scale[FF];
__device__ __nv_bfloat16 g_Ahi[NN * FF];
__device__ __nv_bfloat16 g_Alo[NN * FF];
__device__ __nv_bfloat16 g_eahi[MM * FF];
__device__ __nv_bfloat16 g_ealo[MM * FF];
__device__ __nv_bfloat16 g_W1thi[FF * FF];
__device__ __nv_bfloat16 g_W1tlo[FF * FF];
__device__ __nv_bfloat16 g_W2thi[FF * FF];
__device__ __nv_bfloat16 g_W2tlo[FF * FF];
__device__ __nv_bfloat16 g_f1thi[HIDD * FF];
__device__ __nv_bfloat16 g_f1tlo[HIDD * FF];
__device__ __nv_bfloat16 g_f2thi[HIDD * FF];
__device__ __nv_bfloat16 g_f2tlo[HIDD * FF];

// ---------------- cp.async helpers ----------------
__device__ __forceinline__ uint32_t smem_u32(const void* p) {
    uint32_t a;
    asm("{ .reg .u64 t; cvta.to.shared.u64 t, %1; cvt.u32.u64 %0, t; }" : "=r"(a) : "l"(p));
    return a;
}
__device__ __forceinline__ void cp16(uint32_t dst, const void* src) {
    asm volatile("cp.async.ca.shared.global [%0], [%1], 16;" :: "r"(dst), "l"(src));
}
#define CP_COMMIT() asm volatile("cp.async.commit_group;" ::: "memory")
#define CP_WAIT1()  asm volatile("cp.async.wait_group 1;" ::: "memory")
#define CP_WAIT0()  asm volatile("cp.async.wait_group 0;" ::: "memory")

#define APAD 72
#define SM_A0 0
#define SM_B0 18432
#define SM_A1 36864
#define SM_B1 55296
#define SM_STG 73728
#define GEMM_SMEM 81920

// ---------------- cp.async double-buffered wmma split-bf16 GEMM ----------------
// MODE 0: store fp16 (C is __half*); MODE 1: store lrelu(AB+bias) fp32;
// MODE 2: C += lrelu(AB+bias) fp32
template <int MODE>
__global__ void __launch_bounds__(256) k_wgemm(
    const __nv_bfloat16* __restrict__ Ahi, const __nv_bfloat16* __restrict__ Alo,
    const __nv_bfloat16* __restrict__ Bthi, const __nv_bfloat16* __restrict__ Btlo,
    void* __restrict__ Cv, int Mr, int Nc, int Kd, const float* __restrict__ bias) {
    extern __shared__ __align__(16) char dsm[];
    const uint32_t sb = smem_u32(dsm);

    const int tid = threadIdx.x;
    const int wid = tid >> 5;
    const int lane = tid & 31;
    const int wm = wid >> 2;
    const int wn = wid & 3;
    const int bm = blockIdx.y * 128;
    const int bn = blockIdx.x * 128;

    const int CPS = Kd >> 6;
    const int NCH = 3 * CPS;

    const int lr = tid >> 1;
    const int lc = (tid & 1) * 4;
    const int gaRow = min(bm + lr, Mr - 1);
    const int gbRow = bn + lr;

    wmma::fragment<wmma::accumulator, 16, 16, 16, float> acc[4][2];
#pragma unroll
    for (int i = 0; i < 4; i++)
#pragma unroll
        for (int j = 0; j < 2; j++) wmma::fill_fragment(acc[i][j], 0.0f);

    auto issue = [&](int c) {
        int seg = c / CPS;
        int j = c - seg * CPS;
        const __nv_bfloat16* A = (seg == 1) ? Alo : Ahi;
        const __nv_bfloat16* B = (seg == 2) ? Btlo : Bthi;
        int koff = j << 6;
        int buf = c & 1;
        uint32_t abase = sb + (buf ? SM_A1 : SM_A0) + lr * 144;
        uint32_t bbase = sb + (buf ? SM_B1 : SM_B0) + lr * 144;
        const char* ap = (const char*)(A + (size_t)gaRow * Kd + koff);
        const char* bp = (const char*)(B + (size_t)gbRow * Kd + koff);
#pragma unroll
        for (int u = 0; u < 4; u++) {
            cp16(abase + (lc + u) * 16, ap + (lc + u) * 16);
            cp16(bbase + (lc + u) * 16, bp + (lc + u) * 16);
        }
        CP_COMMIT();
    };

    issue(0);
    for (int c = 0; c < NCH; c++) {
        if (c + 1 < NCH) { issue(c + 1); CP_WAIT1(); }
        else             { CP_WAIT0(); }
        __syncthreads();
        const int buf = c & 1;
        const __nv_bfloat16* As = (const __nv_bfloat16*)(dsm + (buf ? SM_A1 : SM_A0));
        const __nv_bfloat16* Bs = (const __nv_bfloat16*)(dsm + (buf ? SM_B1 : SM_B0));
#pragma unroll
        for (int kt = 0; kt < 4; kt++) {
            wmma::fragment<wmma::matrix_a, 16, 16, 16, __nv_bfloat16, wmma::row_major> af[4];
            wmma::fragment<wmma::matrix_b, 16, 16, 16, __nv_bfloat16, wmma::col_major> bf[2];
#pragma unroll
            for (int n = 0; n < 2; n++)
                wmma::load_matrix_sync(bf[n], Bs + (wn * 32 + n * 16) * APAD + kt * 16, APAD);
#pragma unroll
            for (int m = 0; m < 4; m++)
                wmma::load_matrix_sync(af[m], As + (wm * 64 + m * 16) * APAD + kt * 16, APAD);
#pragma unroll
            for (int m = 0; m < 4; m++)
#pragma unroll
                for (int n = 0; n < 2; n++)
                    wmma::mma_sync(acc[m][n], af[m], bf[n], acc[m][n]);
        }
        __syncthreads();
    }

    float* stg = (float*)(dsm + SM_STG) + wid * 256;
    const int srow = lane >> 1;
    const int scol = (lane & 1) * 8;
#pragma unroll
    for (int m = 0; m < 4; m++) {
#pragma unroll
        for (int n = 0; n < 2; n++) {
            wmma::store_matrix_sync(stg, acc[m][n], 16, wmma::mem_row_major);
            __syncwarp();
            int grow = bm + wm * 64 + m * 16 + srow;
            int gcol = bn + wn * 32 + n * 16 + scol;
            if (grow < Mr) {
                const float* sp = stg + srow * 16 + scol;
                if (MODE == 0) {
                    __half* crow = (__half*)Cv + (size_t)grow * Nc + gcol;
#pragma unroll
                    for (int q = 0; q < 2; q++) {
                        float4 v = *(const float4*)(sp + q * 4);
                        ((__half2*)(crow + q * 4))[0] = __floats2half2_rn(v.x, v.y);
                        ((__half2*)(crow + q * 4))[1] = __floats2half2_rn(v.z, v.w);
                    }
                } else {
                    float* crow = (float*)Cv + (size_t)grow * Nc + gcol;
#pragma unroll
                    for (int q = 0; q < 2; q++) {
                        float4 v = *(const float4*)(sp + q * 4);
                        float4 bb = *(const float4*)(bias + gcol + q * 4);
                        v.x += bb.x; v.y += bb.y; v.z += bb.z; v.w += bb.w;
                        v.x = (v.x > 0.f) ? v.x : NEG_SLOPE * v.x;
                        v.y = (v.y > 0.f) ? v.y : NEG_SLOPE * v.y;
                        v.z = (v.z > 0.f) ? v.z : NEG_SLOPE * v.z;
                        v.w = (v.w > 0.f) ? v.w : NEG_SLOPE * v.w;
                        if (MODE == 2) {
                            float4 o = *(const float4*)(crow + q * 4);
                            v.x += o.x; v.y += o.y; v.z += o.z; v.w += o.w;
                        }
                        *(float4*)(crow + q * 4) = v;
                    }
                }
            }
            __syncwarp();
        }
    }
}

// ---------------- conversions ----------------
__global__ void k_wsplit(const float* __restrict__ W, __nv_bfloat16* __restrict__ thi,
                         __nv_bfloat16* __restrict__ tlo, int K, int N) {
    int i = blockIdx.x * blockDim.x + threadIdx.x;
    if (i >= K * N) return;
    int n = i / K, k = i - n * K;
    float v = W[(size_t)k * N + n];
    __nv_bfloat16 h = __float2bfloat16(v);
    thi[i] = h;
    tlo[i] = __float2bfloat16(v - __bfloat162float(h));
}

// fp32 -> fp16 (round), vectorized
__global__ void k_tof16(const float* __restrict__ X, __half* __restrict__ Y, int total4) {
    int i = blockIdx.x * blockDim.x + threadIdx.x;
    if (i >= total4) return;
    float4 v = ((const float4*)X)[i];
    ((__half2*)Y)[i * 2]     = __floats2half2_rn(v.x, v.y);
    ((__half2*)Y)[i * 2 + 1] = __floats2half2_rn(v.z, v.w);
}

// ---------------- structure kernels ----------------
__global__ void k_zero2(int* a, int na, int* b, int nb) {
    int i = blockIdx.x * blockDim.x + threadIdx.x;
    if (i < na) a[i] = 0;
    else if (i < na + nb) b[i - na] = 0;
}

__global__ void k_hist(const int* __restrict__ row, const int* __restrict__ col,
                       int* degn, int* dege, int E) {
    int i = blockIdx.x * blockDim.x + threadIdx.x;
    if (i < E) {
        atomicAdd(&degn[row[i]], 1);
        atomicAdd(&dege[col[i]], 1);
    }
}

__global__ void k_bsum(const int* __restrict__ cnt, int* __restrict__ bsum, int n) {
    int b = blockIdx.x, t = threadIdx.x;
    int base = b * 1024;
    int s = 0;
#pragma unroll
    for (int u = 0; u < 4; u++) {
        int i = base + t + u * 256;
        if (i < n) s += cnt[i];
    }
    __shared__ int red[8];
    for (int o = 16; o; o >>= 1) s += __shfl_down_sync(0xffffffffu, s, o);
    if ((t & 31) == 0) red[t >> 5] = s;
    __syncthreads();
    if (t == 0) {
        int v = 0;
#pragma unroll
        for (int w = 0; w < 8; w++) v += red[w];
        bsum[b] = v;
    }
}

__global__ void k_bscan(int* bsum, int nb) {
    if (threadIdx.x == 0) {
        int run = 0;
        for (int i = 0; i < nb; i++) { int v = bsum[i]; bsum[i] = run; run += v; }
        bsum[nb] = run;
    }
}

__global__ void k_lscan(const int* __restrict__ cnt, const int* __restrict__ bsum,
                        int* __restrict__ start, int* __restrict__ cur, int n, int nb) {
    int b = blockIdx.x, t = threadIdx.x;
    __shared__ int sh[256];
    int base = b * 1024;
    int v[4];
    int s = 0;
#pragma unroll
    for (int u = 0; u < 4; u++) {
        int i = base + t * 4 + u;
        v[u] = (i < n) ? cnt[i] : 0;
        s += v[u];
    }
    sh[t] = s;
    __syncthreads();
    for (int o = 1; o < 256; o <<= 1) {
        int a = (t >= o) ? sh[t - o] : 0;
        __syncthreads();
        sh[t] += a;
        __syncthreads();
    }
    int run = bsum[b] + ((t == 0) ? 0 : sh[t - 1]);
#pragma unroll
    for (int u = 0; u < 4; u++) {
        int i = base + t * 4 + u;
        if (i < n) { start[i] = run; cur[i] = run; run += v[u]; }
    }
    if (b == 0 && t == 0) start[n] = bsum[nb];
}

__global__ void k_scatter(const int* __restrict__ row, const int* __restrict__ col,
                          int* rcur, int* ccur, int* __restrict__ rcsr,
                          int* __restrict__ ccsr, int E) {
    int i = blockIdx.x * blockDim.x + threadIdx.x;
    if (i < E) {
        int pr = atomicAdd(&rcur[row[i]], 1);
        rcsr[pr] = i;
        int pc = atomicAdd(&ccur[col[i]], 1);
        ccsr[pc] = i;
    }
}

__global__ void k_inv2(const int* __restrict__ da, float* __restrict__ ia, int na,
                       const int* __restrict__ db, float* __restrict__ ib, int nb) {
    int i = blockIdx.x * blockDim.x + threadIdx.x;
    if (i < na) {
        int d = da[i];
        ia[i] = (d > 0) ? (1.0f / (float)d) : 0.0f;
    } else if (i < na + nb) {
        int d = db[i - na];
        ib[i - na] = (d > 0) ? (1.0f / (float)d) : 0.0f;
    }
}

// ---------------- row dots ----------------
__global__ void k_rowdot(const float* __restrict__ X, const float* __restrict__ v,
                         float* __restrict__ out, int rows) {
    int gw = (blockIdx.x * blockDim.x + threadIdx.x) >> 5;
    int lane = threadIdx.x & 31;
    if (gw >= rows) return;
    const float4* xr = (const float4*)(X + (size_t)gw * FF);
    const float4* vv = (const float4*)v;
    float s = 0.f;
#pragma unroll
    for (int j = 0; j < 4; j++) {
        float4 a = xr[lane + 32 * j];
        float4 b = vv[lane + 32 * j];
        s += a.x * b.x + a.y * b.y + a.z * b.z + a.w * b.w;
    }
    for (int o = 16; o; o >>= 1) s += __shfl_down_sync(0xffffffffu, s, o);
    if (!lane) out[gw] = s;
}

__global__ void k_rowdot2(const float* __restrict__ X, const float* __restrict__ v1,
                          const float* __restrict__ v2, float* __restrict__ o1,
                          float* __restrict__ o2, int rows) {
    int gw = (blockIdx.x * blockDim.x + threadIdx.x) >> 5;
    int lane = threadIdx.x & 31;
    if (gw >= rows) return;
    const float4* xr = (const float4*)(X + (size_t)gw * FF);
    const float4* va = (const float4*)v1;
    const float4* vb = (const float4*)v2;
    float s1 = 0.f, s2 = 0.f;
#pragma unroll
    for (int j = 0; j < 4; j++) {
        float4 a = xr[lane + 32 * j];
        float4 b = va[lane + 32 * j];
        float4 c = vb[lane + 32 * j];
        s1 += a.x * b.x + a.y * b.y + a.z * b.z + a.w * b.w;
        s2 += a.x * c.x + a.y * c.y + a.z * c.z + a.w * c.w;
    }
    for (int o = 16; o; o >>= 1) {
        s1 += __shfl_down_sync(0xffffffffu, s1, o);
        s2 += __shfl_down_sync(0xffffffffu, s2, o);
    }
    if (!lane) { o1[gw] = s1; o2[gw] = s2; }
}

// ---------------- fused attention softmax + propagate-1 (fp16 gather) ----------------
__global__ void __launch_bounds__(256) k_attnprop(
    const int* __restrict__ cstart, const int* __restrict__ ccsr,
    const int* __restrict__ row, const float* __restrict__ xn,
    const float* __restrict__ en, const float* __restrict__ Binv,
    const __half* __restrict__ X, float* __restrict__ alpha,
    __nv_bfloat16* __restrict__ efhi, __nv_bfloat16* __restrict__ eflo) {
    int m = blockIdx.x;
    int s = cstart[m], e = cstart[m + 1];
    int tid = threadIdx.x;
    __shared__ float red[256];
    __shared__ int   shr[256];
    __shared__ float shc[256];

    float enm = en[m];
    float mx = -3.0e38f;
    for (int i = s + tid; i < e; i += 256) {
        int ed = ccsr[i];
        float p = xn[row[ed]] + enm;
        p = (p > 0.f) ? p : ATT_SLOPE * p;
        alpha[ed] = p;
        mx = fmaxf(mx, p);
    }
    red[tid] = mx;
    __syncthreads();
    for (int o = 128; o; o >>= 1) {
        if (tid < o) red[tid] = fmaxf(red[tid], red[tid + o]);
        __syncthreads();
    }
    float amax = red[0];
    if (!(amax > -1e37f)) amax = 0.f;
    __syncthreads();
    float sm = 0.f;
    for (int i = s + tid; i < e; i += 256) {
        int ed = ccsr[i];
        float ex = expf(alpha[ed] - amax);
        alpha[ed] = ex;
        sm += ex;
    }
    red[tid] = sm;
    __syncthreads();
    for (int o = 128; o; o >>= 1) {
        if (tid < o) red[tid] += red[tid + o];
        __syncthreads();
    }
    float inv = 1.f / fmaxf(red[0], 1e-16f);
    float bi = Binv[m];
    float ax = 0.f, ay = 0.f;
    const __half2* base = (const __half2*)X + tid;  // pair (2*tid, 2*tid+1)
    for (int b0 = s; b0 < e; b0 += 256) {
        int cnt = min(256, e - b0);
        __syncthreads();
        if (tid < cnt) {
            int ed = ccsr[b0 + tid];
            float a = alpha[ed] * inv;
            alpha[ed] = a;
            shr[tid] = row[ed];
            shc[tid] = a * bi;
        }
        __syncthreads();
        int j = 0;
        for (; j + 4 <= cnt; j += 4) {
            int r0 = shr[j], r1 = shr[j + 1], r2 = shr[j + 2], r3 = shr[j + 3];
            float c0 = shc[j], c1 = shc[j + 1], c2 = shc[j + 2], c3 = shc[j + 3];
            float2 v0 = __half22float2(base[(size_t)r0 * (FF / 2)]);
            float2 v1 = __half22float2(base[(size_t)r1 * (FF / 2)]);
            float2 v2 = __half22float2(base[(size_t)r2 * (FF / 2)]);
            float2 v3 = __half22float2(base[(size_t)r3 * (FF / 2)]);
            ax += c0 * v0.x + c1 * v1.x + c2 * v2.x + c3 * v3.x;
            ay += c0 * v0.y + c1 * v1.y + c2 * v2.y + c3 * v3.y;
        }
        for (; j < cnt; j++) {
            float2 v = __half22float2(base[(size_t)shr[j] * (FF / 2)]);
            float cf = shc[j];
            ax += cf * v.x;
            ay += cf * v.y;
        }
    }
    __nv_bfloat16 hx = __float2bfloat16(ax), hy = __float2bfloat16(ay);
    __nv_bfloat16 lx = __float2bfloat16(ax - __bfloat162float(hx));
    __nv_bfloat16 ly = __float2bfloat16(ay - __bfloat162float(hy));
    ((__nv_bfloat162*)(efhi + (size_t)m * FF))[tid] = __nv_bfloat162(hx, hy);
    ((__nv_bfloat162*)(eflo + (size_t)m * FF))[tid] = __nv_bfloat162(lx, ly);
}

// ---------------- propagate-2 (fp16 gather, unrolled x4) ----------------
__global__ void k_prop2(const int* __restrict__ rstart, const int* __restrict__ rcsr,
                        const int* __restrict__ col, const float* __restrict__ alpha,
                        const float* __restrict__ Dinv, const __half* __restrict__ ef,
                        const float* __restrict__ bias, float* __restrict__ out) {
    int n = blockIdx.x;
    int s = rstart[n], e = rstart[n + 1];
    int tid = threadIdx.x;
    float a0 = 0.f, a1 = 0.f, a2 = 0.f, a3 = 0.f;
    const uint2* base = (const uint2*)ef + tid;   // uint2 = 4 fp16
    int i = s;
    for (; i + 4 <= e; i += 4) {
        int e0 = rcsr[i], e1 = rcsr[i + 1], e2 = rcsr[i + 2], e3 = rcsr[i + 3];
        float c0 = alpha[e0], c1 = alpha[e1], c2 = alpha[e2], c3 = alpha[e3];
        uint2 u0 = base[(size_t)col[e0] * (FF / 4)];
        uint2 u1 = base[(size_t)col[e1] * (FF / 4)];
        uint2 u2 = base[(size_t)col[e2] * (FF / 4)];
        uint2 u3 = base[(size_t)col[e3] * (FF / 4)];
        float2 p0a = __half22float2(*(const __half2*)&u0.x);
        float2 p0b = __half22float2(*(const __half2*)&u0.y);
        float2 p1a = __half22float2(*(const __half2*)&u1.x);
        float2 p1b = __half22float2(*(const __half2*)&u1.y);
        float2 p2a = __half22float2(*(const __half2*)&u2.x);
        float2 p2b = __half22float2(*(const __half2*)&u2.y);
        float2 p3a = __half22float2(*(const __half2*)&u3.x);
        float2 p3b = __half22float2(*(const __half2*)&u3.y);
        a0 += c0 * p0a.x + c1 * p1a.x + c2 * p2a.x + c3 * p3a.x;
        a1 += c0 * p0a.y + c1 * p1a.y + c2 * p2a.y + c3 * p3a.y;
        a2 += c0 * p0b.x + c1 * p1b.x + c2 * p2b.x + c3 * p3b.x;
        a3 += c0 * p0b.y + c1 * p1b.y + c2 * p2b.y + c3 * p3b.y;
    }
    for (; i < e; i++) {
        int ed = rcsr[i];
        float cf = alpha[ed];
        uint2 u = base[(size_t)col[ed] * (FF / 4)];
        float2 pa = __half22float2(*(const __half2*)&u.x);
        float2 pb = __half22float2(*(const __half2*)&u.y);
        a0 += cf * pa.x; a1 += cf * pa.y; a2 += cf * pb.x; a3 += cf * pb.y;
    }
    float d = Dinv[n];
    float4 b = *(const float4*)(bias + 4 * tid);
    float4 o;
    o.x = a0 * d + b.x; o.y = a1 * d + b.y; o.z = a2 * d + b.z; o.w = a3 * d + b.w;
    *(float4*)(out + (size_t)n * FF + 4 * tid) = o;
}

// ---------------- graph norm ----------------
__global__ void k_colstat(const float* __restrict__ X, float* __restrict__ p1,
                          float* __restrict__ p2, int rows) {
    int b = blockIdx.x;
    int c = threadIdx.x;
    int r0 = b * CSTAT_ROWS, r1 = min(r0 + CSTAT_ROWS, rows);
    float s1 = 0.f, s2 = 0.f;
    for (int r = r0; r < r1; r++) {
        float v = X[(size_t)r * FF + c];
        s1 += v;
        s2 += v * v;
    }
    p1[b * FF + c] = s1;
    p2[b * FF + c] = s2;
}

__global__ void k_statfin(const float* __restrict__ p1, const float* __restrict__ p2,
                          int nblk, const float* __restrict__ w,
                          const float* __restrict__ ms, float* __restrict__ shift,
                          float* __restrict__ scale, float rows_inv) {
    int c = threadIdx.x;
    float s1 = 0.f, s2 = 0.f;
    for (int i = 0; i < nblk; i++) {
        s1 += p1[i * FF + c];
        s2 += p2[i * FF + c];
    }
    float mu = s1 * rows_inv;
    float ex2 = s2 * rows_inv;
    float m = ms[c];
    float sh = m * mu;
    float var = ex2 - sh * (2.f * mu - sh);
    shift[c] = sh;
    scale[c] = w[c] / sqrtf(var + 1e-5f);
}

// graph_norm apply + leaky_relu: fp32 out, bf16 hi/lo split, fp16 gather copy
__global__ void k_normsplit(const float* __restrict__ X, const float* __restrict__ shift,
                            const float* __restrict__ scale, const float* __restrict__ beta,
                            float* __restrict__ Yf, __nv_bfloat16* __restrict__ hi,
                            __nv_bfloat16* __restrict__ lo, __half* __restrict__ y16,
                            int total4) {
    int i = blockIdx.x * blockDim.x + threadIdx.x;
    if (i >= total4) return;
    int c = (i & 127) * 4;
    float4 v = ((const float4*)X)[i];
    float4 sh = *(const float4*)(shift + c);
    float4 sc = *(const float4*)(scale + c);
    float4 be = *(const float4*)(beta + c);
    float y0 = (v.x - sh.x) * sc.x + be.x;
    float y1 = (v.y - sh.y) * sc.y + be.y;
    float y2 = (v.z - sh.z) * sc.z + be.z;
    float y3 = (v.w - sh.w) * sc.w + be.w;
    y0 = (y0 > 0.f) ? y0 : NEG_SLOPE * y0;
    y1 = (y1 > 0.f) ? y1 : NEG_SLOPE * y1;
    y2 = (y2 > 0.f) ? y2 : NEG_SLOPE * y2;
    y3 = (y3 > 0.f) ? y3 : NEG_SLOPE * y3;
    ((float4*)Yf)[i] = make_float4(y0, y1, y2, y3);
    ((__half2*)y16)[i * 2]     = __floats2half2_rn(y0, y1);
    ((__half2*)y16)[i * 2 + 1] = __floats2half2_rn(y2, y3);
    __nv_bfloat16 h0 = __float2bfloat16(y0), h1 = __float2bfloat16(y1);
    __nv_bfloat16 h2 = __float2bfloat16(y2), h3 = __float2bfloat16(y3);
    __nv_bfloat16 l0 = __float2bfloat16(y0 - __bfloat162float(h0));
    __nv_bfloat16 l1 = __float2bfloat16(y1 - __bfloat162float(h1));
    __nv_bfloat16 l2 = __float2bfloat16(y2 - __bfloat162float(h2));
    __nv_bfloat16 l3 = __float2bfloat16(y3 - __bfloat162float(h3));
    ((__nv_bfloat162*)hi)[i * 2]     = __nv_bfloat162(h0, h1);
    ((__nv_bfloat162*)hi)[i * 2 + 1] = __nv_bfloat162(h2, h3);
    ((__nv_bfloat162*)lo)[i * 2]     = __nv_bfloat162(l0, l1);
    ((__nv_bfloat162*)lo)[i * 2 + 1] = __nv_bfloat162(l2, l3);
}

__global__ void k_cls(const float* __restrict__ A, const float* __restrict__ W,
                      const float* __restrict__ b, float* __restrict__ out, int rows) {
    int gw = (blockIdx.x * blockDim.x + threadIdx.x) >> 5;
    int lane = threadIdx.x & 31;
    if (gw >= rows) return;
    const float* ar = A + (size_t)gw * HIDD;
    float s0 = 0.f, s1 = 0.f;
    for (int h = lane; h < HIDD; h += 32) {
        float v = ar[h];
        s0 += v * W[h * 2];
        s1 += v * W[h * 2 + 1];
    }
    for (int o = 16; o; o >>= 1) {
        s0 += __shfl_down_sync(0xffffffffu, s0, o);
        s1 += __shfl_down_sync(0xffffffffu, s1, o);
    }
    if (!lane) {
        out[gw * 2] = s0 + b[0];
        out[gw * 2 + 1] = s1 + b[1];
    }
}

// ---------------- host launch ----------------
extern "C" void kernel_launch(void* const* d_in, const int* in_sizes, int n_in,
                              void* d_out, int out_size) {
    const float* x    = (const float*)d_in[0];
    const int*   ei   = (const int*)d_in[1];
    const float* ea   = (const float*)d_in[2];
    const float* W1   = (const float*)d_in[3];
    const float* att1 = (const float*)d_in[4];
    const float* b1   = (const float*)d_in[5];
    const float* W2   = (const float*)d_in[6];
    const float* att2 = (const float*)d_in[7];
    const float* b2   = (const float*)d_in[8];
    const float* gn1w = (const float*)d_in[9];
    const float* gn1b = (const float*)d_in[10];
    const float* gn1ms= (const float*)d_in[11];
    const float* gn2w = (const float*)d_in[12];
    const float* gn2b = (const float*)d_in[13];
    const float* gn2ms= (const float*)d_in[14];
    const float* fc1W = (const float*)d_in[15];
    const float* fc1b = (const float*)d_in[16];
    const float* fc2W = (const float*)d_in[17];
    const float* fc2b = (const float*)d_in[18];
    const float* clsW = (const float*)d_in[19];
    const float* clsb = (const float*)d_in[20];
    float* outp = (float*)d_out;

    const int* row = ei;
    const int* col = ei + EE;

    float *xl, *h, *fc, *xn, *en, *wa, *wb, *alpha, *Dinv, *Binv;
    float *p1, *p2, *shift, *scale;
    int *degn, *dege, *rstart, *cstart, *rcur, *ccur, *rcsr, *ccsr, *bsumN, *bsumM;
    __half *elb, *h16;
    __nv_bfloat16 *Ahi, *Alo, *eahi, *ealo, *W1thi, *W1tlo, *W2thi, *W2tlo;
    __nv_bfloat16 *f1thi, *f1tlo, *f2thi, *f2tlo;
    cudaGetSymbolAddress((void**)&xl, g_xl);
    cudaGetSymbolAddress((void**)&elb, g_elb);
    cudaGetSymbolAddress((void**)&h, g_h);
    cudaGetSymbolAddress((void**)&h16, g_h16);
    cudaGetSymbolAddress((void**)&fc, g_fc);
    cudaGetSymbolAddress((void**)&xn, g_xn);
    cudaGetSymbolAddress((void**)&en, g_en);
    cudaGetSymbolAddress((void**)&wa, g_wa);
    cudaGetSymbolAddress((void**)&wb, g_wb);
    cudaGetSymbolAddress((void**)&alpha, g_alpha);
    cudaGetSymbolAddress((void**)&Dinv, g_Dinv);
    cudaGetSymbolAddress((void**)&Binv, g_Binv);
    cudaGetSymbolAddress((void**)&p1, g_p1);
    cudaGetSymbolAddress((void**)&p2, g_p2);
    cudaGetSymbolAddress((void**)&shift, g_shift);
    cudaGetSymbolAddress((void**)&scale, g_scale);
    cudaGetSymbolAddress((void**)&degn, g_degn);
    cudaGetSymbolAddress((void**)&dege, g_dege);
    cudaGetSymbolAddress((void**)&rstart, g_rstart);
    cudaGetSymbolAddress((void**)&cstart, g_cstart);
    cudaGetSymbolAddress((void**)&rcur, g_rcur);
    cudaGetSymbolAddress((void**)&ccur, g_ccur);
    cudaGetSymbolAddress((void**)&rcsr, g_rcsr);
    cudaGetSymbolAddress((void**)&ccsr, g_ccsr);
    cudaGetSymbolAddress((void**)&bsumN, g_bsumN);
    cudaGetSymbolAddress((void**)&bsumM, g_bsumM);
    cudaGetSymbolAddress((void**)&Ahi, g_Ahi);
    cudaGetSymbolAddress((void**)&Alo, g_Alo);
    cudaGetSymbolAddress((void**)&eahi, g_eahi);
    cudaGetSymbolAddress((void**)&ealo, g_ealo);
    cudaGetSymbolAddress((void**)&W1thi, g_W1thi);
    cudaGetSymbolAddress((void**)&W1tlo, g_W1tlo);
    cudaGetSymbolAddress((void**)&W2thi, g_W2thi);
    cudaGetSymbolAddress((void**)&W2tlo, g_W2tlo);
    cudaGetSymbolAddress((void**)&f1thi, g_f1thi);
    cudaGetSymbolAddress((void**)&f1tlo, g_f1tlo);
    cudaGetSymbolAddress((void**)&f2thi, g_f2thi);
    cudaGetSymbolAddress((void**)&f2tlo, g_f2tlo);

    static bool attr_set = false;
    if (!attr_set) {
        cudaFuncSetAttribute(k_wgemm<0>, cudaFuncAttributeMaxDynamicSharedMemorySize, GEMM_SMEM);
        cudaFuncSetAttribute(k_wgemm<1>, cudaFuncAttributeMaxDynamicSharedMemorySize, GEMM_SMEM);
        cudaFuncSetAttribute(k_wgemm<2>, cudaFuncAttributeMaxDynamicSharedMemorySize, GEMM_SMEM);
        attr_set = true;
    }

    const int NBN = (NN + 1023) / 1024;
    const int NBM = (MM + 1023) / 1024;

    // ---- graph structure ----
    k_zero2<<<(NN + MM + 255) / 256, 256>>>(degn, NN, dege, MM);
    k_hist<<<(EE + 255) / 256, 256>>>(row, col, degn, dege, EE);
    k_bsum<<<NBM, 256>>>(dege, bsumM, MM);
    k_bsum<<<NBN, 256>>>(degn, bsumN, NN);
    k_bscan<<<1, 32>>>(bsumM, NBM);
    k_bscan<<<1, 32>>>(bsumN, NBN);
    k_lscan<<<NBM, 256>>>(dege, bsumM, cstart, ccur, MM, NBM);
    k_lscan<<<NBN, 256>>>(degn, bsumN, rstart, rcur, NN, NBN);
    k_scatter<<<(EE + 255) / 256, 256>>>(row, col, rcur, ccur, rcsr, ccsr, EE);
    k_inv2<<<(NN + MM + 255) / 256, 256>>>(degn, Dinv, NN, dege, Binv, MM);

    // ---- weight conversions + x -> fp16 gather table ----
    k_wsplit<<<(FF * FF + 255) / 256, 256>>>(W1, W1thi, W1tlo, FF, FF);
    k_wsplit<<<(FF * FF + 255) / 256, 256>>>(W2, W2thi, W2tlo, FF, FF);
    k_wsplit<<<(FF * HIDD + 255) / 256, 256>>>(fc1W, f1thi, f1tlo, FF, HIDD);
    k_wsplit<<<(FF * HIDD + 255) / 256, 256>>>(fc2W, f2thi, f2tlo, FF, HIDD);
    k_tof16<<<(NN * (FF / 4) + 255) / 256, 256>>>(x, h16, NN * (FF / 4));

    const float rows_inv = 1.0f / (float)NN;
    dim3 gM(FF / 128, MM / 128);
    dim3 gFC(HIDD / 128, (NN + 127) / 128);

    // ==== conv1 ====
    k_rowdot2<<<(FF * 32 + 255) / 256, 256>>>(W1, att1, att1 + FF, wa, wb, FF);
    k_rowdot<<<(NN * 32 + 255) / 256, 256>>>(x, wa, xn, NN);
    k_rowdot<<<(MM * 32 + 255) / 256, 256>>>(ea, wb, en, MM);
    k_attnprop<<<MM, 256>>>(cstart, ccsr, row, xn, en, Binv, h16, alpha, eahi, ealo);
    k_wgemm<0><<<gM, 256, GEMM_SMEM>>>(eahi, ealo, W1thi, W1tlo, elb, MM, FF, FF, nullptr);
    k_prop2<<<NN, 128>>>(rstart, rcsr, col, alpha, Dinv, elb, b1, xl);
    k_colstat<<<CSTAT_BLKS, FF>>>(xl, p1, p2, NN);
    k_statfin<<<1, FF>>>(p1, p2, CSTAT_BLKS, gn1w, gn1ms, shift, scale, rows_inv);
    k_normsplit<<<(NN * (FF / 4) + 255) / 256, 256>>>(xl, shift, scale, gn1b, h, Ahi, Alo, h16, NN * (FF / 4));
    k_wgemm<1><<<gFC, 256, GEMM_SMEM>>>(Ahi, Alo, f1thi, f1tlo, fc, NN, HIDD, FF, fc1b);

    // ==== conv2 (gathers fp16(h) = h16) ====
    k_rowdot2<<<(FF * 32 + 255) / 256, 256>>>(W2, att2, att2 + FF, wa, wb, FF);
    k_rowdot<<<(NN * 32 + 255) / 256, 256>>>(h, wa, xn, NN);
    k_rowdot<<<(MM * 32 + 255) / 256, 256>>>(ea, wb, en, MM);
    k_attnprop<<<MM, 256>>>(cstart, ccsr, row, xn, en, Binv, h16, alpha, eahi, ealo);
    k_wgemm<0><<<gM, 256, GEMM_SMEM>>>(eahi, ealo, W2thi, W2tlo, elb, MM, FF, FF, nullptr);
    k_prop2<<<NN, 128>>>(rstart, rcsr, col, alpha, Dinv, elb, b2, xl);
    k_colstat<<<CSTAT_BLKS, FF>>>(xl, p1, p2, NN);
    k_statfin<<<1, FF>>>(p1, p2, CSTAT_BLKS, gn2w, gn2ms, shift, scale, rows_inv);
    k_normsplit<<<(NN * (FF / 4) + 255) / 256, 256>>>(xl, shift, scale, gn2b, h, Ahi, Alo, h16, NN * (FF / 4));
    k_wgemm<2><<<gFC, 256, GEMM_SMEM>>>(Ahi, Alo, f2thi, f2tlo, fc, NN, HIDD, FF, fc2b);

    // ---- classifier ----
    k_cls<<<(NN * 32 + 255) / 256, 256>>>(fc, clsW, clsb, outp, NN);
}

// round 10
// speedup vs baseline: 2.3754x; 1.1013x over previous
#include <cuda_runtime.h>
#include <cuda_bf16.h>
#include <cuda_fp16.h>
#include <mma.h>
#include <cstdint>
#include <math.h>

using namespace nvcuda;

#define NN 20000
#define MM 2048
#define EE 320000
#define FF 512
#define HIDD 256
#define CSTAT_ROWS 128
#define CSTAT_BLKS ((NN + CSTAT_ROWS - 1) / CSTAT_ROWS)   // 157

#define NEG_SLOPE 0.01f
#define ATT_SLOPE 0.2f

// ---------------- scratch ----------------
__device__ float g_xl[NN * FF];
__device__ __half g_elb[MM * FF];
__device__ float g_h[NN * FF];
__device__ __half g_h16[NN * FF];
__device__ float g_fc[NN * HIDD];
__device__ float g_xn[NN];
__device__ float g_en[MM];
__device__ float g_wa[FF];
__device__ float g_wb[FF];
__device__ float g_alpha[EE];
__device__ float g_Dinv[NN];
__device__ float g_Binv[MM];
__device__ int   g_degn[NN];
__device__ int   g_dege[MM];
__device__ int   g_rstart[NN + 1];
__device__ int   g_cstart[MM + 1];
__device__ int   g_rcur[NN];
__device__ int   g_ccur[MM];
__device__ int   g_rcsr[EE];
__device__ int   g_ccsr[EE];
__device__ int   g_bsumN[32];
__device__ int   g_bsumM[8];
__device__ float g_p1[CSTAT_BLKS * FF];
__device__ float g_p2[CSTAT_BLKS * FF];
__device__ float g_shift[FF];
__device__ float g_scale[FF];
__device__ __nv_bfloat16 g_Ahi[NN * FF];
__device__ __nv_bfloat16 g_Alo[NN * FF];
__device__ __nv_bfloat16 g_eahi[MM * FF];
__device__ __nv_bfloat16 g_ealo[MM * FF];
__device__ __nv_bfloat16 g_W1thi[FF * FF];
__device__ __nv_bfloat16 g_W1tlo[FF * FF];
__device__ __nv_bfloat16 g_W2thi[FF * FF];
__device__ __nv_bfloat16 g_W2tlo[FF * FF];
__device__ __nv_bfloat16 g_f1thi[HIDD * FF];
__device__ __nv_bfloat16 g_f1tlo[HIDD * FF];
__device__ __nv_bfloat16 g_f2thi[HIDD * FF];
__device__ __nv_bfloat16 g_f2tlo[HIDD * FF];

// ---------------- cp.async helpers ----------------
__device__ __forceinline__ uint32_t smem_u32(const void* p) {
    uint32_t a;
    asm("{ .reg .u64 t; cvta.to.shared.u64 t, %1; cvt.u32.u64 %0, t; }" : "=r"(a) : "l"(p));
    return a;
}
__device__ __forceinline__ void cp16(uint32_t dst, const void* src) {
    asm volatile("cp.async.ca.shared.global [%0], [%1], 16;" :: "r"(dst), "l"(src));
}
#define CP_COMMIT() asm volatile("cp.async.commit_group;" ::: "memory")
#define CP_WAIT1()  asm volatile("cp.async.wait_group 1;" ::: "memory")
#define CP_WAIT0()  asm volatile("cp.async.wait_group 0;" ::: "memory")

#define APAD 72
#define SM_A0 0
#define SM_B0 18432
#define SM_A1 36864
#define SM_B1 55296
#define SM_STG 73728
#define GEMM_SMEM 81920

// ---------------- cp.async double-buffered wmma split-bf16 GEMM ----------------
// MODE 0: store fp16; MODE 1: store lrelu(AB+bias) fp32; MODE 2: C += lrelu(AB+bias) fp32
template <int MODE>
__global__ void __launch_bounds__(256) k_wgemm(
    const __nv_bfloat16* __restrict__ Ahi, const __nv_bfloat16* __restrict__ Alo,
    const __nv_bfloat16* __restrict__ Bthi, const __nv_bfloat16* __restrict__ Btlo,
    void* __restrict__ Cv, int Mr, int Nc, int Kd, const float* __restrict__ bias) {
    extern __shared__ __align__(16) char dsm[];
    const uint32_t sb = smem_u32(dsm);

    const int tid = threadIdx.x;
    const int wid = tid >> 5;
    const int lane = tid & 31;
    const int wm = wid >> 2;
    const int wn = wid & 3;
    const int bm = blockIdx.y * 128;
    const int bn = blockIdx.x * 128;

    const int CPS = Kd >> 6;
    const int NCH = 3 * CPS;

    const int lr = tid >> 1;
    const int lc = (tid & 1) * 4;
    const int gaRow = min(bm + lr, Mr - 1);
    const int gbRow = bn + lr;

    wmma::fragment<wmma::accumulator, 16, 16, 16, float> acc[4][2];
#pragma unroll
    for (int i = 0; i < 4; i++)
#pragma unroll
        for (int j = 0; j < 2; j++) wmma::fill_fragment(acc[i][j], 0.0f);

    auto issue = [&](int c) {
        int seg = c / CPS;
        int j = c - seg * CPS;
        const __nv_bfloat16* A = (seg == 1) ? Alo : Ahi;
        const __nv_bfloat16* B = (seg == 2) ? Btlo : Bthi;
        int koff = j << 6;
        int buf = c & 1;
        uint32_t abase = sb + (buf ? SM_A1 : SM_A0) + lr * 144;
        uint32_t bbase = sb + (buf ? SM_B1 : SM_B0) + lr * 144;
        const char* ap = (const char*)(A + (size_t)gaRow * Kd + koff);
        const char* bp = (const char*)(B + (size_t)gbRow * Kd + koff);
#pragma unroll
        for (int u = 0; u < 4; u++) {
            cp16(abase + (lc + u) * 16, ap + (lc + u) * 16);
            cp16(bbase + (lc + u) * 16, bp + (lc + u) * 16);
        }
        CP_COMMIT();
    };

    issue(0);
    for (int c = 0; c < NCH; c++) {
        if (c + 1 < NCH) { issue(c + 1); CP_WAIT1(); }
        else             { CP_WAIT0(); }
        __syncthreads();
        const int buf = c & 1;
        const __nv_bfloat16* As = (const __nv_bfloat16*)(dsm + (buf ? SM_A1 : SM_A0));
        const __nv_bfloat16* Bs = (const __nv_bfloat16*)(dsm + (buf ? SM_B1 : SM_B0));
#pragma unroll
        for (int kt = 0; kt < 4; kt++) {
            wmma::fragment<wmma::matrix_a, 16, 16, 16, __nv_bfloat16, wmma::row_major> af[4];
            wmma::fragment<wmma::matrix_b, 16, 16, 16, __nv_bfloat16, wmma::col_major> bf[2];
#pragma unroll
            for (int n = 0; n < 2; n++)
                wmma::load_matrix_sync(bf[n], Bs + (wn * 32 + n * 16) * APAD + kt * 16, APAD);
#pragma unroll
            for (int m = 0; m < 4; m++)
                wmma::load_matrix_sync(af[m], As + (wm * 64 + m * 16) * APAD + kt * 16, APAD);
#pragma unroll
            for (int m = 0; m < 4; m++)
#pragma unroll
                for (int n = 0; n < 2; n++)
                    wmma::mma_sync(acc[m][n], af[m], bf[n], acc[m][n]);
        }
        __syncthreads();
    }

    float* stg = (float*)(dsm + SM_STG) + wid * 256;
    const int srow = lane >> 1;
    const int scol = (lane & 1) * 8;
#pragma unroll
    for (int m = 0; m < 4; m++) {
#pragma unroll
        for (int n = 0; n < 2; n++) {
            wmma::store_matrix_sync(stg, acc[m][n], 16, wmma::mem_row_major);
            __syncwarp();
            int grow = bm + wm * 64 + m * 16 + srow;
            int gcol = bn + wn * 32 + n * 16 + scol;
            if (grow < Mr) {
                const float* sp = stg + srow * 16 + scol;
                if (MODE == 0) {
                    __half* crow = (__half*)Cv + (size_t)grow * Nc + gcol;
#pragma unroll
                    for (int q = 0; q < 2; q++) {
                        float4 v = *(const float4*)(sp + q * 4);
                        ((__half2*)(crow + q * 4))[0] = __floats2half2_rn(v.x, v.y);
                        ((__half2*)(crow + q * 4))[1] = __floats2half2_rn(v.z, v.w);
                    }
                } else {
                    float* crow = (float*)Cv + (size_t)grow * Nc + gcol;
#pragma unroll
                    for (int q = 0; q < 2; q++) {
                        float4 v = *(const float4*)(sp + q * 4);
                        float4 bb = *(const float4*)(bias + gcol + q * 4);
                        v.x += bb.x; v.y += bb.y; v.z += bb.z; v.w += bb.w;
                        v.x = (v.x > 0.f) ? v.x : NEG_SLOPE * v.x;
                        v.y = (v.y > 0.f) ? v.y : NEG_SLOPE * v.y;
                        v.z = (v.z > 0.f) ? v.z : NEG_SLOPE * v.z;
                        v.w = (v.w > 0.f) ? v.w : NEG_SLOPE * v.w;
                        if (MODE == 2) {
                            float4 o = *(const float4*)(crow + q * 4);
                            v.x += o.x; v.y += o.y; v.z += o.z; v.w += o.w;
                        }
                        *(float4*)(crow + q * 4) = v;
                    }
                }
            }
            __syncwarp();
        }
    }
}

// ---------------- conversions ----------------
__global__ void k_wsplit(const float* __restrict__ W, __nv_bfloat16* __restrict__ thi,
                         __nv_bfloat16* __restrict__ tlo, int K, int N) {
    int i = blockIdx.x * blockDim.x + threadIdx.x;
    if (i >= K * N) return;
    int n = i / K, k = i - n * K;
    float v = W[(size_t)k * N + n];
    __nv_bfloat16 h = __float2bfloat16(v);
    thi[i] = h;
    tlo[i] = __float2bfloat16(v - __bfloat162float(h));
}

__global__ void k_tof16(const float* __restrict__ X, __half* __restrict__ Y, int total4) {
    int i = blockIdx.x * blockDim.x + threadIdx.x;
    if (i >= total4) return;
    float4 v = ((const float4*)X)[i];
    ((__half2*)Y)[i * 2]     = __floats2half2_rn(v.x, v.y);
    ((__half2*)Y)[i * 2 + 1] = __floats2half2_rn(v.z, v.w);
}

// ---------------- structure kernels ----------------
__global__ void k_zero2(int* a, int na, int* b, int nb) {
    int i = blockIdx.x * blockDim.x + threadIdx.x;
    if (i < na) a[i] = 0;
    else if (i < na + nb) b[i - na] = 0;
}

__global__ void k_hist(const int* __restrict__ row, const int* __restrict__ col,
                       int* degn, int* dege, int E) {
    int i = blockIdx.x * blockDim.x + threadIdx.x;
    if (i < E) {
        atomicAdd(&degn[row[i]], 1);
        atomicAdd(&dege[col[i]], 1);
    }
}

__global__ void k_bsum(const int* __restrict__ cnt, int* __restrict__ bsum, int n) {
    int b = blockIdx.x, t = threadIdx.x;
    int base = b * 1024;
    int s = 0;
#pragma unroll
    for (int u = 0; u < 4; u++) {
        int i = base + t + u * 256;
        if (i < n) s += cnt[i];
    }
    __shared__ int red[8];
    for (int o = 16; o; o >>= 1) s += __shfl_down_sync(0xffffffffu, s, o);
    if ((t & 31) == 0) red[t >> 5] = s;
    __syncthreads();
    if (t == 0) {
        int v = 0;
#pragma unroll
        for (int w = 0; w < 8; w++) v += red[w];
        bsum[b] = v;
    }
}

__global__ void k_bscan(int* bsum, int nb) {
    if (threadIdx.x == 0) {
        int run = 0;
        for (int i = 0; i < nb; i++) { int v = bsum[i]; bsum[i] = run; run += v; }
        bsum[nb] = run;
    }
}

__global__ void k_lscan(const int* __restrict__ cnt, const int* __restrict__ bsum,
                        int* __restrict__ start, int* __restrict__ cur, int n, int nb) {
    int b = blockIdx.x, t = threadIdx.x;
    __shared__ int sh[256];
    int base = b * 1024;
    int v[4];
    int s = 0;
#pragma unroll
    for (int u = 0; u < 4; u++) {
        int i = base + t * 4 + u;
        v[u] = (i < n) ? cnt[i] : 0;
        s += v[u];
    }
    sh[t] = s;
    __syncthreads();
    for (int o = 1; o < 256; o <<= 1) {
        int a = (t >= o) ? sh[t - o] : 0;
        __syncthreads();
        sh[t] += a;
        __syncthreads();
    }
    int run = bsum[b] + ((t == 0) ? 0 : sh[t - 1]);
#pragma unroll
    for (int u = 0; u < 4; u++) {
        int i = base + t * 4 + u;
        if (i < n) { start[i] = run; cur[i] = run; run += v[u]; }
    }
    if (b == 0 && t == 0) start[n] = bsum[nb];
}

__global__ void k_scatter(const int* __restrict__ row, const int* __restrict__ col,
                          int* rcur, int* ccur, int* __restrict__ rcsr,
                          int* __restrict__ ccsr, int E) {
    int i = blockIdx.x * blockDim.x + threadIdx.x;
    if (i < E) {
        int pr = atomicAdd(&rcur[row[i]], 1);
        rcsr[pr] = i;
        int pc = atomicAdd(&ccur[col[i]], 1);
        ccsr[pc] = i;
    }
}

__global__ void k_inv2(const int* __restrict__ da, float* __restrict__ ia, int na,
                       const int* __restrict__ db, float* __restrict__ ib, int nb) {
    int i = blockIdx.x * blockDim.x + threadIdx.x;
    if (i < na) {
        int d = da[i];
        ia[i] = (d > 0) ? (1.0f / (float)d) : 0.0f;
    } else if (i < na + nb) {
        int d = db[i - na];
        ib[i - na] = (d > 0) ? (1.0f / (float)d) : 0.0f;
    }
}

// ---------------- row dots ----------------
__global__ void k_rowdot(const float* __restrict__ X, const float* __restrict__ v,
                         float* __restrict__ out, int rows) {
    int gw = (blockIdx.x * blockDim.x + threadIdx.x) >> 5;
    int lane = threadIdx.x & 31;
    if (gw >= rows) return;
    const float4* xr = (const float4*)(X + (size_t)gw * FF);
    const float4* vv = (const float4*)v;
    float s = 0.f;
#pragma unroll
    for (int j = 0; j < 4; j++) {
        float4 a = xr[lane + 32 * j];
        float4 b = vv[lane + 32 * j];
        s += a.x * b.x + a.y * b.y + a.z * b.z + a.w * b.w;
    }
    for (int o = 16; o; o >>= 1) s += __shfl_down_sync(0xffffffffu, s, o);
    if (!lane) out[gw] = s;
}

__global__ void k_rowdot2(const float* __restrict__ X, const float* __restrict__ v1,
                          const float* __restrict__ v2, float* __restrict__ o1,
                          float* __restrict__ o2, int rows) {
    int gw = (blockIdx.x * blockDim.x + threadIdx.x) >> 5;
    int lane = threadIdx.x & 31;
    if (gw >= rows) return;
    const float4* xr = (const float4*)(X + (size_t)gw * FF);
    const float4* va = (const float4*)v1;
    const float4* vb = (const float4*)v2;
    float s1 = 0.f, s2 = 0.f;
#pragma unroll
    for (int j = 0; j < 4; j++) {
        float4 a = xr[lane + 32 * j];
        float4 b = va[lane + 32 * j];
        float4 c = vb[lane + 32 * j];
        s1 += a.x * b.x + a.y * b.y + a.z * b.z + a.w * b.w;
        s2 += a.x * c.x + a.y * c.y + a.z * c.z + a.w * c.w;
    }
    for (int o = 16; o; o >>= 1) {
        s1 += __shfl_down_sync(0xffffffffu, s1, o);
        s2 += __shfl_down_sync(0xffffffffu, s2, o);
    }
    if (!lane) { o1[gw] = s1; o2[gw] = s2; }
}

// ---------------- fused attention softmax + propagate-1 (fp16 gather) ----------------
__global__ void __launch_bounds__(256) k_attnprop(
    const int* __restrict__ cstart, const int* __restrict__ ccsr,
    const int* __restrict__ row, const float* __restrict__ xn,
    const float* __restrict__ en, const float* __restrict__ Binv,
    const __half* __restrict__ X, float* __restrict__ alpha,
    __nv_bfloat16* __restrict__ efhi, __nv_bfloat16* __restrict__ eflo) {
    int m = blockIdx.x;
    int s = cstart[m], e = cstart[m + 1];
    int tid = threadIdx.x;
    __shared__ float red[256];
    __shared__ int   shr[256];
    __shared__ float shc[256];

    float enm = en[m];
    float mx = -3.0e38f;
    for (int i = s + tid; i < e; i += 256) {
        int ed = ccsr[i];
        float p = xn[row[ed]] + enm;
        p = (p > 0.f) ? p : ATT_SLOPE * p;
        alpha[ed] = p;
        mx = fmaxf(mx, p);
    }
    red[tid] = mx;
    __syncthreads();
    for (int o = 128; o; o >>= 1) {
        if (tid < o) red[tid] = fmaxf(red[tid], red[tid + o]);
        __syncthreads();
    }
    float amax = red[0];
    if (!(amax > -1e37f)) amax = 0.f;
    __syncthreads();
    float sm = 0.f;
    for (int i = s + tid; i < e; i += 256) {
        int ed = ccsr[i];
        float ex = expf(alpha[ed] - amax);
        alpha[ed] = ex;
        sm += ex;
    }
    red[tid] = sm;
    __syncthreads();
    for (int o = 128; o; o >>= 1) {
        if (tid < o) red[tid] += red[tid + o];
        __syncthreads();
    }
    float inv = 1.f / fmaxf(red[0], 1e-16f);
    float bi = Binv[m];
    float ax = 0.f, ay = 0.f;
    const __half2* base = (const __half2*)X + tid;
    for (int b0 = s; b0 < e; b0 += 256) {
        int cnt = min(256, e - b0);
        __syncthreads();
        if (tid < cnt) {
            int ed = ccsr[b0 + tid];
            float a = alpha[ed] * inv;
            alpha[ed] = a;
            shr[tid] = row[ed];
            shc[tid] = a * bi;
        }
        __syncthreads();
        int j = 0;
        for (; j + 4 <= cnt; j += 4) {
            int r0 = shr[j], r1 = shr[j + 1], r2 = shr[j + 2], r3 = shr[j + 3];
            float c0 = shc[j], c1 = shc[j + 1], c2 = shc[j + 2], c3 = shc[j + 3];
            float2 v0 = __half22float2(base[(size_t)r0 * (FF / 2)]);
            float2 v1 = __half22float2(base[(size_t)r1 * (FF / 2)]);
            float2 v2 = __half22float2(base[(size_t)r2 * (FF / 2)]);
            float2 v3 = __half22float2(base[(size_t)r3 * (FF / 2)]);
            ax += c0 * v0.x + c1 * v1.x + c2 * v2.x + c3 * v3.x;
            ay += c0 * v0.y + c1 * v1.y + c2 * v2.y + c3 * v3.y;
        }
        for (; j < cnt; j++) {
            float2 v = __half22float2(base[(size_t)shr[j] * (FF / 2)]);
            float cf = shc[j];
            ax += cf * v.x;
            ay += cf * v.y;
        }
    }
    __nv_bfloat16 hx = __float2bfloat16(ax), hy = __float2bfloat16(ay);
    __nv_bfloat16 lx = __float2bfloat16(ax - __bfloat162float(hx));
    __nv_bfloat16 ly = __float2bfloat16(ay - __bfloat162float(hy));
    ((__nv_bfloat162*)(efhi + (size_t)m * FF))[tid] = __nv_bfloat162(hx, hy);
    ((__nv_bfloat162*)(eflo + (size_t)m * FF))[tid] = __nv_bfloat162(lx, ly);
}

// ---------------- propagate-2 (fp16 gather, unrolled x4) ----------------
__global__ void k_prop2(const int* __restrict__ rstart, const int* __restrict__ rcsr,
                        const int* __restrict__ col, const float* __restrict__ alpha,
                        const float* __restrict__ Dinv, const __half* __restrict__ ef,
                        const float* __restrict__ bias, float* __restrict__ out) {
    int n = blockIdx.x;
    int s = rstart[n], e = rstart[n + 1];
    int tid = threadIdx.x;
    float a0 = 0.f, a1 = 0.f, a2 = 0.f, a3 = 0.f;
    const uint2* base = (const uint2*)ef + tid;
    int i = s;
    for (; i + 4 <= e; i += 4) {
        int e0 = rcsr[i], e1 = rcsr[i + 1], e2 = rcsr[i + 2], e3 = rcsr[i + 3];
        float c0 = alpha[e0], c1 = alpha[e1], c2 = alpha[e2], c3 = alpha[e3];
        uint2 u0 = base[(size_t)col[e0] * (FF / 4)];
        uint2 u1 = base[(size_t)col[e1] * (FF / 4)];
        uint2 u2 = base[(size_t)col[e2] * (FF / 4)];
        uint2 u3 = base[(size_t)col[e3] * (FF / 4)];
        float2 p0a = __half22float2(*(const __half2*)&u0.x);
        float2 p0b = __half22float2(*(const __half2*)&u0.y);
        float2 p1a = __half22float2(*(const __half2*)&u1.x);
        float2 p1b = __half22float2(*(const __half2*)&u1.y);
        float2 p2a = __half22float2(*(const __half2*)&u2.x);
        float2 p2b = __half22float2(*(const __half2*)&u2.y);
        float2 p3a = __half22float2(*(const __half2*)&u3.x);
        float2 p3b = __half22float2(*(const __half2*)&u3.y);
        a0 += c0 * p0a.x + c1 * p1a.x + c2 * p2a.x + c3 * p3a.x;
        a1 += c0 * p0a.y + c1 * p1a.y + c2 * p2a.y + c3 * p3a.y;
        a2 += c0 * p0b.x + c1 * p1b.x + c2 * p2b.x + c3 * p3b.x;
        a3 += c0 * p0b.y + c1 * p1b.y + c2 * p2b.y + c3 * p3b.y;
    }
    for (; i < e; i++) {
        int ed = rcsr[i];
        float cf = alpha[ed];
        uint2 u = base[(size_t)col[ed] * (FF / 4)];
        float2 pa = __half22float2(*(const __half2*)&u.x);
        float2 pb = __half22float2(*(const __half2*)&u.y);
        a0 += cf * pa.x; a1 += cf * pa.y; a2 += cf * pb.x; a3 += cf * pb.y;
    }
    float d = Dinv[n];
    float4 b = *(const float4*)(bias + 4 * tid);
    float4 o;
    o.x = a0 * d + b.x; o.y = a1 * d + b.y; o.z = a2 * d + b.z; o.w = a3 * d + b.w;
    *(float4*)(out + (size_t)n * FF + 4 * tid) = o;
}

// ---------------- graph norm ----------------
__global__ void k_colstat(const float* __restrict__ X, float* __restrict__ p1,
                          float* __restrict__ p2, int rows) {
    int b = blockIdx.x;
    int c = threadIdx.x;
    int r0 = b * CSTAT_ROWS, r1 = min(r0 + CSTAT_ROWS, rows);
    float s1 = 0.f, s2 = 0.f;
    for (int r = r0; r < r1; r++) {
        float v = X[(size_t)r * FF + c];
        s1 += v;
        s2 += v * v;
    }
    p1[b * FF + c] = s1;
    p2[b * FF + c] = s2;
}

__global__ void k_statfin(const float* __restrict__ p1, const float* __restrict__ p2,
                          int nblk, const float* __restrict__ w,
                          const float* __restrict__ ms, float* __restrict__ shift,
                          float* __restrict__ scale, float rows_inv) {
    int c = threadIdx.x;
    float s1 = 0.f, s2 = 0.f;
    for (int i = 0; i < nblk; i++) {
        s1 += p1[i * FF + c];
        s2 += p2[i * FF + c];
    }
    float mu = s1 * rows_inv;
    float ex2 = s2 * rows_inv;
    float m = ms[c];
    float sh = m * mu;
    float var = ex2 - sh * (2.f * mu - sh);
    shift[c] = sh;
    scale[c] = w[c] / sqrtf(var + 1e-5f);
}

__global__ void k_normsplit(const float* __restrict__ X, const float* __restrict__ shift,
                            const float* __restrict__ scale, const float* __restrict__ beta,
                            float* __restrict__ Yf, __nv_bfloat16* __restrict__ hi,
                            __nv_bfloat16* __restrict__ lo, __half* __restrict__ y16,
                            int total4) {
    int i = blockIdx.x * blockDim.x + threadIdx.x;
    if (i >= total4) return;
    int c = (i & 127) * 4;
    float4 v = ((const float4*)X)[i];
    float4 sh = *(const float4*)(shift + c);
    float4 sc = *(const float4*)(scale + c);
    float4 be = *(const float4*)(beta + c);
    float y0 = (v.x - sh.x) * sc.x + be.x;
    float y1 = (v.y - sh.y) * sc.y + be.y;
    float y2 = (v.z - sh.z) * sc.z + be.z;
    float y3 = (v.w - sh.w) * sc.w + be.w;
    y0 = (y0 > 0.f) ? y0 : NEG_SLOPE * y0;
    y1 = (y1 > 0.f) ? y1 : NEG_SLOPE * y1;
    y2 = (y2 > 0.f) ? y2 : NEG_SLOPE * y2;
    y3 = (y3 > 0.f) ? y3 : NEG_SLOPE * y3;
    ((float4*)Yf)[i] = make_float4(y0, y1, y2, y3);
    ((__half2*)y16)[i * 2]     = __floats2half2_rn(y0, y1);
    ((__half2*)y16)[i * 2 + 1] = __floats2half2_rn(y2, y3);
    __nv_bfloat16 h0 = __float2bfloat16(y0), h1 = __float2bfloat16(y1);
    __nv_bfloat16 h2 = __float2bfloat16(y2), h3 = __float2bfloat16(y3);
    __nv_bfloat16 l0 = __float2bfloat16(y0 - __bfloat162float(h0));
    __nv_bfloat16 l1 = __float2bfloat16(y1 - __bfloat162float(h1));
    __nv_bfloat16 l2 = __float2bfloat16(y2 - __bfloat162float(h2));
    __nv_bfloat16 l3 = __float2bfloat16(y3 - __bfloat162float(h3));
    ((__nv_bfloat162*)hi)[i * 2]     = __nv_bfloat162(h0, h1);
    ((__nv_bfloat162*)hi)[i * 2 + 1] = __nv_bfloat162(h2, h3);
    ((__nv_bfloat162*)lo)[i * 2]     = __nv_bfloat162(l0, l1);
    ((__nv_bfloat162*)lo)[i * 2 + 1] = __nv_bfloat162(l2, l3);
}

__global__ void k_cls(const float* __restrict__ A, const float* __restrict__ W,
                      const float* __restrict__ b, float* __restrict__ out, int rows) {
    int gw = (blockIdx.x * blockDim.x + threadIdx.x) >> 5;
    int lane = threadIdx.x & 31;
    if (gw >= rows) return;
    const float* ar = A + (size_t)gw * HIDD;
    float s0 = 0.f, s1 = 0.f;
    for (int h = lane; h < HIDD; h += 32) {
        float v = ar[h];
        s0 += v * W[h * 2];
        s1 += v * W[h * 2 + 1];
    }
    for (int o = 16; o; o >>= 1) {
        s0 += __shfl_down_sync(0xffffffffu, s0, o);
        s1 += __shfl_down_sync(0xffffffffu, s1, o);
    }
    if (!lane) {
        out[gw * 2] = s0 + b[0];
        out[gw * 2 + 1] = s1 + b[1];
    }
}

// ---------------- host launch ----------------
extern "C" void kernel_launch(void* const* d_in, const int* in_sizes, int n_in,
                              void* d_out, int out_size) {
    const float* x    = (const float*)d_in[0];
    const int*   ei   = (const int*)d_in[1];
    const float* ea   = (const float*)d_in[2];
    const float* W1   = (const float*)d_in[3];
    const float* att1 = (const float*)d_in[4];
    const float* b1   = (const float*)d_in[5];
    const float* W2   = (const float*)d_in[6];
    const float* att2 = (const float*)d_in[7];
    const float* b2   = (const float*)d_in[8];
    const float* gn1w = (const float*)d_in[9];
    const float* gn1b = (const float*)d_in[10];
    const float* gn1ms= (const float*)d_in[11];
    const float* gn2w = (const float*)d_in[12];
    const float* gn2b = (const float*)d_in[13];
    const float* gn2ms= (const float*)d_in[14];
    const float* fc1W = (const float*)d_in[15];
    const float* fc1b = (const float*)d_in[16];
    const float* fc2W = (const float*)d_in[17];
    const float* fc2b = (const float*)d_in[18];
    const float* clsW = (const float*)d_in[19];
    const float* clsb = (const float*)d_in[20];
    float* outp = (float*)d_out;

    const int* row = ei;
    const int* col = ei + EE;

    float *xl, *h, *fc, *xn, *en, *wa, *wb, *alpha, *Dinv, *Binv;
    float *p1, *p2, *shift, *scale;
    int *degn, *dege, *rstart, *cstart, *rcur, *ccur, *rcsr, *ccsr, *bsumN, *bsumM;
    __half *elb, *h16;
    __nv_bfloat16 *Ahi, *Alo, *eahi, *ealo, *W1thi, *W1tlo, *W2thi, *W2tlo;
    __nv_bfloat16 *f1thi, *f1tlo, *f2thi, *f2tlo;
    cudaGetSymbolAddress((void**)&xl, g_xl);
    cudaGetSymbolAddress((void**)&elb, g_elb);
    cudaGetSymbolAddress((void**)&h, g_h);
    cudaGetSymbolAddress((void**)&h16, g_h16);
    cudaGetSymbolAddress((void**)&fc, g_fc);
    cudaGetSymbolAddress((void**)&xn, g_xn);
    cudaGetSymbolAddress((void**)&en, g_en);
    cudaGetSymbolAddress((void**)&wa, g_wa);
    cudaGetSymbolAddress((void**)&wb, g_wb);
    cudaGetSymbolAddress((void**)&alpha, g_alpha);
    cudaGetSymbolAddress((void**)&Dinv, g_Dinv);
    cudaGetSymbolAddress((void**)&Binv, g_Binv);
    cudaGetSymbolAddress((void**)&p1, g_p1);
    cudaGetSymbolAddress((void**)&p2, g_p2);
    cudaGetSymbolAddress((void**)&shift, g_shift);
    cudaGetSymbolAddress((void**)&scale, g_scale);
    cudaGetSymbolAddress((void**)&degn, g_degn);
    cudaGetSymbolAddress((void**)&dege, g_dege);
    cudaGetSymbolAddress((void**)&rstart, g_rstart);
    cudaGetSymbolAddress((void**)&cstart, g_cstart);
    cudaGetSymbolAddress((void**)&rcur, g_rcur);
    cudaGetSymbolAddress((void**)&ccur, g_ccur);
    cudaGetSymbolAddress((void**)&rcsr, g_rcsr);
    cudaGetSymbolAddress((void**)&ccsr, g_ccsr);
    cudaGetSymbolAddress((void**)&bsumN, g_bsumN);
    cudaGetSymbolAddress((void**)&bsumM, g_bsumM);
    cudaGetSymbolAddress((void**)&Ahi, g_Ahi);
    cudaGetSymbolAddress((void**)&Alo, g_Alo);
    cudaGetSymbolAddress((void**)&eahi, g_eahi);
    cudaGetSymbolAddress((void**)&ealo, g_ealo);
    cudaGetSymbolAddress((void**)&W1thi, g_W1thi);
    cudaGetSymbolAddress((void**)&W1tlo, g_W1tlo);
    cudaGetSymbolAddress((void**)&W2thi, g_W2thi);
    cudaGetSymbolAddress((void**)&W2tlo, g_W2tlo);
    cudaGetSymbolAddress((void**)&f1thi, g_f1thi);
    cudaGetSymbolAddress((void**)&f1tlo, g_f1tlo);
    cudaGetSymbolAddress((void**)&f2thi, g_f2thi);
    cudaGetSymbolAddress((void**)&f2tlo, g_f2tlo);

    static cudaStream_t s1 = nullptr;
    static cudaEvent_t evFork = nullptr, evJoin1 = nullptr, evFork2 = nullptr, evJoin2 = nullptr;
    static bool init_done = false;
    if (!init_done) {
        cudaFuncSetAttribute(k_wgemm<0>, cudaFuncAttributeMaxDynamicSharedMemorySize, GEMM_SMEM);
        cudaFuncSetAttribute(k_wgemm<1>, cudaFuncAttributeMaxDynamicSharedMemorySize, GEMM_SMEM);
        cudaFuncSetAttribute(k_wgemm<2>, cudaFuncAttributeMaxDynamicSharedMemorySize, GEMM_SMEM);
        cudaStreamCreateWithFlags(&s1, cudaStreamNonBlocking);
        cudaEventCreateWithFlags(&evFork, cudaEventDisableTiming);
        cudaEventCreateWithFlags(&evJoin1, cudaEventDisableTiming);
        cudaEventCreateWithFlags(&evFork2, cudaEventDisableTiming);
        cudaEventCreateWithFlags(&evJoin2, cudaEventDisableTiming);
        init_done = true;
    }

    const int NBN = (NN + 1023) / 1024;
    const int NBM = (MM + 1023) / 1024;
    const float rows_inv = 1.0f / (float)NN;
    dim3 gM(FF / 128, MM / 128);
    dim3 gFC(HIDD / 128, (NN + 127) / 128);

    // ---- fork: s1 joins capture ----
    cudaEventRecord(evFork, 0);
    cudaStreamWaitEvent(s1, evFork, 0);

    // ---- s0: graph structure chain ----
    k_zero2<<<(NN + MM + 255) / 256, 256>>>(degn, NN, dege, MM);
    k_hist<<<(EE + 255) / 256, 256>>>(row, col, degn, dege, EE);
    k_bsum<<<NBM, 256>>>(dege, bsumM, MM);
    k_bsum<<<NBN, 256>>>(degn, bsumN, NN);
    k_bscan<<<1, 32>>>(bsumM, NBM);
    k_bscan<<<1, 32>>>(bsumN, NBN);
    k_lscan<<<NBM, 256>>>(dege, bsumM, cstart, ccur, MM, NBM);
    k_lscan<<<NBN, 256>>>(degn, bsumN, rstart, rcur, NN, NBN);
    k_scatter<<<(EE + 255) / 256, 256>>>(row, col, rcur, ccur, rcsr, ccsr, EE);
    k_inv2<<<(NN + MM + 255) / 256, 256>>>(degn, Dinv, NN, dege, Binv, MM);

    // ---- s1 (parallel): conversions + conv1 pre-dots ----
    k_wsplit<<<(FF * FF + 255) / 256, 256, 0, s1>>>(W1, W1thi, W1tlo, FF, FF);
    k_wsplit<<<(FF * FF + 255) / 256, 256, 0, s1>>>(W2, W2thi, W2tlo, FF, FF);
    k_wsplit<<<(FF * HIDD + 255) / 256, 256, 0, s1>>>(fc1W, f1thi, f1tlo, FF, HIDD);
    k_wsplit<<<(FF * HIDD + 255) / 256, 256, 0, s1>>>(fc2W, f2thi, f2tlo, FF, HIDD);
    k_tof16<<<(NN * (FF / 4) + 255) / 256, 256, 0, s1>>>(x, h16, NN * (FF / 4));
    k_rowdot2<<<(FF * 32 + 255) / 256, 256, 0, s1>>>(W1, att1, att1 + FF, wa, wb, FF);
    k_rowdot<<<(NN * 32 + 255) / 256, 256, 0, s1>>>(x, wa, xn, NN);
    k_rowdot<<<(MM * 32 + 255) / 256, 256, 0, s1>>>(ea, wb, en, MM);
    cudaEventRecord(evJoin1, s1);
    cudaStreamWaitEvent(0, evJoin1, 0);

    // ==== conv1 (s0) ====
    k_attnprop<<<MM, 256>>>(cstart, ccsr, row, xn, en, Binv, h16, alpha, eahi, ealo);
    k_wgemm<0><<<gM, 256, GEMM_SMEM>>>(eahi, ealo, W1thi, W1tlo, elb, MM, FF, FF, nullptr);
    k_prop2<<<NN, 128>>>(rstart, rcsr, col, alpha, Dinv, elb, b1, xl);
    k_colstat<<<CSTAT_BLKS, FF>>>(xl, p1, p2, NN);
    k_statfin<<<1, FF>>>(p1, p2, CSTAT_BLKS, gn1w, gn1ms, shift, scale, rows_inv);
    k_normsplit<<<(NN * (FF / 4) + 255) / 256, 256>>>(xl, shift, scale, gn1b, h, Ahi, Alo, h16, NN * (FF / 4));

    // ---- fork 2: fc1 GEMM on s1, conv2 front on s0 ----
    cudaEventRecord(evFork2, 0);
    cudaStreamWaitEvent(s1, evFork2, 0);
    k_wgemm<1><<<gFC, 256, GEMM_SMEM, s1>>>(Ahi, Alo, f1thi, f1tlo, fc, NN, HIDD, FF, fc1b);

    // ==== conv2 front (s0) ====
    k_rowdot2<<<(FF * 32 + 255) / 256, 256>>>(W2, att2, att2 + FF, wa, wb, FF);
    k_rowdot<<<(NN * 32 + 255) / 256, 256>>>(h, wa, xn, NN);
    k_rowdot<<<(MM * 32 + 255) / 256, 256>>>(ea, wb, en, MM);
    k_attnprop<<<MM, 256>>>(cstart, ccsr, row, xn, en, Binv, h16, alpha, eahi, ealo);
    k_wgemm<0><<<gM, 256, GEMM_SMEM>>>(eahi, ealo, W2thi, W2tlo, elb, MM, FF, FF, nullptr);
    k_prop2<<<NN, 128>>>(rstart, rcsr, col, alpha, Dinv, elb, b2, xl);
    k_colstat<<<CSTAT_BLKS, FF>>>(xl, p1, p2, NN);
    k_statfin<<<1, FF>>>(p1, p2, CSTAT_BLKS, gn2w, gn2ms, shift, scale, rows_inv);

    // join: fc1 must finish before normsplit2 overwrites Ahi/Alo (and before fc2 reads fc)
    cudaEventRecord(evJoin2, s1);
    cudaStreamWaitEvent(0, evJoin2, 0);
    k_normsplit<<<(NN * (FF / 4) + 255) / 256, 256>>>(xl, shift, scale, gn2b, h, Ahi, Alo, h16, NN * (FF / 4));
    k_wgemm<2><<<gFC, 256, GEMM_SMEM>>>(Ahi, Alo, f2thi, f2tlo, fc, NN, HIDD, FF, fc2b);

    // ---- classifier ----
    k_cls<<<(NN * 32 + 255) / 256, 256>>>(fc, clsW, clsb, outp, NN);
}

// round 11
// speedup vs baseline: 2.9929x; 1.2600x over previous
#include <cuda_runtime.h>
#include <cuda_bf16.h>
#include <cuda_fp16.h>
#include <mma.h>
#include <cstdint>
#include <math.h>

using namespace nvcuda;

#define NN 20000
#define MM 2048
#define EE 320000
#define FF 512
#define HIDD 256
#define CSTAT_ROWS 128
#define CSTAT_BLKS ((NN + CSTAT_ROWS - 1) / CSTAT_ROWS)   // 157

#define NEG_SLOPE 0.01f
#define ATT_SLOPE 0.2f

// ---------------- scratch ----------------
__device__ float g_xl[NN * FF];
__device__ __half g_elb[MM * FF];
__device__ float g_h[NN * FF];
__device__ __half g_h16[NN * FF];
__device__ float g_fc[NN * HIDD];
__device__ float g_xn[NN];
__device__ float g_en[MM];
__device__ float g_wa[FF];
__device__ float g_wb[FF];
__device__ float g_alpha[EE];
__device__ float g_Dinv[NN];
__device__ float g_Binv[MM];
__device__ int   g_degn[NN];
__device__ int   g_dege[MM];
__device__ int   g_rstart[NN + 1];
__device__ int   g_cstart[MM + 1];
__device__ int   g_rcur[NN];
__device__ int   g_ccur[MM];
__device__ int   g_rcsr[EE];
__device__ int   g_ccsr[EE];
__device__ int   g_bsumN[32];
__device__ int   g_bsumM[8];
__device__ float g_p1[CSTAT_BLKS * FF];
__device__ float g_p2[CSTAT_BLKS * FF];
__device__ float g_shift[FF];
__device__ float g_scale[FF];
__device__ __nv_bfloat16 g_eahi[MM * FF];
__device__ __nv_bfloat16 g_ealo[MM * FF];
__device__ __nv_bfloat16 g_W1thi[FF * FF];
__device__ __nv_bfloat16 g_W1tlo[FF * FF];
__device__ __nv_bfloat16 g_W2thi[FF * FF];
__device__ __nv_bfloat16 g_W2tlo[FF * FF];
__device__ __half g_f1t16[HIDD * FF];
__device__ __half g_f2t16[HIDD * FF];

// ---------------- cp.async helpers ----------------
__device__ __forceinline__ uint32_t smem_u32(const void* p) {
    uint32_t a;
    asm("{ .reg .u64 t; cvta.to.shared.u64 t, %1; cvt.u32.u64 %0, t; }" : "=r"(a) : "l"(p));
    return a;
}
__device__ __forceinline__ void cp16(uint32_t dst, const void* src) {
    asm volatile("cp.async.ca.shared.global [%0], [%1], 16;" :: "r"(dst), "l"(src));
}
#define CP_COMMIT() asm volatile("cp.async.commit_group;" ::: "memory")
#define CP_WAIT1()  asm volatile("cp.async.wait_group 1;" ::: "memory")
#define CP_WAIT0()  asm volatile("cp.async.wait_group 0;" ::: "memory")

#define APAD 72
#define SM_A0 0
#define SM_B0 18432
#define SM_A1 36864
#define SM_B1 55296
#define SM_STG 73728
#define GEMM_SMEM 81920

// ---------------- cp.async double-buffered wmma split-bf16 GEMM (ef path) ----------------
// MODE 0: store fp16 (C is __half*)
__global__ void __launch_bounds__(256) k_wgemm0(
    const __nv_bfloat16* __restrict__ Ahi, const __nv_bfloat16* __restrict__ Alo,
    const __nv_bfloat16* __restrict__ Bthi, const __nv_bfloat16* __restrict__ Btlo,
    __half* __restrict__ C, int Mr, int Nc, int Kd) {
    extern __shared__ __align__(16) char dsm[];
    const uint32_t sb = smem_u32(dsm);

    const int tid = threadIdx.x;
    const int wid = tid >> 5;
    const int lane = tid & 31;
    const int wm = wid >> 2;
    const int wn = wid & 3;
    const int bm = blockIdx.y * 128;
    const int bn = blockIdx.x * 128;

    const int CPS = Kd >> 6;
    const int NCH = 3 * CPS;

    const int lr = tid >> 1;
    const int lc = (tid & 1) * 4;
    const int gaRow = min(bm + lr, Mr - 1);
    const int gbRow = bn + lr;

    wmma::fragment<wmma::accumulator, 16, 16, 16, float> acc[4][2];
#pragma unroll
    for (int i = 0; i < 4; i++)
#pragma unroll
        for (int j = 0; j < 2; j++) wmma::fill_fragment(acc[i][j], 0.0f);

    auto issue = [&](int c) {
        int seg = c / CPS;
        int j = c - seg * CPS;
        const __nv_bfloat16* A = (seg == 1) ? Alo : Ahi;
        const __nv_bfloat16* B = (seg == 2) ? Btlo : Bthi;
        int koff = j << 6;
        int buf = c & 1;
        uint32_t abase = sb + (buf ? SM_A1 : SM_A0) + lr * 144;
        uint32_t bbase = sb + (buf ? SM_B1 : SM_B0) + lr * 144;
        const char* ap = (const char*)(A + (size_t)gaRow * Kd + koff);
        const char* bp = (const char*)(B + (size_t)gbRow * Kd + koff);
#pragma unroll
        for (int u = 0; u < 4; u++) {
            cp16(abase + (lc + u) * 16, ap + (lc + u) * 16);
            cp16(bbase + (lc + u) * 16, bp + (lc + u) * 16);
        }
        CP_COMMIT();
    };

    issue(0);
    for (int c = 0; c < NCH; c++) {
        if (c + 1 < NCH) { issue(c + 1); CP_WAIT1(); }
        else             { CP_WAIT0(); }
        __syncthreads();
        const int buf = c & 1;
        const __nv_bfloat16* As = (const __nv_bfloat16*)(dsm + (buf ? SM_A1 : SM_A0));
        const __nv_bfloat16* Bs = (const __nv_bfloat16*)(dsm + (buf ? SM_B1 : SM_B0));
#pragma unroll
        for (int kt = 0; kt < 4; kt++) {
            wmma::fragment<wmma::matrix_a, 16, 16, 16, __nv_bfloat16, wmma::row_major> af[4];
            wmma::fragment<wmma::matrix_b, 16, 16, 16, __nv_bfloat16, wmma::col_major> bf[2];
#pragma unroll
            for (int n = 0; n < 2; n++)
                wmma::load_matrix_sync(bf[n], Bs + (wn * 32 + n * 16) * APAD + kt * 16, APAD);
#pragma unroll
            for (int m = 0; m < 4; m++)
                wmma::load_matrix_sync(af[m], As + (wm * 64 + m * 16) * APAD + kt * 16, APAD);
#pragma unroll
            for (int m = 0; m < 4; m++)
#pragma unroll
                for (int n = 0; n < 2; n++)
                    wmma::mma_sync(acc[m][n], af[m], bf[n], acc[m][n]);
        }
        __syncthreads();
    }

    float* stg = (float*)(dsm + SM_STG) + wid * 256;
    const int srow = lane >> 1;
    const int scol = (lane & 1) * 8;
#pragma unroll
    for (int m = 0; m < 4; m++) {
#pragma unroll
        for (int n = 0; n < 2; n++) {
            wmma::store_matrix_sync(stg, acc[m][n], 16, wmma::mem_row_major);
            __syncwarp();
            int grow = bm + wm * 64 + m * 16 + srow;
            int gcol = bn + wn * 32 + n * 16 + scol;
            if (grow < Mr) {
                const float* sp = stg + srow * 16 + scol;
                __half* crow = C + (size_t)grow * Nc + gcol;
#pragma unroll
                for (int q = 0; q < 2; q++) {
                    float4 v = *(const float4*)(sp + q * 4);
                    ((__half2*)(crow + q * 4))[0] = __floats2half2_rn(v.x, v.y);
                    ((__half2*)(crow + q * 4))[1] = __floats2half2_rn(v.z, v.w);
                }
            }
            __syncwarp();
        }
    }
}

// ---------------- fp16 single-segment GEMM (fc path) ----------------
// MODE 1: store lrelu(AB+bias); MODE 2: C += lrelu(AB+bias)
template <int MODE>
__global__ void __launch_bounds__(256) k_hgemm(
    const __half* __restrict__ A, const __half* __restrict__ Bt,
    float* __restrict__ C, int Mr, int Nc, int Kd, const float* __restrict__ bias) {
    extern __shared__ __align__(16) char dsm[];
    const uint32_t sb = smem_u32(dsm);

    const int tid = threadIdx.x;
    const int wid = tid >> 5;
    const int lane = tid & 31;
    const int wm = wid >> 2;
    const int wn = wid & 3;
    const int bm = blockIdx.y * 128;
    const int bn = blockIdx.x * 128;

    const int NCH = Kd >> 6;

    const int lr = tid >> 1;
    const int lc = (tid & 1) * 4;
    const int gaRow = min(bm + lr, Mr - 1);
    const int gbRow = bn + lr;

    wmma::fragment<wmma::accumulator, 16, 16, 16, float> acc[4][2];
#pragma unroll
    for (int i = 0; i < 4; i++)
#pragma unroll
        for (int j = 0; j < 2; j++) wmma::fill_fragment(acc[i][j], 0.0f);

    auto issue = [&](int c) {
        int koff = c << 6;
        int buf = c & 1;
        uint32_t abase = sb + (buf ? SM_A1 : SM_A0) + lr * 144;
        uint32_t bbase = sb + (buf ? SM_B1 : SM_B0) + lr * 144;
        const char* ap = (const char*)(A + (size_t)gaRow * Kd + koff);
        const char* bp = (const char*)(Bt + (size_t)gbRow * Kd + koff);
#pragma unroll
        for (int u = 0; u < 4; u++) {
            cp16(abase + (lc + u) * 16, ap + (lc + u) * 16);
            cp16(bbase + (lc + u) * 16, bp + (lc + u) * 16);
        }
        CP_COMMIT();
    };

    issue(0);
    for (int c = 0; c < NCH; c++) {
        if (c + 1 < NCH) { issue(c + 1); CP_WAIT1(); }
        else             { CP_WAIT0(); }
        __syncthreads();
        const int buf = c & 1;
        const __half* As = (const __half*)(dsm + (buf ? SM_A1 : SM_A0));
        const __half* Bs = (const __half*)(dsm + (buf ? SM_B1 : SM_B0));
#pragma unroll
        for (int kt = 0; kt < 4; kt++) {
            wmma::fragment<wmma::matrix_a, 16, 16, 16, __half, wmma::row_major> af[4];
            wmma::fragment<wmma::matrix_b, 16, 16, 16, __half, wmma::col_major> bf[2];
#pragma unroll
            for (int n = 0; n < 2; n++)
                wmma::load_matrix_sync(bf[n], Bs + (wn * 32 + n * 16) * APAD + kt * 16, APAD);
#pragma unroll
            for (int m = 0; m < 4; m++)
                wmma::load_matrix_sync(af[m], As + (wm * 64 + m * 16) * APAD + kt * 16, APAD);
#pragma unroll
            for (int m = 0; m < 4; m++)
#pragma unroll
                for (int n = 0; n < 2; n++)
                    wmma::mma_sync(acc[m][n], af[m], bf[n], acc[m][n]);
        }
        __syncthreads();
    }

    float* stg = (float*)(dsm + SM_STG) + wid * 256;
    const int srow = lane >> 1;
    const int scol = (lane & 1) * 8;
#pragma unroll
    for (int m = 0; m < 4; m++) {
#pragma unroll
        for (int n = 0; n < 2; n++) {
            wmma::store_matrix_sync(stg, acc[m][n], 16, wmma::mem_row_major);
            __syncwarp();
            int grow = bm + wm * 64 + m * 16 + srow;
            int gcol = bn + wn * 32 + n * 16 + scol;
            if (grow < Mr) {
                const float* sp = stg + srow * 16 + scol;
                float* crow = C + (size_t)grow * Nc + gcol;
#pragma unroll
                for (int q = 0; q < 2; q++) {
                    float4 v = *(const float4*)(sp + q * 4);
                    float4 bb = *(const float4*)(bias + gcol + q * 4);
                    v.x += bb.x; v.y += bb.y; v.z += bb.z; v.w += bb.w;
                    v.x = (v.x > 0.f) ? v.x : NEG_SLOPE * v.x;
                    v.y = (v.y > 0.f) ? v.y : NEG_SLOPE * v.y;
                    v.z = (v.z > 0.f) ? v.z : NEG_SLOPE * v.z;
                    v.w = (v.w > 0.f) ? v.w : NEG_SLOPE * v.w;
                    if (MODE == 2) {
                        float4 o = *(const float4*)(crow + q * 4);
                        v.x += o.x; v.y += o.y; v.z += o.z; v.w += o.w;
                    }
                    *(float4*)(crow + q * 4) = v;
                }
            }
            __syncwarp();
        }
    }
}

// ---------------- conversions ----------------
__global__ void k_wsplit(const float* __restrict__ W, __nv_bfloat16* __restrict__ thi,
                         __nv_bfloat16* __restrict__ tlo, int K, int N) {
    int i = blockIdx.x * blockDim.x + threadIdx.x;
    if (i >= K * N) return;
    int n = i / K, k = i - n * K;
    float v = W[(size_t)k * N + n];
    __nv_bfloat16 h = __float2bfloat16(v);
    thi[i] = h;
    tlo[i] = __float2bfloat16(v - __bfloat162float(h));
}

__global__ void k_wsplit16(const float* __restrict__ W, __half* __restrict__ t16, int K, int N) {
    int i = blockIdx.x * blockDim.x + threadIdx.x;
    if (i >= K * N) return;
    int n = i / K, k = i - n * K;
    t16[i] = __float2half(W[(size_t)k * N + n]);
}

__global__ void k_tof16(const float* __restrict__ X, __half* __restrict__ Y, int total4) {
    int i = blockIdx.x * blockDim.x + threadIdx.x;
    if (i >= total4) return;
    float4 v = ((const float4*)X)[i];
    ((__half2*)Y)[i * 2]     = __floats2half2_rn(v.x, v.y);
    ((__half2*)Y)[i * 2 + 1] = __floats2half2_rn(v.z, v.w);
}

// ---------------- structure kernels ----------------
__global__ void k_zero2(int* a, int na, int* b, int nb) {
    int i = blockIdx.x * blockDim.x + threadIdx.x;
    if (i < na) a[i] = 0;
    else if (i < na + nb) b[i - na] = 0;
}

__global__ void k_hist(const int* __restrict__ row, const int* __restrict__ col,
                       int* degn, int* dege, int E) {
    int i = blockIdx.x * blockDim.x + threadIdx.x;
    if (i < E) {
        atomicAdd(&degn[row[i]], 1);
        atomicAdd(&dege[col[i]], 1);
    }
}

__global__ void k_bsum(const int* __restrict__ cnt, int* __restrict__ bsum, int n) {
    int b = blockIdx.x, t = threadIdx.x;
    int base = b * 1024;
    int s = 0;
#pragma unroll
    for (int u = 0; u < 4; u++) {
        int i = base + t + u * 256;
        if (i < n) s += cnt[i];
    }
    __shared__ int red[8];
    for (int o = 16; o; o >>= 1) s += __shfl_down_sync(0xffffffffu, s, o);
    if ((t & 31) == 0) red[t >> 5] = s;
    __syncthreads();
    if (t == 0) {
        int v = 0;
#pragma unroll
        for (int w = 0; w < 8; w++) v += red[w];
        bsum[b] = v;
    }
}

__global__ void k_bscan(int* bsum, int nb) {
    if (threadIdx.x == 0) {
        int run = 0;
        for (int i = 0; i < nb; i++) { int v = bsum[i]; bsum[i] = run; run += v; }
        bsum[nb] = run;
    }
}

__global__ void k_lscan(const int* __restrict__ cnt, const int* __restrict__ bsum,
                        int* __restrict__ start, int* __restrict__ cur, int n, int nb) {
    int b = blockIdx.x, t = threadIdx.x;
    __shared__ int sh[256];
    int base = b * 1024;
    int v[4];
    int s = 0;
#pragma unroll
    for (int u = 0; u < 4; u++) {
        int i = base + t * 4 + u;
        v[u] = (i < n) ? cnt[i] : 0;
        s += v[u];
    }
    sh[t] = s;
    __syncthreads();
    for (int o = 1; o < 256; o <<= 1) {
        int a = (t >= o) ? sh[t - o] : 0;
        __syncthreads();
        sh[t] += a;
        __syncthreads();
    }
    int run = bsum[b] + ((t == 0) ? 0 : sh[t - 1]);
#pragma unroll
    for (int u = 0; u < 4; u++) {
        int i = base + t * 4 + u;
        if (i < n) { start[i] = run; cur[i] = run; run += v[u]; }
    }
    if (b == 0 && t == 0) start[n] = bsum[nb];
}

__global__ void k_scatter(const int* __restrict__ row, const int* __restrict__ col,
                          int* rcur, int* ccur, int* __restrict__ rcsr,
                          int* __restrict__ ccsr, int E) {
    int i = blockIdx.x * blockDim.x + threadIdx.x;
    if (i < E) {
        int pr = atomicAdd(&rcur[row[i]], 1);
        rcsr[pr] = i;
        int pc = atomicAdd(&ccur[col[i]], 1);
        ccsr[pc] = i;
    }
}

__global__ void k_inv2(const int* __restrict__ da, float* __restrict__ ia, int na,
                       const int* __restrict__ db, float* __restrict__ ib, int nb) {
    int i = blockIdx.x * blockDim.x + threadIdx.x;
    if (i < na) {
        int d = da[i];
        ia[i] = (d > 0) ? (1.0f / (float)d) : 0.0f;
    } else if (i < na + nb) {
        int d = db[i - na];
        ib[i - na] = (d > 0) ? (1.0f / (float)d) : 0.0f;
    }
}

// ---------------- row dots ----------------
__global__ void k_rowdot(const float* __restrict__ X, const float* __restrict__ v,
                         float* __restrict__ out, int rows) {
    int gw = (blockIdx.x * blockDim.x + threadIdx.x) >> 5;
    int lane = threadIdx.x & 31;
    if (gw >= rows) return;
    const float4* xr = (const float4*)(X + (size_t)gw * FF);
    const float4* vv = (const float4*)v;
    float s = 0.f;
#pragma unroll
    for (int j = 0; j < 4; j++) {
        float4 a = xr[lane + 32 * j];
        float4 b = vv[lane + 32 * j];
        s += a.x * b.x + a.y * b.y + a.z * b.z + a.w * b.w;
    }
    for (int o = 16; o; o >>= 1) s += __shfl_down_sync(0xffffffffu, s, o);
    if (!lane) out[gw] = s;
}

__global__ void k_rowdot2(const float* __restrict__ X, const float* __restrict__ v1,
                          const float* __restrict__ v2, float* __restrict__ o1,
                          float* __restrict__ o2, int rows) {
    int gw = (blockIdx.x * blockDim.x + threadIdx.x) >> 5;
    int lane = threadIdx.x & 31;
    if (gw >= rows) return;
    const float4* xr = (const float4*)(X + (size_t)gw * FF);
    const float4* va = (const float4*)v1;
    const float4* vb = (const float4*)v2;
    float s1 = 0.f, s2 = 0.f;
#pragma unroll
    for (int j = 0; j < 4; j++) {
        float4 a = xr[lane + 32 * j];
        float4 b = va[lane + 32 * j];
        float4 c = vb[lane + 32 * j];
        s1 += a.x * b.x + a.y * b.y + a.z * b.z + a.w * b.w;
        s2 += a.x * c.x + a.y * c.y + a.z * c.z + a.w * c.w;
    }
    for (int o = 16; o; o >>= 1) {
        s1 += __shfl_down_sync(0xffffffffu, s1, o);
        s2 += __shfl_down_sync(0xffffffffu, s2, o);
    }
    if (!lane) { o1[gw] = s1; o2[gw] = s2; }
}

// ---------------- fused attention softmax + propagate-1 (fp16 gather) ----------------
__global__ void __launch_bounds__(256) k_attnprop(
    const int* __restrict__ cstart, const int* __restrict__ ccsr,
    const int* __restrict__ row, const float* __restrict__ xn,
    const float* __restrict__ en, const float* __restrict__ Binv,
    const __half* __restrict__ X, float* __restrict__ alpha,
    __nv_bfloat16* __restrict__ efhi, __nv_bfloat16* __restrict__ eflo) {
    int m = blockIdx.x;
    int s = cstart[m], e = cstart[m + 1];
    int tid = threadIdx.x;
    __shared__ float red[256];
    __shared__ int   shr[256];
    __shared__ float shc[256];

    float enm = en[m];
    float mx = -3.0e38f;
    for (int i = s + tid; i < e; i += 256) {
        int ed = ccsr[i];
        float p = xn[row[ed]] + enm;
        p = (p > 0.f) ? p : ATT_SLOPE * p;
        alpha[ed] = p;
        mx = fmaxf(mx, p);
    }
    red[tid] = mx;
    __syncthreads();
    for (int o = 128; o; o >>= 1) {
        if (tid < o) red[tid] = fmaxf(red[tid], red[tid + o]);
        __syncthreads();
    }
    float amax = red[0];
    if (!(amax > -1e37f)) amax = 0.f;
    __syncthreads();
    float sm = 0.f;
    for (int i = s + tid; i < e; i += 256) {
        int ed = ccsr[i];
        float ex = expf(alpha[ed] - amax);
        alpha[ed] = ex;
        sm += ex;
    }
    red[tid] = sm;
    __syncthreads();
    for (int o = 128; o; o >>= 1) {
        if (tid < o) red[tid] += red[tid + o];
        __syncthreads();
    }
    float inv = 1.f / fmaxf(red[0], 1e-16f);
    float bi = Binv[m];
    float ax = 0.f, ay = 0.f;
    const __half2* base = (const __half2*)X + tid;
    for (int b0 = s; b0 < e; b0 += 256) {
        int cnt = min(256, e - b0);
        __syncthreads();
        if (tid < cnt) {
            int ed = ccsr[b0 + tid];
            float a = alpha[ed] * inv;
            alpha[ed] = a;
            shr[tid] = row[ed];
            shc[tid] = a * bi;
        }
        __syncthreads();
        int j = 0;
        for (; j + 4 <= cnt; j += 4) {
            int r0 = shr[j], r1 = shr[j + 1], r2 = shr[j + 2], r3 = shr[j + 3];
            float c0 = shc[j], c1 = shc[j + 1], c2 = shc[j + 2], c3 = shc[j + 3];
            float2 v0 = __half22float2(base[(size_t)r0 * (FF / 2)]);
            float2 v1 = __half22float2(base[(size_t)r1 * (FF / 2)]);
            float2 v2 = __half22float2(base[(size_t)r2 * (FF / 2)]);
            float2 v3 = __half22float2(base[(size_t)r3 * (FF / 2)]);
            ax += c0 * v0.x + c1 * v1.x + c2 * v2.x + c3 * v3.x;
            ay += c0 * v0.y + c1 * v1.y + c2 * v2.y + c3 * v3.y;
        }
        for (; j < cnt; j++) {
            float2 v = __half22float2(base[(size_t)shr[j] * (FF / 2)]);
            float cf = shc[j];
            ax += cf * v.x;
            ay += cf * v.y;
        }
    }
    __nv_bfloat16 hx = __float2bfloat16(ax), hy = __float2bfloat16(ay);
    __nv_bfloat16 lx = __float2bfloat16(ax - __bfloat162float(hx));
    __nv_bfloat16 ly = __float2bfloat16(ay - __bfloat162float(hy));
    ((__nv_bfloat162*)(efhi + (size_t)m * FF))[tid] = __nv_bfloat162(hx, hy);
    ((__nv_bfloat162*)(eflo + (size_t)m * FF))[tid] = __nv_bfloat162(lx, ly);
}

// ---------------- propagate-2 (fp16 gather, unrolled x4) ----------------
__global__ void k_prop2(const int* __restrict__ rstart, const int* __restrict__ rcsr,
                        const int* __restrict__ col, const float* __restrict__ alpha,
                        const float* __restrict__ Dinv, const __half* __restrict__ ef,
                        const float* __restrict__ bias, float* __restrict__ out) {
    int n = blockIdx.x;
    int s = rstart[n], e = rstart[n + 1];
    int tid = threadIdx.x;
    float a0 = 0.f, a1 = 0.f, a2 = 0.f, a3 = 0.f;
    const uint2* base = (const uint2*)ef + tid;
    int i = s;
    for (; i + 4 <= e; i += 4) {
        int e0 = rcsr[i], e1 = rcsr[i + 1], e2 = rcsr[i + 2], e3 = rcsr[i + 3];
        float c0 = alpha[e0], c1 = alpha[e1], c2 = alpha[e2], c3 = alpha[e3];
        uint2 u0 = base[(size_t)col[e0] * (FF / 4)];
        uint2 u1 = base[(size_t)col[e1] * (FF / 4)];
        uint2 u2 = base[(size_t)col[e2] * (FF / 4)];
        uint2 u3 = base[(size_t)col[e3] * (FF / 4)];
        float2 p0a = __half22float2(*(const __half2*)&u0.x);
        float2 p0b = __half22float2(*(const __half2*)&u0.y);
        float2 p1a = __half22float2(*(const __half2*)&u1.x);
        float2 p1b = __half22float2(*(const __half2*)&u1.y);
        float2 p2a = __half22float2(*(const __half2*)&u2.x);
        float2 p2b = __half22float2(*(const __half2*)&u2.y);
        float2 p3a = __half22float2(*(const __half2*)&u3.x);
        float2 p3b = __half22float2(*(const __half2*)&u3.y);
        a0 += c0 * p0a.x + c1 * p1a.x + c2 * p2a.x + c3 * p3a.x;
        a1 += c0 * p0a.y + c1 * p1a.y + c2 * p2a.y + c3 * p3a.y;
        a2 += c0 * p0b.x + c1 * p1b.x + c2 * p2b.x + c3 * p3b.x;
        a3 += c0 * p0b.y + c1 * p1b.y + c2 * p2b.y + c3 * p3b.y;
    }
    for (; i < e; i++) {
        int ed = rcsr[i];
        float cf = alpha[ed];
        uint2 u = base[(size_t)col[ed] * (FF / 4)];
        float2 pa = __half22float2(*(const __half2*)&u.x);
        float2 pb = __half22float2(*(const __half2*)&u.y);
        a0 += cf * pa.x; a1 += cf * pa.y; a2 += cf * pb.x; a3 += cf * pb.y;
    }
    float d = Dinv[n];
    float4 b = *(const float4*)(bias + 4 * tid);
    float4 o;
    o.x = a0 * d + b.x; o.y = a1 * d + b.y; o.z = a2 * d + b.z; o.w = a3 * d + b.w;
    *(float4*)(out + (size_t)n * FF + 4 * tid) = o;
}

// ---------------- graph norm ----------------
__global__ void k_colstat(const float* __restrict__ X, float* __restrict__ p1,
                          float* __restrict__ p2, int rows) {
    int b = blockIdx.x;
    int c = threadIdx.x;
    int r0 = b * CSTAT_ROWS, r1 = min(r0 + CSTAT_ROWS, rows);
    float s1 = 0.f, s2 = 0.f;
    for (int r = r0; r < r1; r++) {
        float v = X[(size_t)r * FF + c];
        s1 += v;
        s2 += v * v;
    }
    p1[b * FF + c] = s1;
    p2[b * FF + c] = s2;
}

__global__ void k_statfin(const float* __restrict__ p1, const float* __restrict__ p2,
                          int nblk, const float* __restrict__ w,
                          const float* __restrict__ ms, float* __restrict__ shift,
                          float* __restrict__ scale, float rows_inv) {
    int c = threadIdx.x;
    float s1 = 0.f, s2 = 0.f;
    for (int i = 0; i < nblk; i++) {
        s1 += p1[i * FF + c];
        s2 += p2[i * FF + c];
    }
    float mu = s1 * rows_inv;
    float ex2 = s2 * rows_inv;
    float m = ms[c];
    float sh = m * mu;
    float var = ex2 - sh * (2.f * mu - sh);
    shift[c] = sh;
    scale[c] = w[c] / sqrtf(var + 1e-5f);
}

// graph_norm apply + leaky_relu: fp32 out + fp16 copy
__global__ void k_normsplit(const float* __restrict__ X, const float* __restrict__ shift,
                            const float* __restrict__ scale, const float* __restrict__ beta,
                            float* __restrict__ Yf, __half* __restrict__ y16, int total4) {
    int i = blockIdx.x * blockDim.x + threadIdx.x;
    if (i >= total4) return;
    int c = (i & 127) * 4;
    float4 v = ((const float4*)X)[i];
    float4 sh = *(const float4*)(shift + c);
    float4 sc = *(const float4*)(scale + c);
    float4 be = *(const float4*)(beta + c);
    float y0 = (v.x - sh.x) * sc.x + be.x;
    float y1 = (v.y - sh.y) * sc.y + be.y;
    float y2 = (v.z - sh.z) * sc.z + be.z;
    float y3 = (v.w - sh.w) * sc.w + be.w;
    y0 = (y0 > 0.f) ? y0 : NEG_SLOPE * y0;
    y1 = (y1 > 0.f) ? y1 : NEG_SLOPE * y1;
    y2 = (y2 > 0.f) ? y2 : NEG_SLOPE * y2;
    y3 = (y3 > 0.f) ? y3 : NEG_SLOPE * y3;
    ((float4*)Yf)[i] = make_float4(y0, y1, y2, y3);
    ((__half2*)y16)[i * 2]     = __floats2half2_rn(y0, y1);
    ((__half2*)y16)[i * 2 + 1] = __floats2half2_rn(y2, y3);
}

__global__ void k_cls(const float* __restrict__ A, const float* __restrict__ W,
                      const float* __restrict__ b, float* __restrict__ out, int rows) {
    int gw = (blockIdx.x * blockDim.x + threadIdx.x) >> 5;
    int lane = threadIdx.x & 31;
    if (gw >= rows) return;
    const float* ar = A + (size_t)gw * HIDD;
    float s0 = 0.f, s1 = 0.f;
    for (int h = lane; h < HIDD; h += 32) {
        float v = ar[h];
        s0 += v * W[h * 2];
        s1 += v * W[h * 2 + 1];
    }
    for (int o = 16; o; o >>= 1) {
        s0 += __shfl_down_sync(0xffffffffu, s0, o);
        s1 += __shfl_down_sync(0xffffffffu, s1, o);
    }
    if (!lane) {
        out[gw * 2] = s0 + b[0];
        out[gw * 2 + 1] = s1 + b[1];
    }
}

// ---------------- host launch ----------------
extern "C" void kernel_launch(void* const* d_in, const int* in_sizes, int n_in,
                              void* d_out, int out_size) {
    const float* x    = (const float*)d_in[0];
    const int*   ei   = (const int*)d_in[1];
    const float* ea   = (const float*)d_in[2];
    const float* W1   = (const float*)d_in[3];
    const float* att1 = (const float*)d_in[4];
    const float* b1   = (const float*)d_in[5];
    const float* W2   = (const float*)d_in[6];
    const float* att2 = (const float*)d_in[7];
    const float* b2   = (const float*)d_in[8];
    const float* gn1w = (const float*)d_in[9];
    const float* gn1b = (const float*)d_in[10];
    const float* gn1ms= (const float*)d_in[11];
    const float* gn2w = (const float*)d_in[12];
    const float* gn2b = (const float*)d_in[13];
    const float* gn2ms= (const float*)d_in[14];
    const float* fc1W = (const float*)d_in[15];
    const float* fc1b = (const float*)d_in[16];
    const float* fc2W = (const float*)d_in[17];
    const float* fc2b = (const float*)d_in[18];
    const float* clsW = (const float*)d_in[19];
    const float* clsb = (const float*)d_in[20];
    float* outp = (float*)d_out;

    const int* row = ei;
    const int* col = ei + EE;

    float *xl, *h, *fc, *xn, *en, *wa, *wb, *alpha, *Dinv, *Binv;
    float *p1, *p2, *shift, *scale;
    int *degn, *dege, *rstart, *cstart, *rcur, *ccur, *rcsr, *ccsr, *bsumN, *bsumM;
    __half *elb, *h16, *f1t16, *f2t16;
    __nv_bfloat16 *eahi, *ealo, *W1thi, *W1tlo, *W2thi, *W2tlo;
    cudaGetSymbolAddress((void**)&xl, g_xl);
    cudaGetSymbolAddress((void**)&elb, g_elb);
    cudaGetSymbolAddress((void**)&h, g_h);
    cudaGetSymbolAddress((void**)&h16, g_h16);
    cudaGetSymbolAddress((void**)&fc, g_fc);
    cudaGetSymbolAddress((void**)&xn, g_xn);
    cudaGetSymbolAddress((void**)&en, g_en);
    cudaGetSymbolAddress((void**)&wa, g_wa);
    cudaGetSymbolAddress((void**)&wb, g_wb);
    cudaGetSymbolAddress((void**)&alpha, g_alpha);
    cudaGetSymbolAddress((void**)&Dinv, g_Dinv);
    cudaGetSymbolAddress((void**)&Binv, g_Binv);
    cudaGetSymbolAddress((void**)&p1, g_p1);
    cudaGetSymbolAddress((void**)&p2, g_p2);
    cudaGetSymbolAddress((void**)&shift, g_shift);
    cudaGetSymbolAddress((void**)&scale, g_scale);
    cudaGetSymbolAddress((void**)&degn, g_degn);
    cudaGetSymbolAddress((void**)&dege, g_dege);
    cudaGetSymbolAddress((void**)&rstart, g_rstart);
    cudaGetSymbolAddress((void**)&cstart, g_cstart);
    cudaGetSymbolAddress((void**)&rcur, g_rcur);
    cudaGetSymbolAddress((void**)&ccur, g_ccur);
    cudaGetSymbolAddress((void**)&rcsr, g_rcsr);
    cudaGetSymbolAddress((void**)&ccsr, g_ccsr);
    cudaGetSymbolAddress((void**)&bsumN, g_bsumN);
    cudaGetSymbolAddress((void**)&bsumM, g_bsumM);
    cudaGetSymbolAddress((void**)&eahi, g_eahi);
    cudaGetSymbolAddress((void**)&ealo, g_ealo);
    cudaGetSymbolAddress((void**)&W1thi, g_W1thi);
    cudaGetSymbolAddress((void**)&W1tlo, g_W1tlo);
    cudaGetSymbolAddress((void**)&W2thi, g_W2thi);
    cudaGetSymbolAddress((void**)&W2tlo, g_W2tlo);
    cudaGetSymbolAddress((void**)&f1t16, g_f1t16);
    cudaGetSymbolAddress((void**)&f2t16, g_f2t16);

    static cudaStream_t s1 = nullptr;
    static cudaEvent_t evFork = nullptr, evJoin1 = nullptr, evFork2 = nullptr, evJoin2 = nullptr;
    static bool init_done = false;
    if (!init_done) {
        cudaFuncSetAttribute(k_wgemm0, cudaFuncAttributeMaxDynamicSharedMemorySize, GEMM_SMEM);
        cudaFuncSetAttribute(k_hgemm<1>, cudaFuncAttributeMaxDynamicSharedMemorySize, GEMM_SMEM);
        cudaFuncSetAttribute(k_hgemm<2>, cudaFuncAttributeMaxDynamicSharedMemorySize, GEMM_SMEM);
        cudaStreamCreateWithFlags(&s1, cudaStreamNonBlocking);
        cudaEventCreateWithFlags(&evFork, cudaEventDisableTiming);
        cudaEventCreateWithFlags(&evJoin1, cudaEventDisableTiming);
        cudaEventCreateWithFlags(&evFork2, cudaEventDisableTiming);
        cudaEventCreateWithFlags(&evJoin2, cudaEventDisableTiming);
        init_done = true;
    }

    const int NBN = (NN + 1023) / 1024;
    const int NBM = (MM + 1023) / 1024;
    const float rows_inv = 1.0f / (float)NN;
    dim3 gM(FF / 128, MM / 128);
    dim3 gFC(HIDD / 128, (NN + 127) / 128);

    // ---- fork: s1 joins capture ----
    cudaEventRecord(evFork, 0);
    cudaStreamWaitEvent(s1, evFork, 0);

    // ---- s0: graph structure chain ----
    k_zero2<<<(NN + MM + 255) / 256, 256>>>(degn, NN, dege, MM);
    k_hist<<<(EE + 255) / 256, 256>>>(row, col, degn, dege, EE);
    k_bsum<<<NBM, 256>>>(dege, bsumM, MM);
    k_bsum<<<NBN, 256>>>(degn, bsumN, NN);
    k_bscan<<<1, 32>>>(bsumM, NBM);
    k_bscan<<<1, 32>>>(bsumN, NBN);
    k_lscan<<<NBM, 256>>>(dege, bsumM, cstart, ccur, MM, NBM);
    k_lscan<<<NBN, 256>>>(degn, bsumN, rstart, rcur, NN, NBN);
    k_scatter<<<(EE + 255) / 256, 256>>>(row, col, rcur, ccur, rcsr, ccsr, EE);
    k_inv2<<<(NN + MM + 255) / 256, 256>>>(degn, Dinv, NN, dege, Binv, MM);

    // ---- s1 (parallel): conversions + conv1 pre-dots ----
    k_wsplit<<<(FF * FF + 255) / 256, 256, 0, s1>>>(W1, W1thi, W1tlo, FF, FF);
    k_wsplit<<<(FF * FF + 255) / 256, 256, 0, s1>>>(W2, W2thi, W2tlo, FF, FF);
    k_wsplit16<<<(FF * HIDD + 255) / 256, 256, 0, s1>>>(fc1W, f1t16, FF, HIDD);
    k_wsplit16<<<(FF * HIDD + 255) / 256, 256, 0, s1>>>(fc2W, f2t16, FF, HIDD);
    k_tof16<<<(NN * (FF / 4) + 255) / 256, 256, 0, s1>>>(x, h16, NN * (FF / 4));
    k_rowdot2<<<(FF * 32 + 255) / 256, 256, 0, s1>>>(W1, att1, att1 + FF, wa, wb, FF);
    k_rowdot<<<(NN * 32 + 255) / 256, 256, 0, s1>>>(x, wa, xn, NN);
    k_rowdot<<<(MM * 32 + 255) / 256, 256, 0, s1>>>(ea, wb, en, MM);
    cudaEventRecord(evJoin1, s1);
    cudaStreamWaitEvent(0, evJoin1, 0);

    // ==== conv1 (s0) ====
    k_attnprop<<<MM, 256>>>(cstart, ccsr, row, xn, en, Binv, h16, alpha, eahi, ealo);
    k_wgemm0<<<gM, 256, GEMM_SMEM>>>(eahi, ealo, W1thi, W1tlo, elb, MM, FF, FF);
    k_prop2<<<NN, 128>>>(rstart, rcsr, col, alpha, Dinv, elb, b1, xl);
    k_colstat<<<CSTAT_BLKS, FF>>>(xl, p1, p2, NN);
    k_statfin<<<1, FF>>>(p1, p2, CSTAT_BLKS, gn1w, gn1ms, shift, scale, rows_inv);
    k_normsplit<<<(NN * (FF / 4) + 255) / 256, 256>>>(xl, shift, scale, gn1b, h, h16, NN * (FF / 4));

    // ---- fork 2: fc1 GEMM on s1 (reads h16), conv2 front on s0 ----
    cudaEventRecord(evFork2, 0);
    cudaStreamWaitEvent(s1, evFork2, 0);
    k_hgemm<1><<<gFC, 256, GEMM_SMEM, s1>>>(h16, f1t16, fc, NN, HIDD, FF, fc1b);

    // ==== conv2 front (s0) ====
    k_rowdot2<<<(FF * 32 + 255) / 256, 256>>>(W2, att2, att2 + FF, wa, wb, FF);
    k_rowdot<<<(NN * 32 + 255) / 256, 256>>>(h, wa, xn, NN);
    k_rowdot<<<(MM * 32 + 255) / 256, 256>>>(ea, wb, en, MM);
    k_attnprop<<<MM, 256>>>(cstart, ccsr, row, xn, en, Binv, h16, alpha, eahi, ealo);
    k_wgemm0<<<gM, 256, GEMM_SMEM>>>(eahi, ealo, W2thi, W2tlo, elb, MM, FF, FF);
    k_prop2<<<NN, 128>>>(rstart, rcsr, col, alpha, Dinv, elb, b2, xl);
    k_colstat<<<CSTAT_BLKS, FF>>>(xl, p1, p2, NN);
    k_statfin<<<1, FF>>>(p1, p2, CSTAT_BLKS, gn2w, gn2ms, shift, scale, rows_inv);

    // join: fc1 must finish before normsplit2 overwrites h16 (and before fc2 reads fc)
    cudaEventRecord(evJoin2, s1);
    cudaStreamWaitEvent(0, evJoin2, 0);
    k_normsplit<<<(NN * (FF / 4) + 255) / 256, 256>>>(xl, shift, scale, gn2b, h, h16, NN * (FF / 4));
    k_hgemm<2><<<gFC, 256, GEMM_SMEM>>>(h16, f2t16, fc, NN, HIDD, FF, fc2b);

    // ---- classifier ----
    k_cls<<<(NN * 32 + 255) / 256, 256>>>(fc, clsW, clsb, outp, NN);
}

// round 12
// speedup vs baseline: 3.0156x; 1.0076x over previous
#include <cuda_runtime.h>
#include <cuda_bf16.h>
#include <cuda_fp16.h>
#include <mma.h>
#include <cstdint>
#include <math.h>

using namespace nvcuda;

#define NN 20000
#define MM 2048
#define EE 320000
#define FF 512
#define HIDD 256
#define CSTAT_ROWS 128
#define CSTAT_BLKS ((NN + CSTAT_ROWS - 1) / CSTAT_ROWS)   // 157

#define NEG_SLOPE 0.01f
#define ATT_SLOPE 0.2f

// ---------------- scratch ----------------
__device__ float g_xl[NN * FF];
__device__ __half g_elb[MM * FF];
__device__ float g_h[NN * FF];
__device__ __half g_h16[NN * FF];
__device__ float g_fc[NN * HIDD];
__device__ float g_xn[NN];
__device__ float g_en1[MM];
__device__ float g_en2[MM];
__device__ float g_wa1[FF];
__device__ float g_wb1[FF];
__device__ float g_wa2[FF];
__device__ float g_wb2[FF];
__device__ float g_alpha[EE];
__device__ float g_Dinv[NN];
__device__ float g_Binv[MM];
__device__ int   g_degn[NN];
__device__ int   g_dege[MM];
__device__ int   g_rstart[NN + 1];
__device__ int   g_cstart[MM + 1];
__device__ int   g_rcur[NN];
__device__ int   g_ccur[MM];
__device__ int   g_rcsr[EE];
__device__ int   g_ccsr[EE];
__device__ int   g_bsumN[32];
__device__ int   g_bsumM[8];
__device__ float g_p1[CSTAT_BLKS * FF];
__device__ float g_p2[CSTAT_BLKS * FF];
__device__ float g_shift[FF];
__device__ float g_scale[FF];
__device__ __nv_bfloat16 g_eahi[MM * FF];
__device__ __nv_bfloat16 g_ealo[MM * FF];
__device__ __nv_bfloat16 g_W1thi[FF * FF];
__device__ __nv_bfloat16 g_W1tlo[FF * FF];
__device__ __nv_bfloat16 g_W2thi[FF * FF];
__device__ __nv_bfloat16 g_W2tlo[FF * FF];
__device__ __half g_f1t16[HIDD * FF];
__device__ __half g_f2t16[HIDD * FF];

// ---------------- cp.async helpers ----------------
__device__ __forceinline__ uint32_t smem_u32(const void* p) {
    uint32_t a;
    asm("{ .reg .u64 t; cvta.to.shared.u64 t, %1; cvt.u32.u64 %0, t; }" : "=r"(a) : "l"(p));
    return a;
}
__device__ __forceinline__ void cp16(uint32_t dst, const void* src) {
    asm volatile("cp.async.ca.shared.global [%0], [%1], 16;" :: "r"(dst), "l"(src));
}
#define CP_COMMIT() asm volatile("cp.async.commit_group;" ::: "memory")
#define CP_WAIT1()  asm volatile("cp.async.wait_group 1;" ::: "memory")
#define CP_WAIT0()  asm volatile("cp.async.wait_group 0;" ::: "memory")

#define APAD 72
#define SM_A0 0
#define SM_B0 18432
#define SM_A1 36864
#define SM_B1 55296
#define SM_STG 73728
#define GEMM_SMEM 81920

// ---------------- cp.async double-buffered wmma split-bf16 GEMM (ef path) ----------------
__global__ void __launch_bounds__(256) k_wgemm0(
    const __nv_bfloat16* __restrict__ Ahi, const __nv_bfloat16* __restrict__ Alo,
    const __nv_bfloat16* __restrict__ Bthi, const __nv_bfloat16* __restrict__ Btlo,
    __half* __restrict__ C, int Mr, int Nc, int Kd) {
    extern __shared__ __align__(16) char dsm[];
    const uint32_t sb = smem_u32(dsm);

    const int tid = threadIdx.x;
    const int wid = tid >> 5;
    const int lane = tid & 31;
    const int wm = wid >> 2;
    const int wn = wid & 3;
    const int bm = blockIdx.y * 128;
    const int bn = blockIdx.x * 128;

    const int CPS = Kd >> 6;
    const int NCH = 3 * CPS;

    const int lr = tid >> 1;
    const int lc = (tid & 1) * 4;
    const int gaRow = min(bm + lr, Mr - 1);
    const int gbRow = bn + lr;

    wmma::fragment<wmma::accumulator, 16, 16, 16, float> acc[4][2];
#pragma unroll
    for (int i = 0; i < 4; i++)
#pragma unroll
        for (int j = 0; j < 2; j++) wmma::fill_fragment(acc[i][j], 0.0f);

    auto issue = [&](int c) {
        int seg = c / CPS;
        int j = c - seg * CPS;
        const __nv_bfloat16* A = (seg == 1) ? Alo : Ahi;
        const __nv_bfloat16* B = (seg == 2) ? Btlo : Bthi;
        int koff = j << 6;
        int buf = c & 1;
        uint32_t abase = sb + (buf ? SM_A1 : SM_A0) + lr * 144;
        uint32_t bbase = sb + (buf ? SM_B1 : SM_B0) + lr * 144;
        const char* ap = (const char*)(A + (size_t)gaRow * Kd + koff);
        const char* bp = (const char*)(B + (size_t)gbRow * Kd + koff);
#pragma unroll
        for (int u = 0; u < 4; u++) {
            cp16(abase + (lc + u) * 16, ap + (lc + u) * 16);
            cp16(bbase + (lc + u) * 16, bp + (lc + u) * 16);
        }
        CP_COMMIT();
    };

    issue(0);
    for (int c = 0; c < NCH; c++) {
        if (c + 1 < NCH) { issue(c + 1); CP_WAIT1(); }
        else             { CP_WAIT0(); }
        __syncthreads();
        const int buf = c & 1;
        const __nv_bfloat16* As = (const __nv_bfloat16*)(dsm + (buf ? SM_A1 : SM_A0));
        const __nv_bfloat16* Bs = (const __nv_bfloat16*)(dsm + (buf ? SM_B1 : SM_B0));
#pragma unroll
        for (int kt = 0; kt < 4; kt++) {
            wmma::fragment<wmma::matrix_a, 16, 16, 16, __nv_bfloat16, wmma::row_major> af[4];
            wmma::fragment<wmma::matrix_b, 16, 16, 16, __nv_bfloat16, wmma::col_major> bf[2];
#pragma unroll
            for (int n = 0; n < 2; n++)
                wmma::load_matrix_sync(bf[n], Bs + (wn * 32 + n * 16) * APAD + kt * 16, APAD);
#pragma unroll
            for (int m = 0; m < 4; m++)
                wmma::load_matrix_sync(af[m], As + (wm * 64 + m * 16) * APAD + kt * 16, APAD);
#pragma unroll
            for (int m = 0; m < 4; m++)
#pragma unroll
                for (int n = 0; n < 2; n++)
                    wmma::mma_sync(acc[m][n], af[m], bf[n], acc[m][n]);
        }
        __syncthreads();
    }

    float* stg = (float*)(dsm + SM_STG) + wid * 256;
    const int srow = lane >> 1;
    const int scol = (lane & 1) * 8;
#pragma unroll
    for (int m = 0; m < 4; m++) {
#pragma unroll
        for (int n = 0; n < 2; n++) {
            wmma::store_matrix_sync(stg, acc[m][n], 16, wmma::mem_row_major);
            __syncwarp();
            int grow = bm + wm * 64 + m * 16 + srow;
            int gcol = bn + wn * 32 + n * 16 + scol;
            if (grow < Mr) {
                const float* sp = stg + srow * 16 + scol;
                __half* crow = C + (size_t)grow * Nc + gcol;
#pragma unroll
                for (int q = 0; q < 2; q++) {
                    float4 v = *(const float4*)(sp + q * 4);
                    ((__half2*)(crow + q * 4))[0] = __floats2half2_rn(v.x, v.y);
                    ((__half2*)(crow + q * 4))[1] = __floats2half2_rn(v.z, v.w);
                }
            }
            __syncwarp();
        }
    }
}

// ---------------- fp16 single-segment GEMM (fc path) ----------------
template <int MODE>
__global__ void __launch_bounds__(256) k_hgemm(
    const __half* __restrict__ A, const __half* __restrict__ Bt,
    float* __restrict__ C, int Mr, int Nc, int Kd, const float* __restrict__ bias) {
    extern __shared__ __align__(16) char dsm[];
    const uint32_t sb = smem_u32(dsm);

    const int tid = threadIdx.x;
    const int wid = tid >> 5;
    const int lane = tid & 31;
    const int wm = wid >> 2;
    const int wn = wid & 3;
    const int bm = blockIdx.y * 128;
    const int bn = blockIdx.x * 128;

    const int NCH = Kd >> 6;

    const int lr = tid >> 1;
    const int lc = (tid & 1) * 4;
    const int gaRow = min(bm + lr, Mr - 1);
    const int gbRow = bn + lr;

    wmma::fragment<wmma::accumulator, 16, 16, 16, float> acc[4][2];
#pragma unroll
    for (int i = 0; i < 4; i++)
#pragma unroll
        for (int j = 0; j < 2; j++) wmma::fill_fragment(acc[i][j], 0.0f);

    auto issue = [&](int c) {
        int koff = c << 6;
        int buf = c & 1;
        uint32_t abase = sb + (buf ? SM_A1 : SM_A0) + lr * 144;
        uint32_t bbase = sb + (buf ? SM_B1 : SM_B0) + lr * 144;
        const char* ap = (const char*)(A + (size_t)gaRow * Kd + koff);
        const char* bp = (const char*)(Bt + (size_t)gbRow * Kd + koff);
#pragma unroll
        for (int u = 0; u < 4; u++) {
            cp16(abase + (lc + u) * 16, ap + (lc + u) * 16);
            cp16(bbase + (lc + u) * 16, bp + (lc + u) * 16);
        }
        CP_COMMIT();
    };

    issue(0);
    for (int c = 0; c < NCH; c++) {
        if (c + 1 < NCH) { issue(c + 1); CP_WAIT1(); }
        else             { CP_WAIT0(); }
        __syncthreads();
        const int buf = c & 1;
        const __half* As = (const __half*)(dsm + (buf ? SM_A1 : SM_A0));
        const __half* Bs = (const __half*)(dsm + (buf ? SM_B1 : SM_B0));
#pragma unroll
        for (int kt = 0; kt < 4; kt++) {
            wmma::fragment<wmma::matrix_a, 16, 16, 16, __half, wmma::row_major> af[4];
            wmma::fragment<wmma::matrix_b, 16, 16, 16, __half, wmma::col_major> bf[2];
#pragma unroll
            for (int n = 0; n < 2; n++)
                wmma::load_matrix_sync(bf[n], Bs + (wn * 32 + n * 16) * APAD + kt * 16, APAD);
#pragma unroll
            for (int m = 0; m < 4; m++)
                wmma::load_matrix_sync(af[m], As + (wm * 64 + m * 16) * APAD + kt * 16, APAD);
#pragma unroll
            for (int m = 0; m < 4; m++)
#pragma unroll
                for (int n = 0; n < 2; n++)
                    wmma::mma_sync(acc[m][n], af[m], bf[n], acc[m][n]);
        }
        __syncthreads();
    }

    float* stg = (float*)(dsm + SM_STG) + wid * 256;
    const int srow = lane >> 1;
    const int scol = (lane & 1) * 8;
#pragma unroll
    for (int m = 0; m < 4; m++) {
#pragma unroll
        for (int n = 0; n < 2; n++) {
            wmma::store_matrix_sync(stg, acc[m][n], 16, wmma::mem_row_major);
            __syncwarp();
            int grow = bm + wm * 64 + m * 16 + srow;
            int gcol = bn + wn * 32 + n * 16 + scol;
            if (grow < Mr) {
                const float* sp = stg + srow * 16 + scol;
                float* crow = C + (size_t)grow * Nc + gcol;
#pragma unroll
                for (int q = 0; q < 2; q++) {
                    float4 v = *(const float4*)(sp + q * 4);
                    float4 bb = *(const float4*)(bias + gcol + q * 4);
                    v.x += bb.x; v.y += bb.y; v.z += bb.z; v.w += bb.w;
                    v.x = (v.x > 0.f) ? v.x : NEG_SLOPE * v.x;
                    v.y = (v.y > 0.f) ? v.y : NEG_SLOPE * v.y;
                    v.z = (v.z > 0.f) ? v.z : NEG_SLOPE * v.z;
                    v.w = (v.w > 0.f) ? v.w : NEG_SLOPE * v.w;
                    if (MODE == 2) {
                        float4 o = *(const float4*)(crow + q * 4);
                        v.x += o.x; v.y += o.y; v.z += o.z; v.w += o.w;
                    }
                    *(float4*)(crow + q * 4) = v;
                }
            }
            __syncwarp();
        }
    }
}

// ---------------- conversions ----------------
__global__ void k_wsplit(const float* __restrict__ W, __nv_bfloat16* __restrict__ thi,
                         __nv_bfloat16* __restrict__ tlo, int K, int N) {
    int i = blockIdx.x * blockDim.x + threadIdx.x;
    if (i >= K * N) return;
    int n = i / K, k = i - n * K;
    float v = W[(size_t)k * N + n];
    __nv_bfloat16 h = __float2bfloat16(v);
    thi[i] = h;
    tlo[i] = __float2bfloat16(v - __bfloat162float(h));
}

__global__ void k_wsplit16(const float* __restrict__ W, __half* __restrict__ t16, int K, int N) {
    int i = blockIdx.x * blockDim.x + threadIdx.x;
    if (i >= K * N) return;
    int n = i / K, k = i - n * K;
    t16[i] = __float2half(W[(size_t)k * N + n]);
}

__global__ void k_tof16(const float* __restrict__ X, __half* __restrict__ Y, int total4) {
    int i = blockIdx.x * blockDim.x + threadIdx.x;
    if (i >= total4) return;
    float4 v = ((const float4*)X)[i];
    ((__half2*)Y)[i * 2]     = __floats2half2_rn(v.x, v.y);
    ((__half2*)Y)[i * 2 + 1] = __floats2half2_rn(v.z, v.w);
}

// ---------------- structure kernels ----------------
__global__ void k_zero2(int* a, int na, int* b, int nb) {
    int i = blockIdx.x * blockDim.x + threadIdx.x;
    if (i < na) a[i] = 0;
    else if (i < na + nb) b[i - na] = 0;
}

__global__ void k_hist(const int* __restrict__ row, const int* __restrict__ col,
                       int* degn, int* dege, int E) {
    int i = blockIdx.x * blockDim.x + threadIdx.x;
    if (i < E) {
        atomicAdd(&degn[row[i]], 1);
        atomicAdd(&dege[col[i]], 1);
    }
}

__global__ void k_bsum(const int* __restrict__ cnt, int* __restrict__ bsum, int n) {
    int b = blockIdx.x, t = threadIdx.x;
    int base = b * 1024;
    int s = 0;
#pragma unroll
    for (int u = 0; u < 4; u++) {
        int i = base + t + u * 256;
        if (i < n) s += cnt[i];
    }
    __shared__ int red[8];
    for (int o = 16; o; o >>= 1) s += __shfl_down_sync(0xffffffffu, s, o);
    if ((t & 31) == 0) red[t >> 5] = s;
    __syncthreads();
    if (t == 0) {
        int v = 0;
#pragma unroll
        for (int w = 0; w < 8; w++) v += red[w];
        bsum[b] = v;
    }
}

__global__ void k_bscan(int* bsum, int nb) {
    if (threadIdx.x == 0) {
        int run = 0;
        for (int i = 0; i < nb; i++) { int v = bsum[i]; bsum[i] = run; run += v; }
        bsum[nb] = run;
    }
}

__global__ void k_lscan(const int* __restrict__ cnt, const int* __restrict__ bsum,
                        int* __restrict__ start, int* __restrict__ cur, int n, int nb) {
    int b = blockIdx.x, t = threadIdx.x;
    __shared__ int sh[256];
    int base = b * 1024;
    int v[4];
    int s = 0;
#pragma unroll
    for (int u = 0; u < 4; u++) {
        int i = base + t * 4 + u;
        v[u] = (i < n) ? cnt[i] : 0;
        s += v[u];
    }
    sh[t] = s;
    __syncthreads();
    for (int o = 1; o < 256; o <<= 1) {
        int a = (t >= o) ? sh[t - o] : 0;
        __syncthreads();
        sh[t] += a;
        __syncthreads();
    }
    int run = bsum[b] + ((t == 0) ? 0 : sh[t - 1]);
#pragma unroll
    for (int u = 0; u < 4; u++) {
        int i = base + t * 4 + u;
        if (i < n) { start[i] = run; cur[i] = run; run += v[u]; }
    }
    if (b == 0 && t == 0) start[n] = bsum[nb];
}

__global__ void k_scatter(const int* __restrict__ row, const int* __restrict__ col,
                          int* rcur, int* ccur, int* __restrict__ rcsr,
                          int* __restrict__ ccsr, int E) {
    int i = blockIdx.x * blockDim.x + threadIdx.x;
    if (i < E) {
        int pr = atomicAdd(&rcur[row[i]], 1);
        rcsr[pr] = i;
        int pc = atomicAdd(&ccur[col[i]], 1);
        ccsr[pc] = i;
    }
}

__global__ void k_inv2(const int* __restrict__ da, float* __restrict__ ia, int na,
                       const int* __restrict__ db, float* __restrict__ ib, int nb) {
    int i = blockIdx.x * blockDim.x + threadIdx.x;
    if (i < na) {
        int d = da[i];
        ia[i] = (d > 0) ? (1.0f / (float)d) : 0.0f;
    } else if (i < na + nb) {
        int d = db[i - na];
        ib[i - na] = (d > 0) ? (1.0f / (float)d) : 0.0f;
    }
}

// ---------------- row dots ----------------
__global__ void k_rowdot(const float* __restrict__ X, const float* __restrict__ v,
                         float* __restrict__ out, int rows) {
    int gw = (blockIdx.x * blockDim.x + threadIdx.x) >> 5;
    int lane = threadIdx.x & 31;
    if (gw >= rows) return;
    const float4* xr = (const float4*)(X + (size_t)gw * FF);
    const float4* vv = (const float4*)v;
    float s = 0.f;
#pragma unroll
    for (int j = 0; j < 4; j++) {
        float4 a = xr[lane + 32 * j];
        float4 b = vv[lane + 32 * j];
        s += a.x * b.x + a.y * b.y + a.z * b.z + a.w * b.w;
    }
    for (int o = 16; o; o >>= 1) s += __shfl_down_sync(0xffffffffu, s, o);
    if (!lane) out[gw] = s;
}

__global__ void k_rowdot2(const float* __restrict__ X, const float* __restrict__ v1,
                          const float* __restrict__ v2, float* __restrict__ o1,
                          float* __restrict__ o2, int rows) {
    int gw = (blockIdx.x * blockDim.x + threadIdx.x) >> 5;
    int lane = threadIdx.x & 31;
    if (gw >= rows) return;
    const float4* xr = (const float4*)(X + (size_t)gw * FF);
    const float4* va = (const float4*)v1;
    const float4* vb = (const float4*)v2;
    float s1 = 0.f, s2 = 0.f;
#pragma unroll
    for (int j = 0; j < 4; j++) {
        float4 a = xr[lane + 32 * j];
        float4 b = va[lane + 32 * j];
        float4 c = vb[lane + 32 * j];
        s1 += a.x * b.x + a.y * b.y + a.z * b.z + a.w * b.w;
        s2 += a.x * c.x + a.y * c.y + a.z * c.z + a.w * c.w;
    }
    for (int o = 16; o; o >>= 1) {
        s1 += __shfl_down_sync(0xffffffffu, s1, o);
        s2 += __shfl_down_sync(0xffffffffu, s2, o);
    }
    if (!lane) { o1[gw] = s1; o2[gw] = s2; }
}

// ---------------- fused attention softmax + propagate-1 (fp16 gather, unroll 8) ----------------
__global__ void __launch_bounds__(256) k_attnprop(
    const int* __restrict__ cstart, const int* __restrict__ ccsr,
    const int* __restrict__ row, const float* __restrict__ xn,
    const float* __restrict__ en, const float* __restrict__ Binv,
    const __half* __restrict__ X, float* __restrict__ alpha,
    __nv_bfloat16* __restrict__ efhi, __nv_bfloat16* __restrict__ eflo) {
    int m = blockIdx.x;
    int s = cstart[m], e = cstart[m + 1];
    int tid = threadIdx.x;
    __shared__ float red[256];
    __shared__ int   shr[256];
    __shared__ float shc[256];

    float enm = en[m];
    float mx = -3.0e38f;
    for (int i = s + tid; i < e; i += 256) {
        int ed = ccsr[i];
        float p = xn[row[ed]] + enm;
        p = (p > 0.f) ? p : ATT_SLOPE * p;
        alpha[ed] = p;
        mx = fmaxf(mx, p);
    }
    red[tid] = mx;
    __syncthreads();
    for (int o = 128; o; o >>= 1) {
        if (tid < o) red[tid] = fmaxf(red[tid], red[tid + o]);
        __syncthreads();
    }
    float amax = red[0];
    if (!(amax > -1e37f)) amax = 0.f;
    __syncthreads();
    float sm = 0.f;
    for (int i = s + tid; i < e; i += 256) {
        int ed = ccsr[i];
        float ex = expf(alpha[ed] - amax);
        alpha[ed] = ex;
        sm += ex;
    }
    red[tid] = sm;
    __syncthreads();
    for (int o = 128; o; o >>= 1) {
        if (tid < o) red[tid] += red[tid + o];
        __syncthreads();
    }
    float inv = 1.f / fmaxf(red[0], 1e-16f);
    float bi = Binv[m];
    float ax = 0.f, ay = 0.f;
    const __half2* base = (const __half2*)X + tid;
    for (int b0 = s; b0 < e; b0 += 256) {
        int cnt = min(256, e - b0);
        __syncthreads();
        if (tid < cnt) {
            int ed = ccsr[b0 + tid];
            float a = alpha[ed] * inv;
            alpha[ed] = a;
            shr[tid] = row[ed];
            shc[tid] = a * bi;
        }
        __syncthreads();
        int j = 0;
        for (; j + 8 <= cnt; j += 8) {
            float2 v0 = __half22float2(base[(size_t)shr[j]     * (FF / 2)]);
            float2 v1 = __half22float2(base[(size_t)shr[j + 1] * (FF / 2)]);
            float2 v2 = __half22float2(base[(size_t)shr[j + 2] * (FF / 2)]);
            float2 v3 = __half22float2(base[(size_t)shr[j + 3] * (FF / 2)]);
            float2 v4 = __half22float2(base[(size_t)shr[j + 4] * (FF / 2)]);
            float2 v5 = __half22float2(base[(size_t)shr[j + 5] * (FF / 2)]);
            float2 v6 = __half22float2(base[(size_t)shr[j + 6] * (FF / 2)]);
            float2 v7 = __half22float2(base[(size_t)shr[j + 7] * (FF / 2)]);
            ax += shc[j] * v0.x + shc[j + 1] * v1.x + shc[j + 2] * v2.x + shc[j + 3] * v3.x
                + shc[j + 4] * v4.x + shc[j + 5] * v5.x + shc[j + 6] * v6.x + shc[j + 7] * v7.x;
            ay += shc[j] * v0.y + shc[j + 1] * v1.y + shc[j + 2] * v2.y + shc[j + 3] * v3.y
                + shc[j + 4] * v4.y + shc[j + 5] * v5.y + shc[j + 6] * v6.y + shc[j + 7] * v7.y;
        }
        for (; j < cnt; j++) {
            float2 v = __half22float2(base[(size_t)shr[j] * (FF / 2)]);
            float cf = shc[j];
            ax += cf * v.x;
            ay += cf * v.y;
        }
    }
    __nv_bfloat16 hx = __float2bfloat16(ax), hy = __float2bfloat16(ay);
    __nv_bfloat16 lx = __float2bfloat16(ax - __bfloat162float(hx));
    __nv_bfloat16 ly = __float2bfloat16(ay - __bfloat162float(hy));
    ((__nv_bfloat162*)(efhi + (size_t)m * FF))[tid] = __nv_bfloat162(hx, hy);
    ((__nv_bfloat162*)(eflo + (size_t)m * FF))[tid] = __nv_bfloat162(lx, ly);
}

// ---------------- propagate-2 (fp16 gather, unrolled x4) ----------------
__global__ void k_prop2(const int* __restrict__ rstart, const int* __restrict__ rcsr,
                        const int* __restrict__ col, const float* __restrict__ alpha,
                        const float* __restrict__ Dinv, const __half* __restrict__ ef,
                        const float* __restrict__ bias, float* __restrict__ out) {
    int n = blockIdx.x;
    int s = rstart[n], e = rstart[n + 1];
    int tid = threadIdx.x;
    float a0 = 0.f, a1 = 0.f, a2 = 0.f, a3 = 0.f;
    const uint2* base = (const uint2*)ef + tid;
    int i = s;
    for (; i + 4 <= e; i += 4) {
        int e0 = rcsr[i], e1 = rcsr[i + 1], e2 = rcsr[i + 2], e3 = rcsr[i + 3];
        float c0 = alpha[e0], c1 = alpha[e1], c2 = alpha[e2], c3 = alpha[e3];
        uint2 u0 = base[(size_t)col[e0] * (FF / 4)];
        uint2 u1 = base[(size_t)col[e1] * (FF / 4)];
        uint2 u2 = base[(size_t)col[e2] * (FF / 4)];
        uint2 u3 = base[(size_t)col[e3] * (FF / 4)];
        float2 p0a = __half22float2(*(const __half2*)&u0.x);
        float2 p0b = __half22float2(*(const __half2*)&u0.y);
        float2 p1a = __half22float2(*(const __half2*)&u1.x);
        float2 p1b = __half22float2(*(const __half2*)&u1.y);
        float2 p2a = __half22float2(*(const __half2*)&u2.x);
        float2 p2b = __half22float2(*(const __half2*)&u2.y);
        float2 p3a = __half22float2(*(const __half2*)&u3.x);
        float2 p3b = __half22float2(*(const __half2*)&u3.y);
        a0 += c0 * p0a.x + c1 * p1a.x + c2 * p2a.x + c3 * p3a.x;
        a1 += c0 * p0a.y + c1 * p1a.y + c2 * p2a.y + c3 * p3a.y;
        a2 += c0 * p0b.x + c1 * p1b.x + c2 * p2b.x + c3 * p3b.x;
        a3 += c0 * p0b.y + c1 * p1b.y + c2 * p2b.y + c3 * p3b.y;
    }
    for (; i < e; i++) {
        int ed = rcsr[i];
        float cf = alpha[ed];
        uint2 u = base[(size_t)col[ed] * (FF / 4)];
        float2 pa = __half22float2(*(const __half2*)&u.x);
        float2 pb = __half22float2(*(const __half2*)&u.y);
        a0 += cf * pa.x; a1 += cf * pa.y; a2 += cf * pb.x; a3 += cf * pb.y;
    }
    float d = Dinv[n];
    float4 b = *(const float4*)(bias + 4 * tid);
    float4 o;
    o.x = a0 * d + b.x; o.y = a1 * d + b.y; o.z = a2 * d + b.z; o.w = a3 * d + b.w;
    *(float4*)(out + (size_t)n * FF + 4 * tid) = o;
}

// ---------------- graph norm ----------------
__global__ void k_colstat(const float* __restrict__ X, float* __restrict__ p1,
                          float* __restrict__ p2, int rows) {
    int b = blockIdx.x;
    int c = threadIdx.x;
    int r0 = b * CSTAT_ROWS, r1 = min(r0 + CSTAT_ROWS, rows);
    float s1 = 0.f, s2 = 0.f;
    for (int r = r0; r < r1; r++) {
        float v = X[(size_t)r * FF + c];
        s1 += v;
        s2 += v * v;
    }
    p1[b * FF + c] = s1;
    p2[b * FF + c] = s2;
}

__global__ void k_statfin(const float* __restrict__ p1, const float* __restrict__ p2,
                          int nblk, const float* __restrict__ w,
                          const float* __restrict__ ms, float* __restrict__ shift,
                          float* __restrict__ scale, float rows_inv) {
    int c = threadIdx.x;
    float s1 = 0.f, s2 = 0.f;
    for (int i = 0; i < nblk; i++) {
        s1 += p1[i * FF + c];
        s2 += p2[i * FF + c];
    }
    float mu = s1 * rows_inv;
    float ex2 = s2 * rows_inv;
    float m = ms[c];
    float sh = m * mu;
    float var = ex2 - sh * (2.f * mu - sh);
    shift[c] = sh;
    scale[c] = w[c] / sqrtf(var + 1e-5f);
}

// graph_norm apply + leaky_relu, block-per-row: fp32 out + fp16 copy + optional fused dot
__global__ void __launch_bounds__(128) k_normfuse(
    const float* __restrict__ X, const float* __restrict__ shift,
    const float* __restrict__ scale, const float* __restrict__ beta,
    const float* __restrict__ wdot, float* __restrict__ Yf,
    __half* __restrict__ y16, float* __restrict__ xnout) {
    int n = blockIdx.x;
    int t = threadIdx.x;          // 128 threads * 4 cols
    int c = t * 4;
    float4 v = *(const float4*)(X + (size_t)n * FF + c);
    float4 sh = *(const float4*)(shift + c);
    float4 sc = *(const float4*)(scale + c);
    float4 be = *(const float4*)(beta + c);
    float y0 = (v.x - sh.x) * sc.x + be.x;
    float y1 = (v.y - sh.y) * sc.y + be.y;
    float y2 = (v.z - sh.z) * sc.z + be.z;
    float y3 = (v.w - sh.w) * sc.w + be.w;
    y0 = (y0 > 0.f) ? y0 : NEG_SLOPE * y0;
    y1 = (y1 > 0.f) ? y1 : NEG_SLOPE * y1;
    y2 = (y2 > 0.f) ? y2 : NEG_SLOPE * y2;
    y3 = (y3 > 0.f) ? y3 : NEG_SLOPE * y3;
    *(float4*)(Yf + (size_t)n * FF + c) = make_float4(y0, y1, y2, y3);
    __half2* y2p = (__half2*)(y16 + (size_t)n * FF + c);
    y2p[0] = __floats2half2_rn(y0, y1);
    y2p[1] = __floats2half2_rn(y2, y3);
    if (xnout) {
        float4 w = *(const float4*)(wdot + c);
        float d = y0 * w.x + y1 * w.y + y2 * w.z + y3 * w.w;
        __shared__ float red[128];
        red[t] = d;
        __syncthreads();
        for (int o = 64; o; o >>= 1) {
            if (t < o) red[t] += red[t + o];
            __syncthreads();
        }
        if (t == 0) xnout[n] = red[0];
    }
}

__global__ void k_cls(const float* __restrict__ A, const float* __restrict__ W,
                      const float* __restrict__ b, float* __restrict__ out, int rows) {
    int gw = (blockIdx.x * blockDim.x + threadIdx.x) >> 5;
    int lane = threadIdx.x & 31;
    if (gw >= rows) return;
    const float* ar = A + (size_t)gw * HIDD;
    float s0 = 0.f, s1 = 0.f;
    for (int h = lane; h < HIDD; h += 32) {
        float v = ar[h];
        s0 += v * W[h * 2];
        s1 += v * W[h * 2 + 1];
    }
    for (int o = 16; o; o >>= 1) {
        s0 += __shfl_down_sync(0xffffffffu, s0, o);
        s1 += __shfl_down_sync(0xffffffffu, s1, o);
    }
    if (!lane) {
        out[gw * 2] = s0 + b[0];
        out[gw * 2 + 1] = s1 + b[1];
    }
}

// ---------------- host launch ----------------
extern "C" void kernel_launch(void* const* d_in, const int* in_sizes, int n_in,
                              void* d_out, int out_size) {
    const float* x    = (const float*)d_in[0];
    const int*   ei   = (const int*)d_in[1];
    const float* ea   = (const float*)d_in[2];
    const float* W1   = (const float*)d_in[3];
    const float* att1 = (const float*)d_in[4];
    const float* b1   = (const float*)d_in[5];
    const float* W2   = (const float*)d_in[6];
    const float* att2 = (const float*)d_in[7];
    const float* b2   = (const float*)d_in[8];
    const float* gn1w = (const float*)d_in[9];
    const float* gn1b = (const float*)d_in[10];
    const float* gn1ms= (const float*)d_in[11];
    const float* gn2w = (const float*)d_in[12];
    const float* gn2b = (const float*)d_in[13];
    const float* gn2ms= (const float*)d_in[14];
    const float* fc1W = (const float*)d_in[15];
    const float* fc1b = (const float*)d_in[16];
    const float* fc2W = (const float*)d_in[17];
    const float* fc2b = (const float*)d_in[18];
    const float* clsW = (const float*)d_in[19];
    const float* clsb = (const float*)d_in[20];
    float* outp = (float*)d_out;

    const int* row = ei;
    const int* col = ei + EE;

    float *xl, *h, *fc, *xn, *en1, *en2, *wa1, *wb1, *wa2, *wb2, *alpha, *Dinv, *Binv;
    float *p1, *p2, *shift, *scale;
    int *degn, *dege, *rstart, *cstart, *rcur, *ccur, *rcsr, *ccsr, *bsumN, *bsumM;
    __half *elb, *h16, *f1t16, *f2t16;
    __nv_bfloat16 *eahi, *ealo, *W1thi, *W1tlo, *W2thi, *W2tlo;
    cudaGetSymbolAddress((void**)&xl, g_xl);
    cudaGetSymbolAddress((void**)&elb, g_elb);
    cudaGetSymbolAddress((void**)&h, g_h);
    cudaGetSymbolAddress((void**)&h16, g_h16);
    cudaGetSymbolAddress((void**)&fc, g_fc);
    cudaGetSymbolAddress((void**)&xn, g_xn);
    cudaGetSymbolAddress((void**)&en1, g_en1);
    cudaGetSymbolAddress((void**)&en2, g_en2);
    cudaGetSymbolAddress((void**)&wa1, g_wa1);
    cudaGetSymbolAddress((void**)&wb1, g_wb1);
    cudaGetSymbolAddress((void**)&wa2, g_wa2);
    cudaGetSymbolAddress((void**)&wb2, g_wb2);
    cudaGetSymbolAddress((void**)&alpha, g_alpha);
    cudaGetSymbolAddress((void**)&Dinv, g_Dinv);
    cudaGetSymbolAddress((void**)&Binv, g_Binv);
    cudaGetSymbolAddress((void**)&p1, g_p1);
    cudaGetSymbolAddress((void**)&p2, g_p2);
    cudaGetSymbolAddress((void**)&shift, g_shift);
    cudaGetSymbolAddress((void**)&scale, g_scale);
    cudaGetSymbolAddress((void**)&degn, g_degn);
    cudaGetSymbolAddress((void**)&dege, g_dege);
    cudaGetSymbolAddress((void**)&rstart, g_rstart);
    cudaGetSymbolAddress((void**)&cstart, g_cstart);
    cudaGetSymbolAddress((void**)&rcur, g_rcur);
    cudaGetSymbolAddress((void**)&ccur, g_ccur);
    cudaGetSymbolAddress((void**)&rcsr, g_rcsr);
    cudaGetSymbolAddress((void**)&ccsr, g_ccsr);
    cudaGetSymbolAddress((void**)&bsumN, g_bsumN);
    cudaGetSymbolAddress((void**)&bsumM, g_bsumM);
    cudaGetSymbolAddress((void**)&eahi, g_eahi);
    cudaGetSymbolAddress((void**)&ealo, g_ealo);
    cudaGetSymbolAddress((void**)&W1thi, g_W1thi);
    cudaGetSymbolAddress((void**)&W1tlo, g_W1tlo);
    cudaGetSymbolAddress((void**)&W2thi, g_W2thi);
    cudaGetSymbolAddress((void**)&W2tlo, g_W2tlo);
    cudaGetSymbolAddress((void**)&f1t16, g_f1t16);
    cudaGetSymbolAddress((void**)&f2t16, g_f2t16);

    static cudaStream_t s1 = nullptr;
    static cudaEvent_t evFork = nullptr, evJoin1 = nullptr, evFork2 = nullptr, evJoin2 = nullptr;
    static bool init_done = false;
    if (!init_done) {
        cudaFuncSetAttribute(k_wgemm0, cudaFuncAttributeMaxDynamicSharedMemorySize, GEMM_SMEM);
        cudaFuncSetAttribute(k_hgemm<1>, cudaFuncAttributeMaxDynamicSharedMemorySize, GEMM_SMEM);
        cudaFuncSetAttribute(k_hgemm<2>, cudaFuncAttributeMaxDynamicSharedMemorySize, GEMM_SMEM);
        cudaStreamCreateWithFlags(&s1, cudaStreamNonBlocking);
        cudaEventCreateWithFlags(&evFork, cudaEventDisableTiming);
        cudaEventCreateWithFlags(&evJoin1, cudaEventDisableTiming);
        cudaEventCreateWithFlags(&evFork2, cudaEventDisableTiming);
        cudaEventCreateWithFlags(&evJoin2, cudaEventDisableTiming);
        init_done = true;
    }

    const int NBN = (NN + 1023) / 1024;
    const int NBM = (MM + 1023) / 1024;
    const float rows_inv = 1.0f / (float)NN;
    dim3 gM(FF / 128, MM / 128);
    dim3 gFC(HIDD / 128, (NN + 127) / 128);

    // ---- fork: s1 joins capture ----
    cudaEventRecord(evFork, 0);
    cudaStreamWaitEvent(s1, evFork, 0);

    // ---- s0: graph structure chain ----
    k_zero2<<<(NN + MM + 255) / 256, 256>>>(degn, NN, dege, MM);
    k_hist<<<(EE + 255) / 256, 256>>>(row, col, degn, dege, EE);
    k_bsum<<<NBM, 256>>>(dege, bsumM, MM);
    k_bsum<<<NBN, 256>>>(degn, bsumN, NN);
    k_bscan<<<1, 32>>>(bsumM, NBM);
    k_bscan<<<1, 32>>>(bsumN, NBN);
    k_lscan<<<NBM, 256>>>(dege, bsumM, cstart, ccur, MM, NBM);
    k_lscan<<<NBN, 256>>>(degn, bsumN, rstart, rcur, NN, NBN);
    k_scatter<<<(EE + 255) / 256, 256>>>(row, col, rcur, ccur, rcsr, ccsr, EE);
    k_inv2<<<(NN + MM + 255) / 256, 256>>>(degn, Dinv, NN, dege, Binv, MM);

    // ---- s1 (parallel): conversions + ALL weight-only projections + conv1 pre-dots ----
    k_wsplit<<<(FF * FF + 255) / 256, 256, 0, s1>>>(W1, W1thi, W1tlo, FF, FF);
    k_wsplit<<<(FF * FF + 255) / 256, 256, 0, s1>>>(W2, W2thi, W2tlo, FF, FF);
    k_wsplit16<<<(FF * HIDD + 255) / 256, 256, 0, s1>>>(fc1W, f1t16, FF, HIDD);
    k_wsplit16<<<(FF * HIDD + 255) / 256, 256, 0, s1>>>(fc2W, f2t16, FF, HIDD);
    k_tof16<<<(NN * (FF / 4) + 255) / 256, 256, 0, s1>>>(x, h16, NN * (FF / 4));
    k_rowdot2<<<(FF * 32 + 255) / 256, 256, 0, s1>>>(W1, att1, att1 + FF, wa1, wb1, FF);
    k_rowdot2<<<(FF * 32 + 255) / 256, 256, 0, s1>>>(W2, att2, att2 + FF, wa2, wb2, FF);
    k_rowdot<<<(NN * 32 + 255) / 256, 256, 0, s1>>>(x, wa1, xn, NN);
    k_rowdot<<<(MM * 32 + 255) / 256, 256, 0, s1>>>(ea, wb1, en1, MM);
    k_rowdot<<<(MM * 32 + 255) / 256, 256, 0, s1>>>(ea, wb2, en2, MM);
    cudaEventRecord(evJoin1, s1);
    cudaStreamWaitEvent(0, evJoin1, 0);

    // ==== conv1 (s0) ====
    k_attnprop<<<MM, 256>>>(cstart, ccsr, row, xn, en1, Binv, h16, alpha, eahi, ealo);
    k_wgemm0<<<gM, 256, GEMM_SMEM>>>(eahi, ealo, W1thi, W1tlo, elb, MM, FF, FF);
    k_prop2<<<NN, 128>>>(rstart, rcsr, col, alpha, Dinv, elb, b1, xl);
    k_colstat<<<CSTAT_BLKS, FF>>>(xl, p1, p2, NN);
    k_statfin<<<1, FF>>>(p1, p2, CSTAT_BLKS, gn1w, gn1ms, shift, scale, rows_inv);
    // normsplit1 + fused xn = h · wa2 (for conv2 attention)
    k_normfuse<<<NN, 128>>>(xl, shift, scale, gn1b, wa2, h, h16, xn);

    // ---- fork 2: fc1 GEMM on s1 (reads h16), conv2 front on s0 ----
    cudaEventRecord(evFork2, 0);
    cudaStreamWaitEvent(s1, evFork2, 0);
    k_hgemm<1><<<gFC, 256, GEMM_SMEM, s1>>>(h16, f1t16, fc, NN, HIDD, FF, fc1b);

    // ==== conv2 front (s0) ====
    k_attnprop<<<MM, 256>>>(cstart, ccsr, row, xn, en2, Binv, h16, alpha, eahi, ealo);
    k_wgemm0<<<gM, 256, GEMM_SMEM>>>(eahi, ealo, W2thi, W2tlo, elb, MM, FF, FF);
    k_prop2<<<NN, 128>>>(rstart, rcsr, col, alpha, Dinv, elb, b2, xl);
    k_colstat<<<CSTAT_BLKS, FF>>>(xl, p1, p2, NN);
    k_statfin<<<1, FF>>>(p1, p2, CSTAT_BLKS, gn2w, gn2ms, shift, scale, rows_inv);

    // join: fc1 must finish before normfuse2 overwrites h16 (and before fc2 reads fc)
    cudaEventRecord(evJoin2, s1);
    cudaStreamWaitEvent(0, evJoin2, 0);
    k_normfuse<<<NN, 128>>>(xl, shift, scale, gn2b, wa2, h, h16, nullptr);
    k_hgemm<2><<<gFC, 256, GEMM_SMEM>>>(h16, f2t16, fc, NN, HIDD, FF, fc2b);

    // ---- classifier ----
    k_cls<<<(NN * 32 + 255) / 256, 256>>>(fc, clsW, clsb, outp, NN);
}

// round 14
// speedup vs baseline: 3.0412x; 1.0085x over previous
#include <cuda_runtime.h>
#include <cuda_bf16.h>
#include <cuda_fp16.h>
#include <mma.h>
#include <cstdint>
#include <math.h>

using namespace nvcuda;

#define NN 20000
#define MM 2048
#define EE 320000
#define FF 512
#define HIDD 256
#define CSTAT_ROWS 128
#define CSTAT_BLKS ((NN + CSTAT_ROWS - 1) / CSTAT_ROWS)   // 157

#define NEG_SLOPE 0.01f
#define ATT_SLOPE 0.2f

// ---------------- scratch ----------------
__device__ float g_xl[NN * FF];         // conv output pre-norm (fp32 — MUST stay fp32, see R13)
__device__ __half g_elb[MM * FF];
__device__ __half g_h16[NN * FF];
__device__ float g_fc[NN * HIDD];
__device__ float g_xn[NN];
__device__ float g_en1[MM];
__device__ float g_en2[MM];
__device__ float g_wa1[FF];
__device__ float g_wb1[FF];
__device__ float g_wa2[FF];
__device__ float g_wb2[FF];
__device__ float g_alpha[EE];
__device__ float g_Dinv[NN];
__device__ float g_Binv[MM];
__device__ int   g_degn[NN];
__device__ int   g_dege[MM];
__device__ int   g_rstart[NN + 1];
__device__ int   g_cstart[MM + 1];
__device__ int   g_rcur[NN];
__device__ int   g_ccur[MM];
__device__ int   g_rcsr[EE];
__device__ int   g_ccsr[EE];
__device__ int   g_bsumN[32];
__device__ int   g_bsumM[8];
__device__ float g_p1[CSTAT_BLKS * FF];
__device__ float g_p2[CSTAT_BLKS * FF];
__device__ float g_shift[FF];
__device__ float g_scale[FF];
__device__ __nv_bfloat16 g_eahi[MM * FF];
__device__ __nv_bfloat16 g_ealo[MM * FF];
__device__ __nv_bfloat16 g_W1thi[FF * FF];
__device__ __nv_bfloat16 g_W1tlo[FF * FF];
__device__ __nv_bfloat16 g_W2thi[FF * FF];
__device__ __nv_bfloat16 g_W2tlo[FF * FF];
__device__ __half g_f1t16[HIDD * FF];
__device__ __half g_f2t16[HIDD * FF];

// ---------------- cp.async helpers ----------------
__device__ __forceinline__ uint32_t smem_u32(const void* p) {
    uint32_t a;
    asm("{ .reg .u64 t; cvta.to.shared.u64 t, %1; cvt.u32.u64 %0, t; }" : "=r"(a) : "l"(p));
    return a;
}
__device__ __forceinline__ void cp16(uint32_t dst, const void* src) {
    asm volatile("cp.async.ca.shared.global [%0], [%1], 16;" :: "r"(dst), "l"(src));
}
#define CP_COMMIT() asm volatile("cp.async.commit_group;" ::: "memory")
#define CP_WAIT1()  asm volatile("cp.async.wait_group 1;" ::: "memory")
#define CP_WAIT0()  asm volatile("cp.async.wait_group 0;" ::: "memory")

#define APAD 72
#define SM_A0 0
#define SM_B0 18432
#define SM_A1 36864
#define SM_B1 55296
#define SM_STG 73728
#define GEMM_SMEM 81920

// ---------------- cp.async double-buffered wmma split-bf16 GEMM (ef path) ----------------
__global__ void __launch_bounds__(256) k_wgemm0(
    const __nv_bfloat16* __restrict__ Ahi, const __nv_bfloat16* __restrict__ Alo,
    const __nv_bfloat16* __restrict__ Bthi, const __nv_bfloat16* __restrict__ Btlo,
    __half* __restrict__ C, int Mr, int Nc, int Kd) {
    extern __shared__ __align__(16) char dsm[];
    const uint32_t sb = smem_u32(dsm);

    const int tid = threadIdx.x;
    const int wid = tid >> 5;
    const int lane = tid & 31;
    const int wm = wid >> 2;
    const int wn = wid & 3;
    const int bm = blockIdx.y * 128;
    const int bn = blockIdx.x * 128;

    const int CPS = Kd >> 6;
    const int NCH = 3 * CPS;

    const int lr = tid >> 1;
    const int lc = (tid & 1) * 4;
    const int gaRow = min(bm + lr, Mr - 1);
    const int gbRow = bn + lr;

    wmma::fragment<wmma::accumulator, 16, 16, 16, float> acc[4][2];
#pragma unroll
    for (int i = 0; i < 4; i++)
#pragma unroll
        for (int j = 0; j < 2; j++) wmma::fill_fragment(acc[i][j], 0.0f);

    auto issue = [&](int c) {
        int seg = c / CPS;
        int j = c - seg * CPS;
        const __nv_bfloat16* A = (seg == 1) ? Alo : Ahi;
        const __nv_bfloat16* B = (seg == 2) ? Btlo : Bthi;
        int koff = j << 6;
        int buf = c & 1;
        uint32_t abase = sb + (buf ? SM_A1 : SM_A0) + lr * 144;
        uint32_t bbase = sb + (buf ? SM_B1 : SM_B0) + lr * 144;
        const char* ap = (const char*)(A + (size_t)gaRow * Kd + koff);
        const char* bp = (const char*)(B + (size_t)gbRow * Kd + koff);
#pragma unroll
        for (int u = 0; u < 4; u++) {
            cp16(abase + (lc + u) * 16, ap + (lc + u) * 16);
            cp16(bbase + (lc + u) * 16, bp + (lc + u) * 16);
        }
        CP_COMMIT();
    };

    issue(0);
    for (int c = 0; c < NCH; c++) {
        if (c + 1 < NCH) { issue(c + 1); CP_WAIT1(); }
        else             { CP_WAIT0(); }
        __syncthreads();
        const int buf = c & 1;
        const __nv_bfloat16* As = (const __nv_bfloat16*)(dsm + (buf ? SM_A1 : SM_A0));
        const __nv_bfloat16* Bs = (const __nv_bfloat16*)(dsm + (buf ? SM_B1 : SM_B0));
#pragma unroll
        for (int kt = 0; kt < 4; kt++) {
            wmma::fragment<wmma::matrix_a, 16, 16, 16, __nv_bfloat16, wmma::row_major> af[4];
            wmma::fragment<wmma::matrix_b, 16, 16, 16, __nv_bfloat16, wmma::col_major> bf[2];
#pragma unroll
            for (int n = 0; n < 2; n++)
                wmma::load_matrix_sync(bf[n], Bs + (wn * 32 + n * 16) * APAD + kt * 16, APAD);
#pragma unroll
            for (int m = 0; m < 4; m++)
                wmma::load_matrix_sync(af[m], As + (wm * 64 + m * 16) * APAD + kt * 16, APAD);
#pragma unroll
            for (int m = 0; m < 4; m++)
#pragma unroll
                for (int n = 0; n < 2; n++)
                    wmma::mma_sync(acc[m][n], af[m], bf[n], acc[m][n]);
        }
        __syncthreads();
    }

    float* stg = (float*)(dsm + SM_STG) + wid * 256;
    const int srow = lane >> 1;
    const int scol = (lane & 1) * 8;
#pragma unroll
    for (int m = 0; m < 4; m++) {
#pragma unroll
        for (int n = 0; n < 2; n++) {
            wmma::store_matrix_sync(stg, acc[m][n], 16, wmma::mem_row_major);
            __syncwarp();
            int grow = bm + wm * 64 + m * 16 + srow;
            int gcol = bn + wn * 32 + n * 16 + scol;
            if (grow < Mr) {
                const float* sp = stg + srow * 16 + scol;
                __half* crow = C + (size_t)grow * Nc + gcol;
#pragma unroll
                for (int q = 0; q < 2; q++) {
                    float4 v = *(const float4*)(sp + q * 4);
                    ((__half2*)(crow + q * 4))[0] = __floats2half2_rn(v.x, v.y);
                    ((__half2*)(crow + q * 4))[1] = __floats2half2_rn(v.z, v.w);
                }
            }
            __syncwarp();
        }
    }
}

// ---------------- fp16 single-segment GEMM (fc path) ----------------
template <int MODE>
__global__ void __launch_bounds__(256) k_hgemm(
    const __half* __restrict__ A, const __half* __restrict__ Bt,
    float* __restrict__ C, int Mr, int Nc, int Kd, const float* __restrict__ bias) {
    extern __shared__ __align__(16) char dsm[];
    const uint32_t sb = smem_u32(dsm);

    const int tid = threadIdx.x;
    const int wid = tid >> 5;
    const int lane = tid & 31;
    const int wm = wid >> 2;
    const int wn = wid & 3;
    const int bm = blockIdx.y * 128;
    const int bn = blockIdx.x * 128;

    const int NCH = Kd >> 6;

    const int lr = tid >> 1;
    const int lc = (tid & 1) * 4;
    const int gaRow = min(bm + lr, Mr - 1);
    const int gbRow = bn + lr;

    wmma::fragment<wmma::accumulator, 16, 16, 16, float> acc[4][2];
#pragma unroll
    for (int i = 0; i < 4; i++)
#pragma unroll
        for (int j = 0; j < 2; j++) wmma::fill_fragment(acc[i][j], 0.0f);

    auto issue = [&](int c) {
        int koff = c << 6;
        int buf = c & 1;
        uint32_t abase = sb + (buf ? SM_A1 : SM_A0) + lr * 144;
        uint32_t bbase = sb + (buf ? SM_B1 : SM_B0) + lr * 144;
        const char* ap = (const char*)(A + (size_t)gaRow * Kd + koff);
        const char* bp = (const char*)(Bt + (size_t)gbRow * Kd + koff);
#pragma unroll
        for (int u = 0; u < 4; u++) {
            cp16(abase + (lc + u) * 16, ap + (lc + u) * 16);
            cp16(bbase + (lc + u) * 16, bp + (lc + u) * 16);
        }
        CP_COMMIT();
    };

    issue(0);
    for (int c = 0; c < NCH; c++) {
        if (c + 1 < NCH) { issue(c + 1); CP_WAIT1(); }
        else             { CP_WAIT0(); }
        __syncthreads();
        const int buf = c & 1;
        const __half* As = (const __half*)(dsm + (buf ? SM_A1 : SM_A0));
        const __half* Bs = (const __half*)(dsm + (buf ? SM_B1 : SM_B0));
#pragma unroll
        for (int kt = 0; kt < 4; kt++) {
            wmma::fragment<wmma::matrix_a, 16, 16, 16, __half, wmma::row_major> af[4];
            wmma::fragment<wmma::matrix_b, 16, 16, 16, __half, wmma::col_major> bf[2];
#pragma unroll
            for (int n = 0; n < 2; n++)
                wmma::load_matrix_sync(bf[n], Bs + (wn * 32 + n * 16) * APAD + kt * 16, APAD);
#pragma unroll
            for (int m = 0; m < 4; m++)
                wmma::load_matrix_sync(af[m], As + (wm * 64 + m * 16) * APAD + kt * 16, APAD);
#pragma unroll
            for (int m = 0; m < 4; m++)
#pragma unroll
                for (int n = 0; n < 2; n++)
                    wmma::mma_sync(acc[m][n], af[m], bf[n], acc[m][n]);
        }
        __syncthreads();
    }

    float* stg = (float*)(dsm + SM_STG) + wid * 256;
    const int srow = lane >> 1;
    const int scol = (lane & 1) * 8;
#pragma unroll
    for (int m = 0; m < 4; m++) {
#pragma unroll
        for (int n = 0; n < 2; n++) {
            wmma::store_matrix_sync(stg, acc[m][n], 16, wmma::mem_row_major);
            __syncwarp();
            int grow = bm + wm * 64 + m * 16 + srow;
            int gcol = bn + wn * 32 + n * 16 + scol;
            if (grow < Mr) {
                const float* sp = stg + srow * 16 + scol;
                float* crow = C + (size_t)grow * Nc + gcol;
#pragma unroll
                for (int q = 0; q < 2; q++) {
                    float4 v = *(const float4*)(sp + q * 4);
                    float4 bb = *(const float4*)(bias + gcol + q * 4);
                    v.x += bb.x; v.y += bb.y; v.z += bb.z; v.w += bb.w;
                    v.x = (v.x > 0.f) ? v.x : NEG_SLOPE * v.x;
                    v.y = (v.y > 0.f) ? v.y : NEG_SLOPE * v.y;
                    v.z = (v.z > 0.f) ? v.z : NEG_SLOPE * v.z;
                    v.w = (v.w > 0.f) ? v.w : NEG_SLOPE * v.w;
                    if (MODE == 2) {
                        float4 o = *(const float4*)(crow + q * 4);
                        v.x += o.x; v.y += o.y; v.z += o.z; v.w += o.w;
                    }
                    *(float4*)(crow + q * 4) = v;
                }
            }
            __syncwarp();
        }
    }
}

// ---------------- conversions ----------------
__global__ void k_wsplit(const float* __restrict__ W, __nv_bfloat16* __restrict__ thi,
                         __nv_bfloat16* __restrict__ tlo, int K, int N) {
    int i = blockIdx.x * blockDim.x + threadIdx.x;
    if (i >= K * N) return;
    int n = i / K, k = i - n * K;
    float v = W[(size_t)k * N + n];
    __nv_bfloat16 h = __float2bfloat16(v);
    thi[i] = h;
    tlo[i] = __float2bfloat16(v - __bfloat162float(h));
}

__global__ void k_wsplit16(const float* __restrict__ W, __half* __restrict__ t16, int K, int N) {
    int i = blockIdx.x * blockDim.x + threadIdx.x;
    if (i >= K * N) return;
    int n = i / K, k = i - n * K;
    t16[i] = __float2half(W[(size_t)k * N + n]);
}

__global__ void k_tof16(const float* __restrict__ X, __half* __restrict__ Y, int total4) {
    int i = blockIdx.x * blockDim.x + threadIdx.x;
    if (i >= total4) return;
    float4 v = ((const float4*)X)[i];
    ((__half2*)Y)[i * 2]     = __floats2half2_rn(v.x, v.y);
    ((__half2*)Y)[i * 2 + 1] = __floats2half2_rn(v.z, v.w);
}

// ---------------- structure kernels ----------------
__global__ void k_zero2(int* a, int na, int* b, int nb) {
    int i = blockIdx.x * blockDim.x + threadIdx.x;
    if (i < na) a[i] = 0;
    else if (i < na + nb) b[i - na] = 0;
}

__global__ void k_hist(const int* __restrict__ row, const int* __restrict__ col,
                       int* degn, int* dege, int E) {
    int i = blockIdx.x * blockDim.x + threadIdx.x;
    if (i < E) {
        atomicAdd(&degn[row[i]], 1);
        atomicAdd(&dege[col[i]], 1);
    }
}

__global__ void k_bsum(const int* __restrict__ cnt, int* __restrict__ bsum, int n) {
    int b = blockIdx.x, t = threadIdx.x;
    int base = b * 1024;
    int s = 0;
#pragma unroll
    for (int u = 0; u < 4; u++) {
        int i = base + t + u * 256;
        if (i < n) s += cnt[i];
    }
    __shared__ int red[8];
    for (int o = 16; o; o >>= 1) s += __shfl_down_sync(0xffffffffu, s, o);
    if ((t & 31) == 0) red[t >> 5] = s;
    __syncthreads();
    if (t == 0) {
        int v = 0;
#pragma unroll
        for (int w = 0; w < 8; w++) v += red[w];
        bsum[b] = v;
    }
}

__global__ void k_bscan(int* bsum, int nb) {
    if (threadIdx.x == 0) {
        int run = 0;
        for (int i = 0; i < nb; i++) { int v = bsum[i]; bsum[i] = run; run += v; }
        bsum[nb] = run;
    }
}

__global__ void k_lscan(const int* __restrict__ cnt, const int* __restrict__ bsum,
                        int* __restrict__ start, int* __restrict__ cur, int n, int nb) {
    int b = blockIdx.x, t = threadIdx.x;
    __shared__ int sh[256];
    int base = b * 1024;
    int v[4];
    int s = 0;
#pragma unroll
    for (int u = 0; u < 4; u++) {
        int i = base + t * 4 + u;
        v[u] = (i < n) ? cnt[i] : 0;
        s += v[u];
    }
    sh[t] = s;
    __syncthreads();
    for (int o = 1; o < 256; o <<= 1) {
        int a = (t >= o) ? sh[t - o] : 0;
        __syncthreads();
        sh[t] += a;
        __syncthreads();
    }
    int run = bsum[b] + ((t == 0) ? 0 : sh[t - 1]);
#pragma unroll
    for (int u = 0; u < 4; u++) {
        int i = base + t * 4 + u;
        if (i < n) { start[i] = run; cur[i] = run; run += v[u]; }
    }
    if (b == 0 && t == 0) start[n] = bsum[nb];
}

__global__ void k_scatter(const int* __restrict__ row, const int* __restrict__ col,
                          int* rcur, int* ccur, int* __restrict__ rcsr,
                          int* __restrict__ ccsr, int E) {
    int i = blockIdx.x * blockDim.x + threadIdx.x;
    if (i < E) {
        int pr = atomicAdd(&rcur[row[i]], 1);
        rcsr[pr] = i;
        int pc = atomicAdd(&ccur[col[i]], 1);
        ccsr[pc] = i;
    }
}

__global__ void k_inv2(const int* __restrict__ da, float* __restrict__ ia, int na,
                       const int* __restrict__ db, float* __restrict__ ib, int nb) {
    int i = blockIdx.x * blockDim.x + threadIdx.x;
    if (i < na) {
        int d = da[i];
        ia[i] = (d > 0) ? (1.0f / (float)d) : 0.0f;
    } else if (i < na + nb) {
        int d = db[i - na];
        ib[i - na] = (d > 0) ? (1.0f / (float)d) : 0.0f;
    }
}

// ---------------- row dots ----------------
__global__ void k_rowdot(const float* __restrict__ X, const float* __restrict__ v,
                         float* __restrict__ out, int rows) {
    int gw = (blockIdx.x * blockDim.x + threadIdx.x) >> 5;
    int lane = threadIdx.x & 31;
    if (gw >= rows) return;
    const float4* xr = (const float4*)(X + (size_t)gw * FF);
    const float4* vv = (const float4*)v;
    float s = 0.f;
#pragma unroll
    for (int j = 0; j < 4; j++) {
        float4 a = xr[lane + 32 * j];
        float4 b = vv[lane + 32 * j];
        s += a.x * b.x + a.y * b.y + a.z * b.z + a.w * b.w;
    }
    for (int o = 16; o; o >>= 1) s += __shfl_down_sync(0xffffffffu, s, o);
    if (!lane) out[gw] = s;
}

__global__ void k_rowdot2(const float* __restrict__ X, const float* __restrict__ v1,
                          const float* __restrict__ v2, float* __restrict__ o1,
                          float* __restrict__ o2, int rows) {
    int gw = (blockIdx.x * blockDim.x + threadIdx.x) >> 5;
    int lane = threadIdx.x & 31;
    if (gw >= rows) return;
    const float4* xr = (const float4*)(X + (size_t)gw * FF);
    const float4* va = (const float4*)v1;
    const float4* vb = (const float4*)v2;
    float s1 = 0.f, s2 = 0.f;
#pragma unroll
    for (int j = 0; j < 4; j++) {
        float4 a = xr[lane + 32 * j];
        float4 b = va[lane + 32 * j];
        float4 c = vb[lane + 32 * j];
        s1 += a.x * b.x + a.y * b.y + a.z * b.z + a.w * b.w;
        s2 += a.x * c.x + a.y * c.y + a.z * c.z + a.w * c.w;
    }
    for (int o = 16; o; o >>= 1) {
        s1 += __shfl_down_sync(0xffffffffu, s1, o);
        s2 += __shfl_down_sync(0xffffffffu, s2, o);
    }
    if (!lane) { o1[gw] = s1; o2[gw] = s2; }
}

// ---------------- fused attention softmax + propagate-1 (fp16 gather, unroll 8) ----------------
__global__ void __launch_bounds__(256) k_attnprop(
    const int* __restrict__ cstart, const int* __restrict__ ccsr,
    const int* __restrict__ row, const float* __restrict__ xn,
    const float* __restrict__ en, const float* __restrict__ Binv,
    const __half* __restrict__ X, float* __restrict__ alpha,
    __nv_bfloat16* __restrict__ efhi, __nv_bfloat16* __restrict__ eflo) {
    int m = blockIdx.x;
    int s = cstart[m], e = cstart[m + 1];
    int tid = threadIdx.x;
    __shared__ float red[256];
    __shared__ int   shr[256];
    __shared__ float shc[256];

    float enm = en[m];
    float mx = -3.0e38f;
    for (int i = s + tid; i < e; i += 256) {
        int ed = ccsr[i];
        float p = xn[row[ed]] + enm;
        p = (p > 0.f) ? p : ATT_SLOPE * p;
        alpha[ed] = p;
        mx = fmaxf(mx, p);
    }
    red[tid] = mx;
    __syncthreads();
    for (int o = 128; o; o >>= 1) {
        if (tid < o) red[tid] = fmaxf(red[tid], red[tid + o]);
        __syncthreads();
    }
    float amax = red[0];
    if (!(amax > -1e37f)) amax = 0.f;
    __syncthreads();
    float sm = 0.f;
    for (int i = s + tid; i < e; i += 256) {
        int ed = ccsr[i];
        float ex = expf(alpha[ed] - amax);
        alpha[ed] = ex;
        sm += ex;
    }
    red[tid] = sm;
    __syncthreads();
    for (int o = 128; o; o >>= 1) {
        if (tid < o) red[tid] += red[tid + o];
        __syncthreads();
    }
    float inv = 1.f / fmaxf(red[0], 1e-16f);
    float bi = Binv[m];
    float ax = 0.f, ay = 0.f;
    const __half2* base = (const __half2*)X + tid;
    for (int b0 = s; b0 < e; b0 += 256) {
        int cnt = min(256, e - b0);
        __syncthreads();
        if (tid < cnt) {
            int ed = ccsr[b0 + tid];
            float a = alpha[ed] * inv;
            alpha[ed] = a;
            shr[tid] = row[ed];
            shc[tid] = a * bi;
        }
        __syncthreads();
        int j = 0;
        for (; j + 8 <= cnt; j += 8) {
            float2 v0 = __half22float2(base[(size_t)shr[j]     * (FF / 2)]);
            float2 v1 = __half22float2(base[(size_t)shr[j + 1] * (FF / 2)]);
            float2 v2 = __half22float2(base[(size_t)shr[j + 2] * (FF / 2)]);
            float2 v3 = __half22float2(base[(size_t)shr[j + 3] * (FF / 2)]);
            float2 v4 = __half22float2(base[(size_t)shr[j + 4] * (FF / 2)]);
            float2 v5 = __half22float2(base[(size_t)shr[j + 5] * (FF / 2)]);
            float2 v6 = __half22float2(base[(size_t)shr[j + 6] * (FF / 2)]);
            float2 v7 = __half22float2(base[(size_t)shr[j + 7] * (FF / 2)]);
            ax += shc[j] * v0.x + shc[j + 1] * v1.x + shc[j + 2] * v2.x + shc[j + 3] * v3.x
                + shc[j + 4] * v4.x + shc[j + 5] * v5.x + shc[j + 6] * v6.x + shc[j + 7] * v7.x;
            ay += shc[j] * v0.y + shc[j + 1] * v1.y + shc[j + 2] * v2.y + shc[j + 3] * v3.y
                + shc[j + 4] * v4.y + shc[j + 5] * v5.y + shc[j + 6] * v6.y + shc[j + 7] * v7.y;
        }
        for (; j < cnt; j++) {
            float2 v = __half22float2(base[(size_t)shr[j] * (FF / 2)]);
            float cf = shc[j];
            ax += cf * v.x;
            ay += cf * v.y;
        }
    }
    __nv_bfloat16 hx = __float2bfloat16(ax), hy = __float2bfloat16(ay);
    __nv_bfloat16 lx = __float2bfloat16(ax - __bfloat162float(hx));
    __nv_bfloat16 ly = __float2bfloat16(ay - __bfloat162float(hy));
    ((__nv_bfloat162*)(efhi + (size_t)m * FF))[tid] = __nv_bfloat162(hx, hy);
    ((__nv_bfloat162*)(eflo + (size_t)m * FF))[tid] = __nv_bfloat162(lx, ly);
}

// ---------------- propagate-2 (fp16 gather, fp32 out) ----------------
__global__ void k_prop2(const int* __restrict__ rstart, const int* __restrict__ rcsr,
                        const int* __restrict__ col, const float* __restrict__ alpha,
                        const float* __restrict__ Dinv, const __half* __restrict__ ef,
                        const float* __restrict__ bias, float* __restrict__ out) {
    int n = blockIdx.x;
    int s = rstart[n], e = rstart[n + 1];
    int tid = threadIdx.x;
    float a0 = 0.f, a1 = 0.f, a2 = 0.f, a3 = 0.f;
    const uint2* base = (const uint2*)ef + tid;
    int i = s;
    for (; i + 4 <= e; i += 4) {
        int e0 = rcsr[i], e1 = rcsr[i + 1], e2 = rcsr[i + 2], e3 = rcsr[i + 3];
        float c0 = alpha[e0], c1 = alpha[e1], c2 = alpha[e2], c3 = alpha[e3];
        uint2 u0 = base[(size_t)col[e0] * (FF / 4)];
        uint2 u1 = base[(size_t)col[e1] * (FF / 4)];
        uint2 u2 = base[(size_t)col[e2] * (FF / 4)];
        uint2 u3 = base[(size_t)col[e3] * (FF / 4)];
        float2 p0a = __half22float2(*(const __half2*)&u0.x);
        float2 p0b = __half22float2(*(const __half2*)&u0.y);
        float2 p1a = __half22float2(*(const __half2*)&u1.x);
        float2 p1b = __half22float2(*(const __half2*)&u1.y);
        float2 p2a = __half22float2(*(const __half2*)&u2.x);
        float2 p2b = __half22float2(*(const __half2*)&u2.y);
        float2 p3a = __half22float2(*(const __half2*)&u3.x);
        float2 p3b = __half22float2(*(const __half2*)&u3.y);
        a0 += c0 * p0a.x + c1 * p1a.x + c2 * p2a.x + c3 * p3a.x;
        a1 += c0 * p0a.y + c1 * p1a.y + c2 * p2a.y + c3 * p3a.y;
        a2 += c0 * p0b.x + c1 * p1b.x + c2 * p2b.x + c3 * p3b.x;
        a3 += c0 * p0b.y + c1 * p1b.y + c2 * p2b.y + c3 * p3b.y;
    }
    for (; i < e; i++) {
        int ed = rcsr[i];
        float cf = alpha[ed];
        uint2 u = base[(size_t)col[ed] * (FF / 4)];
        float2 pa = __half22float2(*(const __half2*)&u.x);
        float2 pb = __half22float2(*(const __half2*)&u.y);
        a0 += cf * pa.x; a1 += cf * pa.y; a2 += cf * pb.x; a3 += cf * pb.y;
    }
    float d = Dinv[n];
    float4 b = *(const float4*)(bias + 4 * tid);
    float4 o;
    o.x = a0 * d + b.x; o.y = a1 * d + b.y; o.z = a2 * d + b.z; o.w = a3 * d + b.w;
    *(float4*)(out + (size_t)n * FF + 4 * tid) = o;
}

// ---------------- graph norm ----------------
__global__ void k_colstat(const float* __restrict__ X, float* __restrict__ p1,
                          float* __restrict__ p2, int rows) {
    int b = blockIdx.x;
    int c = threadIdx.x;
    int r0 = b * CSTAT_ROWS, r1 = min(r0 + CSTAT_ROWS, rows);
    float s1 = 0.f, s2 = 0.f;
    for (int r = r0; r < r1; r++) {
        float v = X[(size_t)r * FF + c];
        s1 += v;
        s2 += v * v;
    }
    p1[b * FF + c] = s1;
    p2[b * FF + c] = s2;
}

__global__ void k_statfin(const float* __restrict__ p1, const float* __restrict__ p2,
                          int nblk, const float* __restrict__ w,
                          const float* __restrict__ ms, float* __restrict__ shift,
                          float* __restrict__ scale, float rows_inv) {
    int c = threadIdx.x;
    float s1 = 0.f, s2 = 0.f;
    for (int i = 0; i < nblk; i++) {
        s1 += p1[i * FF + c];
        s2 += p2[i * FF + c];
    }
    float mu = s1 * rows_inv;
    float ex2 = s2 * rows_inv;
    float m = ms[c];
    float sh = m * mu;
    float var = ex2 - sh * (2.f * mu - sh);
    shift[c] = sh;
    scale[c] = w[c] / sqrtf(var + 1e-5f);
}

// graph_norm apply + leaky_relu, block-per-row: fp16 out + optional fused dot
__global__ void __launch_bounds__(128) k_normfuse(
    const float* __restrict__ X, const float* __restrict__ shift,
    const float* __restrict__ scale, const float* __restrict__ beta,
    const float* __restrict__ wdot, __half* __restrict__ y16,
    float* __restrict__ xnout) {
    int n = blockIdx.x;
    int t = threadIdx.x;          // 128 threads * 4 cols
    int c = t * 4;
    float4 v = *(const float4*)(X + (size_t)n * FF + c);
    float4 sh = *(const float4*)(shift + c);
    float4 sc = *(const float4*)(scale + c);
    float4 be = *(const float4*)(beta + c);
    float y0 = (v.x - sh.x) * sc.x + be.x;
    float y1 = (v.y - sh.y) * sc.y + be.y;
    float y2 = (v.z - sh.z) * sc.z + be.z;
    float y3 = (v.w - sh.w) * sc.w + be.w;
    y0 = (y0 > 0.f) ? y0 : NEG_SLOPE * y0;
    y1 = (y1 > 0.f) ? y1 : NEG_SLOPE * y1;
    y2 = (y2 > 0.f) ? y2 : NEG_SLOPE * y2;
    y3 = (y3 > 0.f) ? y3 : NEG_SLOPE * y3;
    __half2* y2p = (__half2*)(y16 + (size_t)n * FF + c);
    y2p[0] = __floats2half2_rn(y0, y1);
    y2p[1] = __floats2half2_rn(y2, y3);
    if (xnout) {
        float4 w = *(const float4*)(wdot + c);
        float d = y0 * w.x + y1 * w.y + y2 * w.z + y3 * w.w;
        __shared__ float red[128];
        red[t] = d;
        __syncthreads();
        for (int o = 64; o; o >>= 1) {
            if (t < o) red[t] += red[t + o];
            __syncthreads();
        }
        if (t == 0) xnout[n] = red[0];
    }
}

__global__ void k_cls(const float* __restrict__ A, const float* __restrict__ W,
                      const float* __restrict__ b, float* __restrict__ out, int rows) {
    int gw = (blockIdx.x * blockDim.x + threadIdx.x) >> 5;
    int lane = threadIdx.x & 31;
    if (gw >= rows) return;
    const float* ar = A + (size_t)gw * HIDD;
    float s0 = 0.f, s1 = 0.f;
    for (int h = lane; h < HIDD; h += 32) {
        float v = ar[h];
        s0 += v * W[h * 2];
        s1 += v * W[h * 2 + 1];
    }
    for (int o = 16; o; o >>= 1) {
        s0 += __shfl_down_sync(0xffffffffu, s0, o);
        s1 += __shfl_down_sync(0xffffffffu, s1, o);
    }
    if (!lane) {
        out[gw * 2] = s0 + b[0];
        out[gw * 2 + 1] = s1 + b[1];
    }
}

// ---------------- host launch ----------------
extern "C" void kernel_launch(void* const* d_in, const int* in_sizes, int n_in,
                              void* d_out, int out_size) {
    const float* x    = (const float*)d_in[0];
    const int*   ei   = (const int*)d_in[1];
    const float* ea   = (const float*)d_in[2];
    const float* W1   = (const float*)d_in[3];
    const float* att1 = (const float*)d_in[4];
    const float* b1   = (const float*)d_in[5];
    const float* W2   = (const float*)d_in[6];
    const float* att2 = (const float*)d_in[7];
    const float* b2   = (const float*)d_in[8];
    const float* gn1w = (const float*)d_in[9];
    const float* gn1b = (const float*)d_in[10];
    const float* gn1ms= (const float*)d_in[11];
    const float* gn2w = (const float*)d_in[12];
    const float* gn2b = (const float*)d_in[13];
    const float* gn2ms= (const float*)d_in[14];
    const float* fc1W = (const float*)d_in[15];
    const float* fc1b = (const float*)d_in[16];
    const float* fc2W = (const float*)d_in[17];
    const float* fc2b = (const float*)d_in[18];
    const float* clsW = (const float*)d_in[19];
    const float* clsb = (const float*)d_in[20];
    float* outp = (float*)d_out;

    const int* row = ei;
    const int* col = ei + EE;

    float *xl, *fc, *xn, *en1, *en2, *wa1, *wb1, *wa2, *wb2, *alpha, *Dinv, *Binv;
    float *p1, *p2, *shift, *scale;
    int *degn, *dege, *rstart, *cstart, *rcur, *ccur, *rcsr, *ccsr, *bsumN, *bsumM;
    __half *elb, *h16, *f1t16, *f2t16;
    __nv_bfloat16 *eahi, *ealo, *W1thi, *W1tlo, *W2thi, *W2tlo;
    cudaGetSymbolAddress((void**)&xl, g_xl);
    cudaGetSymbolAddress((void**)&elb, g_elb);
    cudaGetSymbolAddress((void**)&h16, g_h16);
    cudaGetSymbolAddress((void**)&fc, g_fc);
    cudaGetSymbolAddress((void**)&xn, g_xn);
    cudaGetSymbolAddress((void**)&en1, g_en1);
    cudaGetSymbolAddress((void**)&en2, g_en2);
    cudaGetSymbolAddress((void**)&wa1, g_wa1);
    cudaGetSymbolAddress((void**)&wb1, g_wb1);
    cudaGetSymbolAddress((void**)&wa2, g_wa2);
    cudaGetSymbolAddress((void**)&wb2, g_wb2);
    cudaGetSymbolAddress((void**)&alpha, g_alpha);
    cudaGetSymbolAddress((void**)&Dinv, g_Dinv);
    cudaGetSymbolAddress((void**)&Binv, g_Binv);
    cudaGetSymbolAddress((void**)&p1, g_p1);
    cudaGetSymbolAddress((void**)&p2, g_p2);
    cudaGetSymbolAddress((void**)&shift, g_shift);
    cudaGetSymbolAddress((void**)&scale, g_scale);
    cudaGetSymbolAddress((void**)&degn, g_degn);
    cudaGetSymbolAddress((void**)&dege, g_dege);
    cudaGetSymbolAddress((void**)&rstart, g_rstart);
    cudaGetSymbolAddress((void**)&cstart, g_cstart);
    cudaGetSymbolAddress((void**)&rcur, g_rcur);
    cudaGetSymbolAddress((void**)&ccur, g_ccur);
    cudaGetSymbolAddress((void**)&rcsr, g_rcsr);
    cudaGetSymbolAddress((void**)&ccsr, g_ccsr);
    cudaGetSymbolAddress((void**)&bsumN, g_bsumN);
    cudaGetSymbolAddress((void**)&bsumM, g_bsumM);
    cudaGetSymbolAddress((void**)&eahi, g_eahi);
    cudaGetSymbolAddress((void**)&ealo, g_ealo);
    cudaGetSymbolAddress((void**)&W1thi, g_W1thi);
    cudaGetSymbolAddress((void**)&W1tlo, g_W1tlo);
    cudaGetSymbolAddress((void**)&W2thi, g_W2thi);
    cudaGetSymbolAddress((void**)&W2tlo, g_W2tlo);
    cudaGetSymbolAddress((void**)&f1t16, g_f1t16);
    cudaGetSymbolAddress((void**)&f2t16, g_f2t16);

    static cudaStream_t s1 = nullptr;
    static cudaEvent_t evFork = nullptr, evJoin1 = nullptr, evFork2 = nullptr, evJoin2 = nullptr;
    static bool init_done = false;
    if (!init_done) {
        cudaFuncSetAttribute(k_wgemm0, cudaFuncAttributeMaxDynamicSharedMemorySize, GEMM_SMEM);
        cudaFuncSetAttribute(k_hgemm<1>, cudaFuncAttributeMaxDynamicSharedMemorySize, GEMM_SMEM);
        cudaFuncSetAttribute(k_hgemm<2>, cudaFuncAttributeMaxDynamicSharedMemorySize, GEMM_SMEM);
        cudaStreamCreateWithFlags(&s1, cudaStreamNonBlocking);
        cudaEventCreateWithFlags(&evFork, cudaEventDisableTiming);
        cudaEventCreateWithFlags(&evJoin1, cudaEventDisableTiming);
        cudaEventCreateWithFlags(&evFork2, cudaEventDisableTiming);
        cudaEventCreateWithFlags(&evJoin2, cudaEventDisableTiming);
        init_done = true;
    }

    const int NBN = (NN + 1023) / 1024;
    const int NBM = (MM + 1023) / 1024;
    const float rows_inv = 1.0f / (float)NN;
    dim3 gM(FF / 128, MM / 128);
    dim3 gFC(HIDD / 128, (NN + 127) / 128);

    // ---- fork: s1 joins capture ----
    cudaEventRecord(evFork, 0);
    cudaStreamWaitEvent(s1, evFork, 0);

    // ---- s0: graph structure chain ----
    k_zero2<<<(NN + MM + 255) / 256, 256>>>(degn, NN, dege, MM);
    k_hist<<<(EE + 255) / 256, 256>>>(row, col, degn, dege, EE);
    k_bsum<<<NBM, 256>>>(dege, bsumM, MM);
    k_bsum<<<NBN, 256>>>(degn, bsumN, NN);
    k_bscan<<<1, 32>>>(bsumM, NBM);
    k_bscan<<<1, 32>>>(bsumN, NBN);
    k_lscan<<<NBM, 256>>>(dege, bsumM, cstart, ccur, MM, NBM);
    k_lscan<<<NBN, 256>>>(degn, bsumN, rstart, rcur, NN, NBN);
    k_scatter<<<(EE + 255) / 256, 256>>>(row, col, rcur, ccur, rcsr, ccsr, EE);
    k_inv2<<<(NN + MM + 255) / 256, 256>>>(degn, Dinv, NN, dege, Binv, MM);

    // ---- s1 (parallel): conversions + weight projections + conv1 pre-dots ----
    k_wsplit<<<(FF * FF + 255) / 256, 256, 0, s1>>>(W1, W1thi, W1tlo, FF, FF);
    k_wsplit<<<(FF * FF + 255) / 256, 256, 0, s1>>>(W2, W2thi, W2tlo, FF, FF);
    k_wsplit16<<<(FF * HIDD + 255) / 256, 256, 0, s1>>>(fc1W, f1t16, FF, HIDD);
    k_wsplit16<<<(FF * HIDD + 255) / 256, 256, 0, s1>>>(fc2W, f2t16, FF, HIDD);
    k_tof16<<<(NN * (FF / 4) + 255) / 256, 256, 0, s1>>>(x, h16, NN * (FF / 4));
    k_rowdot2<<<(FF * 32 + 255) / 256, 256, 0, s1>>>(W1, att1, att1 + FF, wa1, wb1, FF);
    k_rowdot2<<<(FF * 32 + 255) / 256, 256, 0, s1>>>(W2, att2, att2 + FF, wa2, wb2, FF);
    k_rowdot<<<(NN * 32 + 255) / 256, 256, 0, s1>>>(x, wa1, xn, NN);
    k_rowdot<<<(MM * 32 + 255) / 256, 256, 0, s1>>>(ea, wb1, en1, MM);
    k_rowdot<<<(MM * 32 + 255) / 256, 256, 0, s1>>>(ea, wb2, en2, MM);
    cudaEventRecord(evJoin1, s1);
    cudaStreamWaitEvent(0, evJoin1, 0);

    // ==== conv1 (s0) ====
    k_attnprop<<<MM, 256>>>(cstart, ccsr, row, xn, en1, Binv, h16, alpha, eahi, ealo);
    k_wgemm0<<<gM, 256, GEMM_SMEM>>>(eahi, ealo, W1thi, W1tlo, elb, MM, FF, FF);
    k_prop2<<<NN, 128>>>(rstart, rcsr, col, alpha, Dinv, elb, b1, xl);
    k_colstat<<<CSTAT_BLKS, FF>>>(xl, p1, p2, NN);
    k_statfin<<<1, FF>>>(p1, p2, CSTAT_BLKS, gn1w, gn1ms, shift, scale, rows_inv);
    // normfuse1: h16 out + fused xn = h · wa2 (for conv2 attention)
    k_normfuse<<<NN, 128>>>(xl, shift, scale, gn1b, wa2, h16, xn);

    // ---- fork 2: fc1 GEMM on s1 (reads h16), conv2 front on s0 ----
    cudaEventRecord(evFork2, 0);
    cudaStreamWaitEvent(s1, evFork2, 0);
    k_hgemm<1><<<gFC, 256, GEMM_SMEM, s1>>>(h16, f1t16, fc, NN, HIDD, FF, fc1b);

    // ==== conv2 front (s0) ====
    k_attnprop<<<MM, 256>>>(cstart, ccsr, row, xn, en2, Binv, h16, alpha, eahi, ealo);
    k_wgemm0<<<gM, 256, GEMM_SMEM>>>(eahi, ealo, W2thi, W2tlo, elb, MM, FF, FF);
    k_prop2<<<NN, 128>>>(rstart, rcsr, col, alpha, Dinv, elb, b2, xl);
    k_colstat<<<CSTAT_BLKS, FF>>>(xl, p1, p2, NN);
    k_statfin<<<1, FF>>>(p1, p2, CSTAT_BLKS, gn2w, gn2ms, shift, scale, rows_inv);

    // join: fc1 must finish before normfuse2 overwrites h16 (and before fc2 reads fc)
    cudaEventRecord(evJoin2, s1);
    cudaStreamWaitEvent(0, evJoin2, 0);
    k_normfuse<<<NN, 128>>>(xl, shift, scale, gn2b, wa2, h16, nullptr);
    k_hgemm<2><<<gFC, 256, GEMM_SMEM>>>(h16, f2t16, fc, NN, HIDD, FF, fc2b);

    // ---- classifier ----
    k_cls<<<(NN * 32 + 255) / 256, 256>>>(fc, clsW, clsb, outp, NN);
}

// round 15
// speedup vs baseline: 3.2110x; 1.0558x over previous
#include <cuda_runtime.h>
#include <cuda_bf16.h>
#include <cuda_fp16.h>
#include <mma.h>
#include <cstdint>
#include <math.h>

using namespace nvcuda;

#define NN 20000
#define MM 2048
#define EE 320000
#define FF 512
#define HIDD 256
#define CSTAT_ROWS 128
#define CSTAT_BLKS ((NN + CSTAT_ROWS - 1) / CSTAT_ROWS)   // 157

#define NEG_SLOPE 0.01f
#define ATT_SLOPE 0.2f

// ---------------- scratch ----------------
__device__ float g_xl[NN * FF];         // conv output pre-norm (fp32 — MUST stay fp32, see R13)
__device__ __half g_elb[MM * FF];
__device__ __half g_h16[NN * FF];
__device__ float g_fc[NN * HIDD];
__device__ float g_xn[NN];
__device__ float g_en1[MM];
__device__ float g_en2[MM];
__device__ float g_wa1[FF];
__device__ float g_wb1[FF];
__device__ float g_wa2[FF];
__device__ float g_wb2[FF];
__device__ float g_alpha[EE];
__device__ float g_Dinv[NN];
__device__ float g_Binv[MM];
__device__ int   g_degn[NN];
__device__ int   g_dege[MM];
__device__ int   g_rstart[NN + 1];
__device__ int   g_cstart[MM + 1];
__device__ int   g_rcur[NN];
__device__ int   g_ccur[MM];
__device__ int   g_rcsr[EE];
__device__ int   g_ccsr[EE];
__device__ int   g_bsumN[32];
__device__ int   g_bsumM[8];
__device__ float g_p1[CSTAT_BLKS * FF];
__device__ float g_p2[CSTAT_BLKS * FF];
__device__ float g_shift[FF];
__device__ float g_scale[FF];
__device__ int   g_ticket;              // colstat last-block ticket (returns to 0)
__device__ __nv_bfloat16 g_eahi[MM * FF];
__device__ __nv_bfloat16 g_ealo[MM * FF];
__device__ __nv_bfloat16 g_W1thi[FF * FF];
__device__ __nv_bfloat16 g_W1tlo[FF * FF];
__device__ __nv_bfloat16 g_W2thi[FF * FF];
__device__ __nv_bfloat16 g_W2tlo[FF * FF];
__device__ __half g_f1t16[HIDD * FF];
__device__ __half g_f2t16[HIDD * FF];

// ---------------- cp.async helpers ----------------
__device__ __forceinline__ uint32_t smem_u32(const void* p) {
    uint32_t a;
    asm("{ .reg .u64 t; cvta.to.shared.u64 t, %1; cvt.u32.u64 %0, t; }" : "=r"(a) : "l"(p));
    return a;
}
__device__ __forceinline__ void cp16(uint32_t dst, const void* src) {
    asm volatile("cp.async.ca.shared.global [%0], [%1], 16;" :: "r"(dst), "l"(src));
}
#define CP_COMMIT() asm volatile("cp.async.commit_group;" ::: "memory")
#define CP_WAIT1()  asm volatile("cp.async.wait_group 1;" ::: "memory")
#define CP_WAIT0()  asm volatile("cp.async.wait_group 0;" ::: "memory")

#define APAD 72
#define SM_A0 0
#define SM_B0 18432
#define SM_A1 36864
#define SM_B1 55296
#define SM_STG 73728
#define GEMM_SMEM 81920

// ---------------- cp.async double-buffered wmma split-bf16 GEMM (ef path) ----------------
__global__ void __launch_bounds__(256) k_wgemm0(
    const __nv_bfloat16* __restrict__ Ahi, const __nv_bfloat16* __restrict__ Alo,
    const __nv_bfloat16* __restrict__ Bthi, const __nv_bfloat16* __restrict__ Btlo,
    __half* __restrict__ C, int Mr, int Nc, int Kd) {
    extern __shared__ __align__(16) char dsm[];
    const uint32_t sb = smem_u32(dsm);

    const int tid = threadIdx.x;
    const int wid = tid >> 5;
    const int lane = tid & 31;
    const int wm = wid >> 2;
    const int wn = wid & 3;
    const int bm = blockIdx.y * 128;
    const int bn = blockIdx.x * 128;

    const int CPS = Kd >> 6;
    const int NCH = 3 * CPS;

    const int lr = tid >> 1;
    const int lc = (tid & 1) * 4;
    const int gaRow = min(bm + lr, Mr - 1);
    const int gbRow = bn + lr;

    wmma::fragment<wmma::accumulator, 16, 16, 16, float> acc[4][2];
#pragma unroll
    for (int i = 0; i < 4; i++)
#pragma unroll
        for (int j = 0; j < 2; j++) wmma::fill_fragment(acc[i][j], 0.0f);

    auto issue = [&](int c) {
        int seg = c / CPS;
        int j = c - seg * CPS;
        const __nv_bfloat16* A = (seg == 1) ? Alo : Ahi;
        const __nv_bfloat16* B = (seg == 2) ? Btlo : Bthi;
        int koff = j << 6;
        int buf = c & 1;
        uint32_t abase = sb + (buf ? SM_A1 : SM_A0) + lr * 144;
        uint32_t bbase = sb + (buf ? SM_B1 : SM_B0) + lr * 144;
        const char* ap = (const char*)(A + (size_t)gaRow * Kd + koff);
        const char* bp = (const char*)(B + (size_t)gbRow * Kd + koff);
#pragma unroll
        for (int u = 0; u < 4; u++) {
            cp16(abase + (lc + u) * 16, ap + (lc + u) * 16);
            cp16(bbase + (lc + u) * 16, bp + (lc + u) * 16);
        }
        CP_COMMIT();
    };

    issue(0);
    for (int c = 0; c < NCH; c++) {
        if (c + 1 < NCH) { issue(c + 1); CP_WAIT1(); }
        else             { CP_WAIT0(); }
        __syncthreads();
        const int buf = c & 1;
        const __nv_bfloat16* As = (const __nv_bfloat16*)(dsm + (buf ? SM_A1 : SM_A0));
        const __nv_bfloat16* Bs = (const __nv_bfloat16*)(dsm + (buf ? SM_B1 : SM_B0));
#pragma unroll
        for (int kt = 0; kt < 4; kt++) {
            wmma::fragment<wmma::matrix_a, 16, 16, 16, __nv_bfloat16, wmma::row_major> af[4];
            wmma::fragment<wmma::matrix_b, 16, 16, 16, __nv_bfloat16, wmma::col_major> bf[2];
#pragma unroll
            for (int n = 0; n < 2; n++)
                wmma::load_matrix_sync(bf[n], Bs + (wn * 32 + n * 16) * APAD + kt * 16, APAD);
#pragma unroll
            for (int m = 0; m < 4; m++)
                wmma::load_matrix_sync(af[m], As + (wm * 64 + m * 16) * APAD + kt * 16, APAD);
#pragma unroll
            for (int m = 0; m < 4; m++)
#pragma unroll
                for (int n = 0; n < 2; n++)
                    wmma::mma_sync(acc[m][n], af[m], bf[n], acc[m][n]);
        }
        __syncthreads();
    }

    float* stg = (float*)(dsm + SM_STG) + wid * 256;
    const int srow = lane >> 1;
    const int scol = (lane & 1) * 8;
#pragma unroll
    for (int m = 0; m < 4; m++) {
#pragma unroll
        for (int n = 0; n < 2; n++) {
            wmma::store_matrix_sync(stg, acc[m][n], 16, wmma::mem_row_major);
            __syncwarp();
            int grow = bm + wm * 64 + m * 16 + srow;
            int gcol = bn + wn * 32 + n * 16 + scol;
            if (grow < Mr) {
                const float* sp = stg + srow * 16 + scol;
                __half* crow = C + (size_t)grow * Nc + gcol;
#pragma unroll
                for (int q = 0; q < 2; q++) {
                    float4 v = *(const float4*)(sp + q * 4);
                    ((__half2*)(crow + q * 4))[0] = __floats2half2_rn(v.x, v.y);
                    ((__half2*)(crow + q * 4))[1] = __floats2half2_rn(v.z, v.w);
                }
            }
            __syncwarp();
        }
    }
}

// ---------------- fp16 single-segment GEMM (fc path) ----------------
template <int MODE>
__global__ void __launch_bounds__(256) k_hgemm(
    const __half* __restrict__ A, const __half* __restrict__ Bt,
    float* __restrict__ C, int Mr, int Nc, int Kd, const float* __restrict__ bias) {
    extern __shared__ __align__(16) char dsm[];
    const uint32_t sb = smem_u32(dsm);

    const int tid = threadIdx.x;
    const int wid = tid >> 5;
    const int lane = tid & 31;
    const int wm = wid >> 2;
    const int wn = wid & 3;
    const int bm = blockIdx.y * 128;
    const int bn = blockIdx.x * 128;

    const int NCH = Kd >> 6;

    const int lr = tid >> 1;
    const int lc = (tid & 1) * 4;
    const int gaRow = min(bm + lr, Mr - 1);
    const int gbRow = bn + lr;

    wmma::fragment<wmma::accumulator, 16, 16, 16, float> acc[4][2];
#pragma unroll
    for (int i = 0; i < 4; i++)
#pragma unroll
        for (int j = 0; j < 2; j++) wmma::fill_fragment(acc[i][j], 0.0f);

    auto issue = [&](int c) {
        int koff = c << 6;
        int buf = c & 1;
        uint32_t abase = sb + (buf ? SM_A1 : SM_A0) + lr * 144;
        uint32_t bbase = sb + (buf ? SM_B1 : SM_B0) + lr * 144;
        const char* ap = (const char*)(A + (size_t)gaRow * Kd + koff);
        const char* bp = (const char*)(Bt + (size_t)gbRow * Kd + koff);
#pragma unroll
        for (int u = 0; u < 4; u++) {
            cp16(abase + (lc + u) * 16, ap + (lc + u) * 16);
            cp16(bbase + (lc + u) * 16, bp + (lc + u) * 16);
        }
        CP_COMMIT();
    };

    issue(0);
    for (int c = 0; c < NCH; c++) {
        if (c + 1 < NCH) { issue(c + 1); CP_WAIT1(); }
        else             { CP_WAIT0(); }
        __syncthreads();
        const int buf = c & 1;
        const __half* As = (const __half*)(dsm + (buf ? SM_A1 : SM_A0));
        const __half* Bs = (const __half*)(dsm + (buf ? SM_B1 : SM_B0));
#pragma unroll
        for (int kt = 0; kt < 4; kt++) {
            wmma::fragment<wmma::matrix_a, 16, 16, 16, __half, wmma::row_major> af[4];
            wmma::fragment<wmma::matrix_b, 16, 16, 16, __half, wmma::col_major> bf[2];
#pragma unroll
            for (int n = 0; n < 2; n++)
                wmma::load_matrix_sync(bf[n], Bs + (wn * 32 + n * 16) * APAD + kt * 16, APAD);
#pragma unroll
            for (int m = 0; m < 4; m++)
                wmma::load_matrix_sync(af[m], As + (wm * 64 + m * 16) * APAD + kt * 16, APAD);
#pragma unroll
            for (int m = 0; m < 4; m++)
#pragma unroll
                for (int n = 0; n < 2; n++)
                    wmma::mma_sync(acc[m][n], af[m], bf[n], acc[m][n]);
        }
        __syncthreads();
    }

    float* stg = (float*)(dsm + SM_STG) + wid * 256;
    const int srow = lane >> 1;
    const int scol = (lane & 1) * 8;
#pragma unroll
    for (int m = 0; m < 4; m++) {
#pragma unroll
        for (int n = 0; n < 2; n++) {
            wmma::store_matrix_sync(stg, acc[m][n], 16, wmma::mem_row_major);
            __syncwarp();
            int grow = bm + wm * 64 + m * 16 + srow;
            int gcol = bn + wn * 32 + n * 16 + scol;
            if (grow < Mr) {
                const float* sp = stg + srow * 16 + scol;
                float* crow = C + (size_t)grow * Nc + gcol;
#pragma unroll
                for (int q = 0; q < 2; q++) {
                    float4 v = *(const float4*)(sp + q * 4);
                    float4 bb = *(const float4*)(bias + gcol + q * 4);
                    v.x += bb.x; v.y += bb.y; v.z += bb.z; v.w += bb.w;
                    v.x = (v.x > 0.f) ? v.x : NEG_SLOPE * v.x;
                    v.y = (v.y > 0.f) ? v.y : NEG_SLOPE * v.y;
                    v.z = (v.z > 0.f) ? v.z : NEG_SLOPE * v.z;
                    v.w = (v.w > 0.f) ? v.w : NEG_SLOPE * v.w;
                    if (MODE == 2) {
                        float4 o = *(const float4*)(crow + q * 4);
                        v.x += o.x; v.y += o.y; v.z += o.z; v.w += o.w;
                    }
                    *(float4*)(crow + q * 4) = v;
                }
            }
            __syncwarp();
        }
    }
}

// ---------------- conversions ----------------
__global__ void k_wsplit(const float* __restrict__ W, __nv_bfloat16* __restrict__ thi,
                         __nv_bfloat16* __restrict__ tlo, int K, int N) {
    int i = blockIdx.x * blockDim.x + threadIdx.x;
    if (i >= K * N) return;
    int n = i / K, k = i - n * K;
    float v = W[(size_t)k * N + n];
    __nv_bfloat16 h = __float2bfloat16(v);
    thi[i] = h;
    tlo[i] = __float2bfloat16(v - __bfloat162float(h));
}

__global__ void k_wsplit16(const float* __restrict__ W, __half* __restrict__ t16, int K, int N) {
    int i = blockIdx.x * blockDim.x + threadIdx.x;
    if (i >= K * N) return;
    int n = i / K, k = i - n * K;
    t16[i] = __float2half(W[(size_t)k * N + n]);
}

__global__ void k_tof16(const float* __restrict__ X, __half* __restrict__ Y, int total4) {
    int i = blockIdx.x * blockDim.x + threadIdx.x;
    if (i >= total4) return;
    float4 v = ((const float4*)X)[i];
    ((__half2*)Y)[i * 2]     = __floats2half2_rn(v.x, v.y);
    ((__half2*)Y)[i * 2 + 1] = __floats2half2_rn(v.z, v.w);
}

// ---------------- structure kernels ----------------
__global__ void k_zero2(int* a, int na, int* b, int nb) {
    int i = blockIdx.x * blockDim.x + threadIdx.x;
    if (i < na) a[i] = 0;
    else if (i < na + nb) b[i - na] = 0;
}

__global__ void k_hist(const int* __restrict__ row, const int* __restrict__ col,
                       int* degn, int* dege, int E) {
    int i = blockIdx.x * blockDim.x + threadIdx.x;
    if (i < E) {
        atomicAdd(&degn[row[i]], 1);
        atomicAdd(&dege[col[i]], 1);
    }
}

// fused block-sum for BOTH count arrays: blocks [0,NBM) -> dege, [NBM,NBM+NBN) -> degn
__global__ void k_bsum2(const int* __restrict__ cntM, int* __restrict__ bsumM, int nM, int NBM,
                        const int* __restrict__ cntN, int* __restrict__ bsumN, int nN) {
    int b = blockIdx.x, t = threadIdx.x;
    const int* cnt; int* bsum; int n; int lb;
    if (b < NBM) { cnt = cntM; bsum = bsumM; n = nM; lb = b; }
    else         { cnt = cntN; bsum = bsumN; n = nN; lb = b - NBM; }
    int base = lb * 1024;
    int s = 0;
#pragma unroll
    for (int u = 0; u < 4; u++) {
        int i = base + t + u * 256;
        if (i < n) s += cnt[i];
    }
    __shared__ int red[8];
    for (int o = 16; o; o >>= 1) s += __shfl_down_sync(0xffffffffu, s, o);
    if ((t & 31) == 0) red[t >> 5] = s;
    __syncthreads();
    if (t == 0) {
        int v = 0;
#pragma unroll
        for (int w = 0; w < 8; w++) v += red[w];
        bsum[lb] = v;
    }
}

__global__ void k_bscan2(int* bsumM, int nbM, int* bsumN, int nbN) {
    if (threadIdx.x == 0) {
        int run = 0;
        for (int i = 0; i < nbM; i++) { int v = bsumM[i]; bsumM[i] = run; run += v; }
        bsumM[nbM] = run;
    } else if (threadIdx.x == 32) {
        int run = 0;
        for (int i = 0; i < nbN; i++) { int v = bsumN[i]; bsumN[i] = run; run += v; }
        bsumN[nbN] = run;
    }
}

__global__ void k_lscan2(const int* __restrict__ cntM, const int* __restrict__ bsumM,
                         int* __restrict__ startM, int* __restrict__ curM, int nM, int NBM,
                         const int* __restrict__ cntN, const int* __restrict__ bsumN,
                         int* __restrict__ startN, int* __restrict__ curN, int nN) {
    int b = blockIdx.x, t = threadIdx.x;
    const int* cnt; const int* bsum; int* start; int* cur; int n; int lb; int nb;
    if (b < NBM) { cnt = cntM; bsum = bsumM; start = startM; cur = curM; n = nM; lb = b; nb = NBM; }
    else {
        cnt = cntN; bsum = bsumN; start = startN; cur = curN; n = nN; lb = b - NBM;
        nb = gridDim.x - NBM;
    }
    __shared__ int sh[256];
    int base = lb * 1024;
    int v[4];
    int s = 0;
#pragma unroll
    for (int u = 0; u < 4; u++) {
        int i = base + t * 4 + u;
        v[u] = (i < n) ? cnt[i] : 0;
        s += v[u];
    }
    sh[t] = s;
    __syncthreads();
    for (int o = 1; o < 256; o <<= 1) {
        int a = (t >= o) ? sh[t - o] : 0;
        __syncthreads();
        sh[t] += a;
        __syncthreads();
    }
    int run = bsum[lb] + ((t == 0) ? 0 : sh[t - 1]);
#pragma unroll
    for (int u = 0; u < 4; u++) {
        int i = base + t * 4 + u;
        if (i < n) { start[i] = run; cur[i] = run; run += v[u]; }
    }
    if (lb == 0 && t == 0) start[n] = bsum[nb];
}

__global__ void k_scatter(const int* __restrict__ row, const int* __restrict__ col,
                          int* rcur, int* ccur, int* __restrict__ rcsr,
                          int* __restrict__ ccsr, int E) {
    int i = blockIdx.x * blockDim.x + threadIdx.x;
    if (i < E) {
        int pr = atomicAdd(&rcur[row[i]], 1);
        rcsr[pr] = i;
        int pc = atomicAdd(&ccur[col[i]], 1);
        ccsr[pc] = i;
    }
}

__global__ void k_inv2(const int* __restrict__ da, float* __restrict__ ia, int na,
                       const int* __restrict__ db, float* __restrict__ ib, int nb) {
    int i = blockIdx.x * blockDim.x + threadIdx.x;
    if (i < na) {
        int d = da[i];
        ia[i] = (d > 0) ? (1.0f / (float)d) : 0.0f;
    } else if (i < na + nb) {
        int d = db[i - na];
        ib[i - na] = (d > 0) ? (1.0f / (float)d) : 0.0f;
    }
}

// ---------------- row dots ----------------
__global__ void k_rowdot(const float* __restrict__ X, const float* __restrict__ v,
                         float* __restrict__ out, int rows) {
    int gw = (blockIdx.x * blockDim.x + threadIdx.x) >> 5;
    int lane = threadIdx.x & 31;
    if (gw >= rows) return;
    const float4* xr = (const float4*)(X + (size_t)gw * FF);
    const float4* vv = (const float4*)v;
    float s = 0.f;
#pragma unroll
    for (int j = 0; j < 4; j++) {
        float4 a = xr[lane + 32 * j];
        float4 b = vv[lane + 32 * j];
        s += a.x * b.x + a.y * b.y + a.z * b.z + a.w * b.w;
    }
    for (int o = 16; o; o >>= 1) s += __shfl_down_sync(0xffffffffu, s, o);
    if (!lane) out[gw] = s;
}

__global__ void k_rowdot2(const float* __restrict__ X, const float* __restrict__ v1,
                          const float* __restrict__ v2, float* __restrict__ o1,
                          float* __restrict__ o2, int rows) {
    int gw = (blockIdx.x * blockDim.x + threadIdx.x) >> 5;
    int lane = threadIdx.x & 31;
    if (gw >= rows) return;
    const float4* xr = (const float4*)(X + (size_t)gw * FF);
    const float4* va = (const float4*)v1;
    const float4* vb = (const float4*)v2;
    float s1 = 0.f, s2 = 0.f;
#pragma unroll
    for (int j = 0; j < 4; j++) {
        float4 a = xr[lane + 32 * j];
        float4 b = va[lane + 32 * j];
        float4 c = vb[lane + 32 * j];
        s1 += a.x * b.x + a.y * b.y + a.z * b.z + a.w * b.w;
        s2 += a.x * c.x + a.y * c.y + a.z * c.z + a.w * c.w;
    }
    for (int o = 16; o; o >>= 1) {
        s1 += __shfl_down_sync(0xffffffffu, s1, o);
        s2 += __shfl_down_sync(0xffffffffu, s2, o);
    }
    if (!lane) { o1[gw] = s1; o2[gw] = s2; }
}

// ---------------- fused attention softmax (2-pass, no max shift) + propagate-1 ----------------
__global__ void __launch_bounds__(256) k_attnprop(
    const int* __restrict__ cstart, const int* __restrict__ ccsr,
    const int* __restrict__ row, const float* __restrict__ xn,
    const float* __restrict__ en, const float* __restrict__ Binv,
    const __half* __restrict__ X, float* __restrict__ alpha,
    __nv_bfloat16* __restrict__ efhi, __nv_bfloat16* __restrict__ eflo) {
    int m = blockIdx.x;
    int s = cstart[m], e = cstart[m + 1];
    int tid = threadIdx.x;
    __shared__ float red[256];
    __shared__ int   shr[256];
    __shared__ float shc[256];

    float enm = en[m];
    // pass 1: exp(leaky(p)) directly — logits are O(1), no overflow possible
    float sm = 0.f;
    for (int i = s + tid; i < e; i += 256) {
        int ed = ccsr[i];
        float p = xn[row[ed]] + enm;
        p = (p > 0.f) ? p : ATT_SLOPE * p;
        float ex = expf(p);
        alpha[ed] = ex;
        sm += ex;
    }
    red[tid] = sm;
    __syncthreads();
    for (int o = 128; o; o >>= 1) {
        if (tid < o) red[tid] += red[tid + o];
        __syncthreads();
    }
    float inv = 1.f / fmaxf(red[0], 1e-16f);
    float bi = Binv[m];
    float ax = 0.f, ay = 0.f;
    const __half2* base = (const __half2*)X + tid;
    for (int b0 = s; b0 < e; b0 += 256) {
        int cnt = min(256, e - b0);
        __syncthreads();
        if (tid < cnt) {
            int ed = ccsr[b0 + tid];
            float a = alpha[ed] * inv;
            alpha[ed] = a;
            shr[tid] = row[ed];
            shc[tid] = a * bi;
        }
        __syncthreads();
        int j = 0;
        for (; j + 8 <= cnt; j += 8) {
            float2 v0 = __half22float2(base[(size_t)shr[j]     * (FF / 2)]);
            float2 v1 = __half22float2(base[(size_t)shr[j + 1] * (FF / 2)]);
            float2 v2 = __half22float2(base[(size_t)shr[j + 2] * (FF / 2)]);
            float2 v3 = __half22float2(base[(size_t)shr[j + 3] * (FF / 2)]);
            float2 v4 = __half22float2(base[(size_t)shr[j + 4] * (FF / 2)]);
            float2 v5 = __half22float2(base[(size_t)shr[j + 5] * (FF / 2)]);
            float2 v6 = __half22float2(base[(size_t)shr[j + 6] * (FF / 2)]);
            float2 v7 = __half22float2(base[(size_t)shr[j + 7] * (FF / 2)]);
            ax += shc[j] * v0.x + shc[j + 1] * v1.x + shc[j + 2] * v2.x + shc[j + 3] * v3.x
                + shc[j + 4] * v4.x + shc[j + 5] * v5.x + shc[j + 6] * v6.x + shc[j + 7] * v7.x;
            ay += shc[j] * v0.y + shc[j + 1] * v1.y + shc[j + 2] * v2.y + shc[j + 3] * v3.y
                + shc[j + 4] * v4.y + shc[j + 5] * v5.y + shc[j + 6] * v6.y + shc[j + 7] * v7.y;
        }
        for (; j < cnt; j++) {
            float2 v = __half22float2(base[(size_t)shr[j] * (FF / 2)]);
            float cf = shc[j];
            ax += cf * v.x;
            ay += cf * v.y;
        }
    }
    __nv_bfloat16 hx = __float2bfloat16(ax), hy = __float2bfloat16(ay);
    __nv_bfloat16 lx = __float2bfloat16(ax - __bfloat162float(hx));
    __nv_bfloat16 ly = __float2bfloat16(ay - __bfloat162float(hy));
    ((__nv_bfloat162*)(efhi + (size_t)m * FF))[tid] = __nv_bfloat162(hx, hy);
    ((__nv_bfloat162*)(eflo + (size_t)m * FF))[tid] = __nv_bfloat162(lx, ly);
}

// ---------------- propagate-2 (fp16 gather, fp32 out) ----------------
__global__ void k_prop2(const int* __restrict__ rstart, const int* __restrict__ rcsr,
                        const int* __restrict__ col, const float* __restrict__ alpha,
                        const float* __restrict__ Dinv, const __half* __restrict__ ef,
                        const float* __restrict__ bias, float* __restrict__ out) {
    int n = blockIdx.x;
    int s = rstart[n], e = rstart[n + 1];
    int tid = threadIdx.x;
    float a0 = 0.f, a1 = 0.f, a2 = 0.f, a3 = 0.f;
    const uint2* base = (const uint2*)ef + tid;
    int i = s;
    for (; i + 4 <= e; i += 4) {
        int e0 = rcsr[i], e1 = rcsr[i + 1], e2 = rcsr[i + 2], e3 = rcsr[i + 3];
        float c0 = alpha[e0], c1 = alpha[e1], c2 = alpha[e2], c3 = alpha[e3];
        uint2 u0 = base[(size_t)col[e0] * (FF / 4)];
        uint2 u1 = base[(size_t)col[e1] * (FF / 4)];
        uint2 u2 = base[(size_t)col[e2] * (FF / 4)];
        uint2 u3 = base[(size_t)col[e3] * (FF / 4)];
        float2 p0a = __half22float2(*(const __half2*)&u0.x);
        float2 p0b = __half22float2(*(const __half2*)&u0.y);
        float2 p1a = __half22float2(*(const __half2*)&u1.x);
        float2 p1b = __half22float2(*(const __half2*)&u1.y);
        float2 p2a = __half22float2(*(const __half2*)&u2.x);
        float2 p2b = __half22float2(*(const __half2*)&u2.y);
        float2 p3a = __half22float2(*(const __half2*)&u3.x);
        float2 p3b = __half22float2(*(const __half2*)&u3.y);
        a0 += c0 * p0a.x + c1 * p1a.x + c2 * p2a.x + c3 * p3a.x;
        a1 += c0 * p0a.y + c1 * p1a.y + c2 * p2a.y + c3 * p3a.y;
        a2 += c0 * p0b.x + c1 * p1b.x + c2 * p2b.x + c3 * p3b.x;
        a3 += c0 * p0b.y + c1 * p1b.y + c2 * p2b.y + c3 * p3b.y;
    }
    for (; i < e; i++) {
        int ed = rcsr[i];
        float cf = alpha[ed];
        uint2 u = base[(size_t)col[ed] * (FF / 4)];
        float2 pa = __half22float2(*(const __half2*)&u.x);
        float2 pb = __half22float2(*(const __half2*)&u.y);
        a0 += cf * pa.x; a1 += cf * pa.y; a2 += cf * pb.x; a3 += cf * pb.y;
    }
    float d = Dinv[n];
    float4 b = *(const float4*)(bias + 4 * tid);
    float4 o;
    o.x = a0 * d + b.x; o.y = a1 * d + b.y; o.z = a2 * d + b.z; o.w = a3 * d + b.w;
    *(float4*)(out + (size_t)n * FF + 4 * tid) = o;
}

// ---------------- graph norm: colstat + statfin fused (last-block reduce) ----------------
__global__ void k_colstat(const float* __restrict__ X, float* __restrict__ p1,
                          float* __restrict__ p2, int rows,
                          const float* __restrict__ w, const float* __restrict__ ms,
                          float* __restrict__ shift, float* __restrict__ scale,
                          float rows_inv, int* ticket) {
    int b = blockIdx.x;
    int c = threadIdx.x;
    int r0 = b * CSTAT_ROWS, r1 = min(r0 + CSTAT_ROWS, rows);
    float s1 = 0.f, s2 = 0.f;
    for (int r = r0; r < r1; r++) {
        float v = X[(size_t)r * FF + c];
        s1 += v;
        s2 += v * v;
    }
    p1[b * FF + c] = s1;
    p2[b * FF + c] = s2;
    // last-block fixed-order reduce (deterministic)
    __threadfence();
    __shared__ int isLast;
    if (c == 0) {
        int t = atomicAdd(ticket, 1);
        isLast = (t == gridDim.x - 1);
    }
    __syncthreads();
    if (isLast) {
        float t1 = 0.f, t2 = 0.f;
        for (int i = 0; i < CSTAT_BLKS; i++) {
            t1 += p1[i * FF + c];
            t2 += p2[i * FF + c];
        }
        float mu = t1 * rows_inv;
        float ex2 = t2 * rows_inv;
        float m = ms[c];
        float sh = m * mu;
        float var = ex2 - sh * (2.f * mu - sh);
        shift[c] = sh;
        scale[c] = w[c] / sqrtf(var + 1e-5f);
        if (c == 0) *ticket = 0;   // reset for next call / replay
    }
}

// graph_norm apply + leaky_relu, block-per-row: fp16 out + optional fused dot
__global__ void __launch_bounds__(128) k_normfuse(
    const float* __restrict__ X, const float* __restrict__ shift,
    const float* __restrict__ scale, const float* __restrict__ beta,
    const float* __restrict__ wdot, __half* __restrict__ y16,
    float* __restrict__ xnout) {
    int n = blockIdx.x;
    int t = threadIdx.x;
    int c = t * 4;
    float4 v = *(const float4*)(X + (size_t)n * FF + c);
    float4 sh = *(const float4*)(shift + c);
    float4 sc = *(const float4*)(scale + c);
    float4 be = *(const float4*)(beta + c);
    float y0 = (v.x - sh.x) * sc.x + be.x;
    float y1 = (v.y - sh.y) * sc.y + be.y;
    float y2 = (v.z - sh.z) * sc.z + be.z;
    float y3 = (v.w - sh.w) * sc.w + be.w;
    y0 = (y0 > 0.f) ? y0 : NEG_SLOPE * y0;
    y1 = (y1 > 0.f) ? y1 : NEG_SLOPE * y1;
    y2 = (y2 > 0.f) ? y2 : NEG_SLOPE * y2;
    y3 = (y3 > 0.f) ? y3 : NEG_SLOPE * y3;
    __half2* y2p = (__half2*)(y16 + (size_t)n * FF + c);
    y2p[0] = __floats2half2_rn(y0, y1);
    y2p[1] = __floats2half2_rn(y2, y3);
    if (xnout) {
        float4 w = *(const float4*)(wdot + c);
        float d = y0 * w.x + y1 * w.y + y2 * w.z + y3 * w.w;
        __shared__ float red[128];
        red[t] = d;
        __syncthreads();
        for (int o = 64; o; o >>= 1) {
            if (t < o) red[t] += red[t + o];
            __syncthreads();
        }
        if (t == 0) xnout[n] = red[0];
    }
}

__global__ void k_cls(const float* __restrict__ A, const float* __restrict__ W,
                      const float* __restrict__ b, float* __restrict__ out, int rows) {
    int gw = (blockIdx.x * blockDim.x + threadIdx.x) >> 5;
    int lane = threadIdx.x & 31;
    if (gw >= rows) return;
    const float* ar = A + (size_t)gw * HIDD;
    float s0 = 0.f, s1 = 0.f;
    for (int h = lane; h < HIDD; h += 32) {
        float v = ar[h];
        s0 += v * W[h * 2];
        s1 += v * W[h * 2 + 1];
    }
    for (int o = 16; o; o >>= 1) {
        s0 += __shfl_down_sync(0xffffffffu, s0, o);
        s1 += __shfl_down_sync(0xffffffffu, s1, o);
    }
    if (!lane) {
        out[gw * 2] = s0 + b[0];
        out[gw * 2 + 1] = s1 + b[1];
    }
}

// ---------------- host launch ----------------
extern "C" void kernel_launch(void* const* d_in, const int* in_sizes, int n_in,
                              void* d_out, int out_size) {
    const float* x    = (const float*)d_in[0];
    const int*   ei   = (const int*)d_in[1];
    const float* ea   = (const float*)d_in[2];
    const float* W1   = (const float*)d_in[3];
    const float* att1 = (const float*)d_in[4];
    const float* b1   = (const float*)d_in[5];
    const float* W2   = (const float*)d_in[6];
    const float* att2 = (const float*)d_in[7];
    const float* b2   = (const float*)d_in[8];
    const float* gn1w = (const float*)d_in[9];
    const float* gn1b = (const float*)d_in[10];
    const float* gn1ms= (const float*)d_in[11];
    const float* gn2w = (const float*)d_in[12];
    const float* gn2b = (const float*)d_in[13];
    const float* gn2ms= (const float*)d_in[14];
    const float* fc1W = (const float*)d_in[15];
    const float* fc1b = (const float*)d_in[16];
    const float* fc2W = (const float*)d_in[17];
    const float* fc2b = (const float*)d_in[18];
    const float* clsW = (const float*)d_in[19];
    const float* clsb = (const float*)d_in[20];
    float* outp = (float*)d_out;

    const int* row = ei;
    const int* col = ei + EE;

    float *xl, *fc, *xn, *en1, *en2, *wa1, *wb1, *wa2, *wb2, *alpha, *Dinv, *Binv;
    float *p1, *p2, *shift, *scale;
    int *degn, *dege, *rstart, *cstart, *rcur, *ccur, *rcsr, *ccsr, *bsumN, *bsumM, *ticket;
    __half *elb, *h16, *f1t16, *f2t16;
    __nv_bfloat16 *eahi, *ealo, *W1thi, *W1tlo, *W2thi, *W2tlo;
    cudaGetSymbolAddress((void**)&xl, g_xl);
    cudaGetSymbolAddress((void**)&elb, g_elb);
    cudaGetSymbolAddress((void**)&h16, g_h16);
    cudaGetSymbolAddress((void**)&fc, g_fc);
    cudaGetSymbolAddress((void**)&xn, g_xn);
    cudaGetSymbolAddress((void**)&en1, g_en1);
    cudaGetSymbolAddress((void**)&en2, g_en2);
    cudaGetSymbolAddress((void**)&wa1, g_wa1);
    cudaGetSymbolAddress((void**)&wb1, g_wb1);
    cudaGetSymbolAddress((void**)&wa2, g_wa2);
    cudaGetSymbolAddress((void**)&wb2, g_wb2);
    cudaGetSymbolAddress((void**)&alpha, g_alpha);
    cudaGetSymbolAddress((void**)&Dinv, g_Dinv);
    cudaGetSymbolAddress((void**)&Binv, g_Binv);
    cudaGetSymbolAddress((void**)&p1, g_p1);
    cudaGetSymbolAddress((void**)&p2, g_p2);
    cudaGetSymbolAddress((void**)&shift, g_shift);
    cudaGetSymbolAddress((void**)&scale, g_scale);
    cudaGetSymbolAddress((void**)&degn, g_degn);
    cudaGetSymbolAddress((void**)&dege, g_dege);
    cudaGetSymbolAddress((void**)&rstart, g_rstart);
    cudaGetSymbolAddress((void**)&cstart, g_cstart);
    cudaGetSymbolAddress((void**)&rcur, g_rcur);
    cudaGetSymbolAddress((void**)&ccur, g_ccur);
    cudaGetSymbolAddress((void**)&rcsr, g_rcsr);
    cudaGetSymbolAddress((void**)&ccsr, g_ccsr);
    cudaGetSymbolAddress((void**)&bsumN, g_bsumN);
    cudaGetSymbolAddress((void**)&bsumM, g_bsumM);
    cudaGetSymbolAddress((void**)&ticket, g_ticket);
    cudaGetSymbolAddress((void**)&eahi, g_eahi);
    cudaGetSymbolAddress((void**)&ealo, g_ealo);
    cudaGetSymbolAddress((void**)&W1thi, g_W1thi);
    cudaGetSymbolAddress((void**)&W1tlo, g_W1tlo);
    cudaGetSymbolAddress((void**)&W2thi, g_W2thi);
    cudaGetSymbolAddress((void**)&W2tlo, g_W2tlo);
    cudaGetSymbolAddress((void**)&f1t16, g_f1t16);
    cudaGetSymbolAddress((void**)&f2t16, g_f2t16);

    static cudaStream_t s1 = nullptr;
    static cudaEvent_t evFork = nullptr, evJoin1 = nullptr, evFork2 = nullptr, evJoin2 = nullptr;
    static bool init_done = false;
    if (!init_done) {
        cudaFuncSetAttribute(k_wgemm0, cudaFuncAttributeMaxDynamicSharedMemorySize, GEMM_SMEM);
        cudaFuncSetAttribute(k_hgemm<1>, cudaFuncAttributeMaxDynamicSharedMemorySize, GEMM_SMEM);
        cudaFuncSetAttribute(k_hgemm<2>, cudaFuncAttributeMaxDynamicSharedMemorySize, GEMM_SMEM);
        cudaStreamCreateWithFlags(&s1, cudaStreamNonBlocking);
        cudaEventCreateWithFlags(&evFork, cudaEventDisableTiming);
        cudaEventCreateWithFlags(&evJoin1, cudaEventDisableTiming);
        cudaEventCreateWithFlags(&evFork2, cudaEventDisableTiming);
        cudaEventCreateWithFlags(&evJoin2, cudaEventDisableTiming);
        init_done = true;
    }

    const int NBN = (NN + 1023) / 1024;   // 20
    const int NBM = (MM + 1023) / 1024;   // 2
    const float rows_inv = 1.0f / (float)NN;
    dim3 gM(FF / 128, MM / 128);
    dim3 gFC(HIDD / 128, (NN + 127) / 128);

    // ---- fork: s1 joins capture ----
    cudaEventRecord(evFork, 0);
    cudaStreamWaitEvent(s1, evFork, 0);

    // ---- s0: graph structure chain ----
    k_zero2<<<(NN + MM + 255) / 256, 256>>>(degn, NN, dege, MM);
    k_hist<<<(EE + 255) / 256, 256>>>(row, col, degn, dege, EE);
    k_bsum2<<<NBM + NBN, 256>>>(dege, bsumM, MM, NBM, degn, bsumN, NN);
    k_bscan2<<<1, 64>>>(bsumM, NBM, bsumN, NBN);
    k_lscan2<<<NBM + NBN, 256>>>(dege, bsumM, cstart, ccur, MM, NBM,
                                 degn, bsumN, rstart, rcur, NN);
    k_scatter<<<(EE + 255) / 256, 256>>>(row, col, rcur, ccur, rcsr, ccsr, EE);
    k_inv2<<<(NN + MM + 255) / 256, 256>>>(degn, Dinv, NN, dege, Binv, MM);

    // ---- s1 (parallel): conversions + weight projections + conv1 pre-dots ----
    k_wsplit<<<(FF * FF + 255) / 256, 256, 0, s1>>>(W1, W1thi, W1tlo, FF, FF);
    k_wsplit<<<(FF * FF + 255) / 256, 256, 0, s1>>>(W2, W2thi, W2tlo, FF, FF);
    k_wsplit16<<<(FF * HIDD + 255) / 256, 256, 0, s1>>>(fc1W, f1t16, FF, HIDD);
    k_wsplit16<<<(FF * HIDD + 255) / 256, 256, 0, s1>>>(fc2W, f2t16, FF, HIDD);
    k_tof16<<<(NN * (FF / 4) + 255) / 256, 256, 0, s1>>>(x, h16, NN * (FF / 4));
    k_rowdot2<<<(FF * 32 + 255) / 256, 256, 0, s1>>>(W1, att1, att1 + FF, wa1, wb1, FF);
    k_rowdot2<<<(FF * 32 + 255) / 256, 256, 0, s1>>>(W2, att2, att2 + FF, wa2, wb2, FF);
    k_rowdot<<<(NN * 32 + 255) / 256, 256, 0, s1>>>(x, wa1, xn, NN);
    k_rowdot<<<(MM * 32 + 255) / 256, 256, 0, s1>>>(ea, wb1, en1, MM);
    k_rowdot<<<(MM * 32 + 255) / 256, 256, 0, s1>>>(ea, wb2, en2, MM);
    cudaEventRecord(evJoin1, s1);
    cudaStreamWaitEvent(0, evJoin1, 0);

    // ==== conv1 (s0) ====
    k_attnprop<<<MM, 256>>>(cstart, ccsr, row, xn, en1, Binv, h16, alpha, eahi, ealo);
    k_wgemm0<<<gM, 256, GEMM_SMEM>>>(eahi, ealo, W1thi, W1tlo, elb, MM, FF, FF);
    k_prop2<<<NN, 128>>>(rstart, rcsr, col, alpha, Dinv, elb, b1, xl);
    k_colstat<<<CSTAT_BLKS, FF>>>(xl, p1, p2, NN, gn1w, gn1ms, shift, scale, rows_inv, ticket);
    k_normfuse<<<NN, 128>>>(xl, shift, scale, gn1b, wa2, h16, xn);

    // ---- fork 2: fc1 GEMM on s1 (reads h16), conv2 front on s0 ----
    cudaEventRecord(evFork2, 0);
    cudaStreamWaitEvent(s1, evFork2, 0);
    k_hgemm<1><<<gFC, 256, GEMM_SMEM, s1>>>(h16, f1t16, fc, NN, HIDD, FF, fc1b);

    // ==== conv2 front (s0) ====
    k_attnprop<<<MM, 256>>>(cstart, ccsr, row, xn, en2, Binv, h16, alpha, eahi, ealo);
    k_wgemm0<<<gM, 256, GEMM_SMEM>>>(eahi, ealo, W2thi, W2tlo, elb, MM, FF, FF);
    k_prop2<<<NN, 128>>>(rstart, rcsr, col, alpha, Dinv, elb, b2, xl);
    k_colstat<<<CSTAT_BLKS, FF>>>(xl, p1, p2, NN, gn2w, gn2ms, shift, scale, rows_inv, ticket);

    // join: fc1 must finish before normfuse2 overwrites h16 (and before fc2 reads fc)
    cudaEventRecord(evJoin2, s1);
    cudaStreamWaitEvent(0, evJoin2, 0);
    k_normfuse<<<NN, 128>>>(xl, shift, scale, gn2b, wa2, h16, nullptr);
    k_hgemm<2><<<gFC, 256, GEMM_SMEM>>>(h16, f2t16, fc, NN, HIDD, FF, fc2b);

    // ---- classifier ----
    k_cls<<<(NN * 32 + 255) / 256, 256>>>(fc, clsW, clsb, outp, NN);
}